// round 6
// baseline (speedup 1.0000x reference)
#include <cuda_runtime.h>
#include <cuda_fp16.h>
#include <math.h>
#include <stdint.h>

// ---------------- Problem constants ----------------
#define B_    32
#define T_    512
#define C_    32
#define D_    512
#define H_    8
#define E_    64
#define DFF_  2048
#define NL_   3
#define P_    16
#define N_    64
#define BC_   (B_*C_)          // 1024
#define ROWS_ ((BC_)*(N_))     // 65536
#define KSPLIT_ 8
#define KCH_    4096           // 32768 / 8
#define KHEAD_  (D_*N_)        // 32768

// ---------------- Scratch (device globals; no allocation) ----------------
__device__ float  g_mean[BC_];
__device__ float  g_std[BC_];
__device__ float  g_tok  [ROWS_ * D_];        // fp32 residual stream
__device__ __half g_tok_h[ROWS_ * D_];        // half copy (QKV input)
__device__ __half g_qkv_h[ROWS_ * 1536];      // fused QKV output
__device__ __half g_attn_h[ROWS_ * D_];       // attention output (O input)
__device__ __half g_y_h  [ROWS_ * D_];        // ln1 output (FF1 input)
__device__ __half g_h_h  [ROWS_ * DFF_];      // gelu output (FF2 input)
__device__ __half g_enc_h[BC_ * KHEAD_];      // head input
__device__ float  g_hpart[KSPLIT_ * BC_ * T_];
__device__ float  g_psum [256 * D_];
__device__ float  g_psq  [256 * D_];
__device__ float  g_bna  [D_];
__device__ float  g_bnb  [D_];
__device__ float  g_bqkv [NL_ * 1536];
// transposed half weights ([N,K] K-major)
__device__ __half g_wqkvT[NL_ * 1536 * D_];
__device__ __half g_woT  [NL_ * D_ * D_];
__device__ __half g_wc1T [NL_ * DFF_ * D_];
__device__ __half g_wc2T [NL_ * D_ * DFF_];
__device__ __half g_whT  [T_ * KHEAD_];

// ---------------- helpers ----------------
#define CP16(dst, src)  asm volatile("cp.async.cg.shared.global [%0], [%1], 16;\n" :: "r"(dst), "l"(src))
#define CP_COMMIT()     asm volatile("cp.async.commit_group;\n")
#define CP_WAIT1()      asm volatile("cp.async.wait_group 1;\n")
#define CP_WAIT0()      asm volatile("cp.async.wait_group 0;\n")

#define LDSM4(r0, r1, r2, r3, addr) \
    asm volatile("ldmatrix.sync.aligned.m8n8.x4.shared.b16 {%0,%1,%2,%3}, [%4];" \
        : "=r"(r0), "=r"(r1), "=r"(r2), "=r"(r3) : "r"(addr))

__device__ __forceinline__ uint32_t smem_u32(const void* p) {
    uint32_t a;
    asm("{ .reg .u64 t; cvta.to.shared.u64 t, %1; cvt.u32.u64 %0, t; }" : "=r"(a) : "l"(p));
    return a;
}

// ---------------- Weight transpose -> half ----------------
__global__ void whtrans_kernel(const float* __restrict__ W, __half* __restrict__ WT,
                               int K, int N) {
    __shared__ float s[32][33];
    int n0 = blockIdx.x * 32, k0 = blockIdx.y * 32;
    int tx = threadIdx.x, ty = threadIdx.y;   // 32 x 8
    #pragma unroll
    for (int j = 0; j < 32; j += 8)
        s[ty + j][tx] = W[(size_t)(k0 + ty + j) * N + n0 + tx];
    __syncthreads();
    #pragma unroll
    for (int j = 0; j < 32; j += 8)
        WT[(size_t)(n0 + ty + j) * K + k0 + tx] = __float2half_rn(s[tx][ty + j]);
}

__global__ void bqkv_kernel(const float* __restrict__ bq, const float* __restrict__ bk,
                            const float* __restrict__ bv) {
    int i = blockIdx.x, t = threadIdx.x;   // NL_ x 512
    g_bqkv[i * 1536 + t]        = bq[i * D_ + t];
    g_bqkv[i * 1536 + 512 + t]  = bk[i * D_ + t];
    g_bqkv[i * 1536 + 1024 + t] = bv[i * D_ + t];
}

// ---------------- Instance-norm stats over time ----------------
__global__ void inst_stats_kernel(const float* __restrict__ x_enc) {
    int bc = blockIdx.x;
    int b = bc >> 5, c = bc & 31;
    int tid = threadIdx.x;          // 256
    const float* p = x_enc + (size_t)b * T_ * C_ + c;
    float v0 = p[(size_t)tid * C_];
    float v1 = p[(size_t)(tid + 256) * C_];
    __shared__ float rs[256], rq[256];
    rs[tid] = v0 + v1; rq[tid] = v0 * v0 + v1 * v1;
    __syncthreads();
    for (int off = 128; off > 0; off >>= 1) {
        if (tid < off) { rs[tid] += rs[tid + off]; rq[tid] += rq[tid + off]; }
        __syncthreads();
    }
    if (tid == 0) {
        float mean = rs[0] / (float)T_;
        float var  = rq[0] / (float)T_ - mean * mean;
        g_mean[bc] = mean;
        g_std[bc]  = sqrtf(var + 1e-5f);
    }
}

// ---------------- Patch embedding + sinusoidal PE ----------------
__global__ void patch_embed_kernel(const float* __restrict__ x_enc,
                                   const float* __restrict__ W_val) {
    int bn = blockIdx.x;            // bc*64 + n
    int bc = bn >> 6, n = bn & 63;
    int b = bc >> 5, c = bc & 31;
    int d = threadIdx.x;            // 512
    __shared__ float pv[P_];
    if (d < P_) {
        int t = n * 8 + d;
        if (t > T_ - 1) t = T_ - 1;
        pv[d] = (x_enc[(size_t)(b * T_ + t) * C_ + c] - g_mean[bc]) / g_std[bc];
    }
    __syncthreads();
    int i2 = d >> 1;
    float div = expf(-(float)(2 * i2) * (logf(10000.0f) / (float)D_));
    float ang = (float)n * div;
    float acc = (d & 1) ? cosf(ang) : sinf(ang);
    #pragma unroll
    for (int p = 0; p < P_; p++)
        acc = fmaf(pv[p], W_val[p * D_ + d], acc);
    g_tok  [(size_t)bn * D_ + d] = acc;
    g_tok_h[(size_t)bn * D_ + d] = __float2half_rn(acc);
}

// ---------------- FP16 mma GEMM (m16n8k16 + ldmatrix), 256x128x32 tiles ----------------
// A: [M,K] half row-major; BT: [N,K] half row-major (= col-major B)
// EPI 0: Ch = h(A*B + bias)
// EPI 1: Cf = A*B + bias + res      (fp32 out)
// EPI 2: Ch = h(gelu(A*B + bias))
// EPI 4: Cf = A*B   (split-K partials via blockIdx.z)
#define HPITCH 40                        // halves per row (80B; ldmatrix conflict-free)
#define A_STG_B (256 * HPITCH * 2)       // 20480 bytes
#define B_STG_B (128 * HPITCH * 2)       // 10240 bytes
#define STG_B   (A_STG_B + B_STG_B)      // 30720 bytes
#define NSTG   3
#define HG_SMEM (NSTG * STG_B)           // 92160 bytes

template<int EPI>
__global__ __launch_bounds__(256, 1)
void hgemm_kernel(const __half* __restrict__ A, const __half* __restrict__ BT,
                  const float* __restrict__ bias, const float* __restrict__ res,
                  void* __restrict__ Cv, int M, int N, int K, int lda, int ldb) {
    extern __shared__ __half smh[];
    const uint32_t sbase = smem_u32(smh);

    if (EPI == 4) {
        size_t z = blockIdx.z;
        A  += z * KCH_;
        BT += z * KCH_;
    }

    const int tid  = threadIdx.x;
    const int warp = tid >> 5, lane = tid & 31;
    const int wm = warp >> 1, wn = warp & 1;       // 4x2 warp grid (64x64 warp tile)
    const int lr = lane >> 2, lc = lane & 3;
    const int bm = blockIdx.y * 256, bn = blockIdx.x * 128;

    float acc[4][8][4];
    #pragma unroll
    for (int mt = 0; mt < 4; mt++)
        #pragma unroll
        for (int nt = 0; nt < 8; nt++)
            #pragma unroll
            for (int i = 0; i < 4; i++) acc[mt][nt][i] = 0.0f;

    // ---- copy slots: A 256x32h -> 4 chunks/thread; B 128x32h -> 2 chunks/thread
    const __half* pA[4]; uint32_t aof[4];
    #pragma unroll
    for (int j = 0; j < 4; j++) {
        int q = tid + j * 256;                 // 0..1023
        int row = q >> 2, c16 = q & 3;
        pA[j] = A + (size_t)(bm + row) * lda + c16 * 8;
        aof[j] = (uint32_t)(row * (HPITCH * 2) + c16 * 16);
    }
    const __half* pB[2]; uint32_t bof[2];
    #pragma unroll
    for (int j = 0; j < 2; j++) {
        int q = tid + j * 256;                 // 0..511
        int row = q >> 2, c16 = q & 3;
        pB[j] = BT + (size_t)(bn + row) * ldb + c16 * 8;
        bof[j] = (uint32_t)(A_STG_B + row * (HPITCH * 2) + c16 * 16);
    }

    // ---- ldmatrix base addresses (per stage add s*STG_B, per ks add 32B)
    uint32_t aBase[4], bBase[4];
    #pragma unroll
    for (int mt = 0; mt < 4; mt++)
        aBase[mt] = sbase + (uint32_t)(((wm * 64 + mt * 16 + (lane & 15)) * HPITCH
                                        + (lane >> 4) * 8) * 2);
    #pragma unroll
    for (int ng = 0; ng < 4; ng++)
        bBase[ng] = sbase + A_STG_B + (uint32_t)(((wn * 64 + ng * 16 + (lane & 15)) * HPITCH
                                        + (lane >> 4) * 8) * 2);

    const int NIT = K >> 5;

    auto FILL = [&](int s, int k0) {
        uint32_t st = sbase + s * STG_B;
        #pragma unroll
        for (int j = 0; j < 4; j++) CP16(st + aof[j], pA[j] + k0);
        #pragma unroll
        for (int j = 0; j < 2; j++) CP16(st + bof[j], pB[j] + k0);
        CP_COMMIT();
    };

    FILL(0, 0);
    FILL(1, 32);

    for (int it = 0; it < NIT; ++it) {
        const int s = it % NSTG;
        if (it + 1 < NIT) { CP_WAIT1(); } else { CP_WAIT0(); }
        __syncthreads();
        if (it + 2 < NIT) FILL((it + 2) % NSTG, (it + 2) << 5);

        const uint32_t so = (uint32_t)(s * STG_B);
        #pragma unroll
        for (int ks = 0; ks < 2; ks++) {
            const uint32_t kb = so + ks * 32;      // 16 halves = 32 bytes
            uint32_t af[4][4];
            #pragma unroll
            for (int mt = 0; mt < 4; mt++)
                LDSM4(af[mt][0], af[mt][1], af[mt][2], af[mt][3], aBase[mt] + kb);
            uint32_t bq[4][4];
            #pragma unroll
            for (int ng = 0; ng < 4; ng++)
                LDSM4(bq[ng][0], bq[ng][1], bq[ng][2], bq[ng][3], bBase[ng] + kb);
            #pragma unroll
            for (int mt = 0; mt < 4; mt++)
                #pragma unroll
                for (int nt = 0; nt < 8; nt++) {
                    uint32_t b0 = bq[nt >> 1][nt & 1];
                    uint32_t b1 = bq[nt >> 1][(nt & 1) + 2];
                    asm volatile(
                        "mma.sync.aligned.m16n8k16.row.col.f32.f16.f16.f32 "
                        "{%0,%1,%2,%3},{%4,%5,%6,%7},{%8,%9},{%0,%1,%2,%3};"
                        : "+f"(acc[mt][nt][0]), "+f"(acc[mt][nt][1]),
                          "+f"(acc[mt][nt][2]), "+f"(acc[mt][nt][3])
                        : "r"(af[mt][0]), "r"(af[mt][1]),
                          "r"(af[mt][2]), "r"(af[mt][3]),
                          "r"(b0), "r"(b1));
                }
        }
        __syncthreads();
    }

    // ---------------- epilogue ----------------
    float* Cf = (float*)Cv;
    __half* Ch = (__half*)Cv;
    if (EPI == 4) Cf += (size_t)blockIdx.z * M * N;

    #pragma unroll
    for (int mt = 0; mt < 4; mt++) {
        #pragma unroll
        for (int half = 0; half < 2; half++) {
            int m = bm + wm * 64 + mt * 16 + lr + half * 8;
            #pragma unroll
            for (int nt = 0; nt < 8; nt++) {
                int col = bn + wn * 64 + nt * 8 + lc * 2;
                float v0 = acc[mt][nt][half * 2 + 0];
                float v1 = acc[mt][nt][half * 2 + 1];
                if (EPI != 4) { v0 += bias[col]; v1 += bias[col + 1]; }
                if (EPI == 1) {
                    const float2 r2 = *(const float2*)(res + (size_t)m * N + col);
                    v0 += r2.x; v1 += r2.y;
                }
                if (EPI == 2) {
                    v0 = 0.5f * v0 * (1.0f + erff(v0 * 0.70710678118654752f));
                    v1 = 0.5f * v1 * (1.0f + erff(v1 * 0.70710678118654752f));
                }
                if (EPI == 0 || EPI == 2) {
                    __half2 hv;
                    hv.x = __float2half_rn(v0); hv.y = __float2half_rn(v1);
                    *(__half2*)(Ch + (size_t)m * N + col) = hv;
                } else {
                    *(float2*)(Cf + (size_t)m * N + col) = make_float2(v0, v1);
                }
            }
        }
    }
}

// ---------------- Attention (per bc, per head), register-tiled ----------------
#define ATTN_SMEM (4 * 64 * 68 * 4)
__global__ void attn_kernel() {
    int bh = blockIdx.x;
    int bc = bh >> 3, h = bh & 7;
    extern __shared__ float sm[];
    float* qs = sm;
    float* kt = qs + 64 * 68;
    float* vs = kt + 64 * 68;
    float* ss = vs + 64 * 68;
    int tid = threadIdx.x;   // 256
    const __half* Qb = g_qkv_h + (size_t)bc * 64 * 1536 + h * 64;
    const __half* Kb = Qb + 512;
    const __half* Vb = Qb + 1024;

    #pragma unroll
    for (int i = 0; i < 16; i++) {
        int flat = i * 256 + tid;
        int r = flat >> 6, e = flat & 63;
        qs[r * 68 + e] = __half2float(Qb[(size_t)r * 1536 + e]);
        kt[e * 68 + r] = __half2float(Kb[(size_t)r * 1536 + e]);   // transpose
        vs[r * 68 + e] = __half2float(Vb[(size_t)r * 1536 + e]);
    }
    __syncthreads();

    const int l  = tid >> 2;
    const int sq = tid & 3;
    const int s0 = sq << 4;

    float a[16];
    #pragma unroll
    for (int j = 0; j < 16; j++) a[j] = 0.0f;
    for (int e = 0; e < 64; e++) {
        float qv = qs[l * 68 + e];
        const float* kr = &kt[e * 68 + s0];
        float4 k0 = *(const float4*)(kr);
        float4 k1 = *(const float4*)(kr + 4);
        float4 k2 = *(const float4*)(kr + 8);
        float4 k3 = *(const float4*)(kr + 12);
        a[0]  = fmaf(qv, k0.x, a[0]);  a[1]  = fmaf(qv, k0.y, a[1]);
        a[2]  = fmaf(qv, k0.z, a[2]);  a[3]  = fmaf(qv, k0.w, a[3]);
        a[4]  = fmaf(qv, k1.x, a[4]);  a[5]  = fmaf(qv, k1.y, a[5]);
        a[6]  = fmaf(qv, k1.z, a[6]);  a[7]  = fmaf(qv, k1.w, a[7]);
        a[8]  = fmaf(qv, k2.x, a[8]);  a[9]  = fmaf(qv, k2.y, a[9]);
        a[10] = fmaf(qv, k2.z, a[10]); a[11] = fmaf(qv, k2.w, a[11]);
        a[12] = fmaf(qv, k3.x, a[12]); a[13] = fmaf(qv, k3.y, a[13]);
        a[14] = fmaf(qv, k3.z, a[14]); a[15] = fmaf(qv, k3.w, a[15]);
    }
    float mx = -1e30f;
    #pragma unroll
    for (int j = 0; j < 16; j++) { a[j] *= 0.125f; mx = fmaxf(mx, a[j]); }
    mx = fmaxf(mx, __shfl_xor_sync(0xffffffffu, mx, 1));
    mx = fmaxf(mx, __shfl_xor_sync(0xffffffffu, mx, 2));
    float sum = 0.0f;
    #pragma unroll
    for (int j = 0; j < 16; j++) { a[j] = expf(a[j] - mx); sum += a[j]; }
    sum += __shfl_xor_sync(0xffffffffu, sum, 1);
    sum += __shfl_xor_sync(0xffffffffu, sum, 2);
    float inv = 1.0f / sum;
    #pragma unroll
    for (int j = 0; j < 16; j++) ss[l * 68 + s0 + j] = a[j] * inv;
    __syncthreads();

    const int e0 = s0;
    float o[16];
    #pragma unroll
    for (int j = 0; j < 16; j++) o[j] = 0.0f;
    for (int s = 0; s < 64; s++) {
        float av = ss[l * 68 + s];
        const float* vr = &vs[s * 68 + e0];
        float4 v0 = *(const float4*)(vr);
        float4 v1 = *(const float4*)(vr + 4);
        float4 v2 = *(const float4*)(vr + 8);
        float4 v3 = *(const float4*)(vr + 12);
        o[0]  = fmaf(av, v0.x, o[0]);  o[1]  = fmaf(av, v0.y, o[1]);
        o[2]  = fmaf(av, v0.z, o[2]);  o[3]  = fmaf(av, v0.w, o[3]);
        o[4]  = fmaf(av, v1.x, o[4]);  o[5]  = fmaf(av, v1.y, o[5]);
        o[6]  = fmaf(av, v1.z, o[6]);  o[7]  = fmaf(av, v1.w, o[7]);
        o[8]  = fmaf(av, v2.x, o[8]);  o[9]  = fmaf(av, v2.y, o[9]);
        o[10] = fmaf(av, v2.z, o[10]); o[11] = fmaf(av, v2.w, o[11]);
        o[12] = fmaf(av, v3.x, o[12]); o[13] = fmaf(av, v3.y, o[13]);
        o[14] = fmaf(av, v3.z, o[14]); o[15] = fmaf(av, v3.w, o[15]);
    }
    __half* Ob = g_attn_h + ((size_t)bc * 64 + l) * D_ + h * 64 + e0;
    #pragma unroll
    for (int j = 0; j < 16; j += 2) {
        __half2 hv;
        hv.x = __float2half_rn(o[j]); hv.y = __float2half_rn(o[j + 1]);
        *(__half2*)(Ob + j) = hv;
    }
}

// ---------------- LayerNorm (row of 512) ----------------
__global__ void ln_kernel(const float* __restrict__ X,
                          const float* __restrict__ g, const float* __restrict__ b,
                          float* __restrict__ Yf, __half* __restrict__ Yh) {
    int row = blockIdx.x;
    int tid = threadIdx.x;  // 256
    const float* x = X + (size_t)row * D_;
    float v0 = x[tid], v1 = x[tid + 256];
    __shared__ float rs[256], rq[256];
    rs[tid] = v0 + v1;
    rq[tid] = v0 * v0 + v1 * v1;
    __syncthreads();
    for (int off = 128; off > 0; off >>= 1) {
        if (tid < off) { rs[tid] += rs[tid + off]; rq[tid] += rq[tid + off]; }
        __syncthreads();
    }
    __shared__ float s_mean, s_inv;
    if (tid == 0) {
        float mean = rs[0] / (float)D_;
        float var  = rq[0] / (float)D_ - mean * mean;
        s_mean = mean;
        s_inv  = rsqrtf(var + 1e-5f);
    }
    __syncthreads();
    float mean = s_mean, inv = s_inv;
    float o0 = (v0 - mean) * inv * g[tid]       + b[tid];
    float o1 = (v1 - mean) * inv * g[tid + 256] + b[tid + 256];
    if (Yf) {
        Yf[(size_t)row * D_ + tid]       = o0;
        Yf[(size_t)row * D_ + tid + 256] = o1;
    }
    if (Yh) {
        Yh[(size_t)row * D_ + tid]       = __float2half_rn(o0);
        Yh[(size_t)row * D_ + tid + 256] = __float2half_rn(o1);
    }
}

// ---------------- BatchNorm stats (deterministic 2-stage) ----------------
__global__ void bn_partial_kernel() {
    int blk = blockIdx.x;
    int d = threadIdx.x;      // 512
    float s = 0.0f, q = 0.0f;
    const float* base = g_tok + (size_t)blk * 256 * D_ + d;
    for (int r = 0; r < 256; r++) {
        float v = base[(size_t)r * D_];
        s += v; q += v * v;
    }
    g_psum[blk * D_ + d] = s;
    g_psq [blk * D_ + d] = q;
}

__global__ void bn_final_kernel(const float* __restrict__ gam,
                                const float* __restrict__ bet) {
    int d = threadIdx.x;      // 512, one block
    float s = 0.0f, q = 0.0f;
    for (int i = 0; i < 256; i++) {
        s += g_psum[i * D_ + d];
        q += g_psq [i * D_ + d];
    }
    float mean = s / (float)ROWS_;
    float var  = q / (float)ROWS_ - mean * mean;
    float a = gam[d] * rsqrtf(var + 1e-5f);
    g_bna[d] = a;
    g_bnb[d] = bet[d] - mean * a;
}

// ---------------- BN apply + (N,D)->(D,N) transpose into enc (half) ----------------
__global__ void enc_transpose_kernel() {
    __shared__ float sm[32][33];
    int bid = blockIdx.x;
    int bc = bid >> 5;
    int r = bid & 31;
    int dt = r >> 1, nt = r & 1;
    int tx = threadIdx.x, ty = threadIdx.y;   // 32 x 8
    int d0 = dt * 32, n0 = nt * 32;
    #pragma unroll
    for (int j = 0; j < 32; j += 8) {
        int n = n0 + ty + j;
        int d = d0 + tx;
        float v = g_tok[((size_t)bc * 64 + n) * D_ + d];
        sm[ty + j][tx] = v * g_bna[d] + g_bnb[d];
    }
    __syncthreads();
    #pragma unroll
    for (int j = 0; j < 32; j += 8) {
        int d = d0 + ty + j;
        int n = n0 + tx;
        g_enc_h[(size_t)bc * KHEAD_ + d * N_ + n] = __float2half_rn(sm[tx][ty + j]);
    }
}

// ---------------- head final: sum split-K partials + bias + denorm ----------------
__global__ void head_final_kernel(const float* __restrict__ b_head,
                                  float* __restrict__ out) {
    int m = blockIdx.x;        // bc
    int t = threadIdx.x;       // 512
    float v = b_head[t];
    #pragma unroll
    for (int z = 0; z < KSPLIT_; z++)
        v += g_hpart[((size_t)z * BC_ + m) * T_ + t];
    int b = m >> 5, c = m & 31;
    out[((size_t)b * T_ + t) * C_ + c] = v * g_std[m] + g_mean[m];
}

// ---------------- Launch ----------------
extern "C" void kernel_launch(void* const* d_in, const int* in_sizes, int n_in,
                              void* d_out, int out_size) {
    const float* x_enc = (const float*)d_in[0];
    const float* W_val = (const float*)d_in[1];
    const float* Wq    = (const float*)d_in[2];
    const float* bq    = (const float*)d_in[3];
    const float* Wk    = (const float*)d_in[4];
    const float* bk    = (const float*)d_in[5];
    const float* Wv    = (const float*)d_in[6];
    const float* bv    = (const float*)d_in[7];
    const float* Wo    = (const float*)d_in[8];
    const float* bo    = (const float*)d_in[9];
    const float* Wc1   = (const float*)d_in[10];
    const float* bc1   = (const float*)d_in[11];
    const float* Wc2   = (const float*)d_in[12];
    const float* bc2   = (const float*)d_in[13];
    const float* ln1_g = (const float*)d_in[14];
    const float* ln1_b = (const float*)d_in[15];
    const float* ln2_g = (const float*)d_in[16];
    const float* ln2_b = (const float*)d_in[17];
    const float* bn_g  = (const float*)d_in[18];
    const float* bn_b  = (const float*)d_in[19];
    const float* W_head= (const float*)d_in[20];
    const float* b_head= (const float*)d_in[21];
    float* out = (float*)d_out;

    float *tok, *hpart, *bqkv;
    __half *tok_h, *qkv_h, *attn_h, *y_h, *h_h, *enc_h;
    __half *wqkvT, *woT, *wc1T, *wc2T, *whT;
    cudaGetSymbolAddress((void**)&tok,    g_tok);
    cudaGetSymbolAddress((void**)&tok_h,  g_tok_h);
    cudaGetSymbolAddress((void**)&qkv_h,  g_qkv_h);
    cudaGetSymbolAddress((void**)&attn_h, g_attn_h);
    cudaGetSymbolAddress((void**)&y_h,    g_y_h);
    cudaGetSymbolAddress((void**)&h_h,    g_h_h);
    cudaGetSymbolAddress((void**)&enc_h,  g_enc_h);
    cudaGetSymbolAddress((void**)&hpart,  g_hpart);
    cudaGetSymbolAddress((void**)&bqkv,   g_bqkv);
    cudaGetSymbolAddress((void**)&wqkvT,  g_wqkvT);
    cudaGetSymbolAddress((void**)&woT,    g_woT);
    cudaGetSymbolAddress((void**)&wc1T,   g_wc1T);
    cudaGetSymbolAddress((void**)&wc2T,   g_wc2T);
    cudaGetSymbolAddress((void**)&whT,    g_whT);

    cudaFuncSetAttribute(attn_kernel, cudaFuncAttributeMaxDynamicSharedMemorySize, ATTN_SMEM);
    cudaFuncSetAttribute(hgemm_kernel<0>, cudaFuncAttributeMaxDynamicSharedMemorySize, HG_SMEM);
    cudaFuncSetAttribute(hgemm_kernel<1>, cudaFuncAttributeMaxDynamicSharedMemorySize, HG_SMEM);
    cudaFuncSetAttribute(hgemm_kernel<2>, cudaFuncAttributeMaxDynamicSharedMemorySize, HG_SMEM);
    cudaFuncSetAttribute(hgemm_kernel<4>, cudaFuncAttributeMaxDynamicSharedMemorySize, HG_SMEM);

    // ---- weight prep: transpose -> half ----
    dim3 tb32(32, 8);
    for (int i = 0; i < NL_; i++) {
        whtrans_kernel<<<dim3(16, 16), tb32>>>(Wq + (size_t)i * D_ * D_,
            wqkvT + (size_t)i * 1536 * D_, D_, D_);
        whtrans_kernel<<<dim3(16, 16), tb32>>>(Wk + (size_t)i * D_ * D_,
            wqkvT + (size_t)i * 1536 * D_ + (size_t)512 * D_, D_, D_);
        whtrans_kernel<<<dim3(16, 16), tb32>>>(Wv + (size_t)i * D_ * D_,
            wqkvT + (size_t)i * 1536 * D_ + (size_t)1024 * D_, D_, D_);
        whtrans_kernel<<<dim3(16, 16), tb32>>>(Wo + (size_t)i * D_ * D_,
            woT + (size_t)i * D_ * D_, D_, D_);
        whtrans_kernel<<<dim3(64, 16), tb32>>>(Wc1 + (size_t)i * D_ * DFF_,
            wc1T + (size_t)i * DFF_ * D_, D_, DFF_);
        whtrans_kernel<<<dim3(16, 64), tb32>>>(Wc2 + (size_t)i * DFF_ * D_,
            wc2T + (size_t)i * D_ * DFF_, DFF_, D_);
    }
    whtrans_kernel<<<dim3(16, 1024), tb32>>>(W_head, whT, KHEAD_, T_);
    bqkv_kernel<<<NL_, 512>>>(bq, bk, bv);

    inst_stats_kernel<<<BC_, 256>>>(x_enc);
    patch_embed_kernel<<<ROWS_, 512>>>(x_enc, W_val);

    dim3 gqkv(1536 / 128, ROWS_ / 256);       // (12, 256)
    dim3 gproj(D_ / 128, ROWS_ / 256);        // (4, 256)
    dim3 gff1(DFF_ / 128, ROWS_ / 256);       // (16, 256)
    dim3 ghead(T_ / 128, BC_ / 256, KSPLIT_); // (4, 4, 8)

    for (int i = 0; i < NL_; i++) {
        hgemm_kernel<0><<<gqkv, 256, HG_SMEM>>>(tok_h, wqkvT + (size_t)i * 1536 * D_,
            bqkv + i * 1536, nullptr, qkv_h, ROWS_, 1536, D_, D_, D_);
        attn_kernel<<<BC_ * H_, 256, ATTN_SMEM>>>();
        hgemm_kernel<1><<<gproj, 256, HG_SMEM>>>(attn_h, woT + (size_t)i * D_ * D_,
            bo + i * D_, tok, tok, ROWS_, D_, D_, D_, D_);
        ln_kernel<<<ROWS_, 256>>>(tok, ln1_g + i * D_, ln1_b + i * D_, nullptr, y_h);
        hgemm_kernel<2><<<gff1, 256, HG_SMEM>>>(y_h, wc1T + (size_t)i * DFF_ * D_,
            bc1 + i * DFF_, nullptr, h_h, ROWS_, DFF_, D_, D_, D_);
        hgemm_kernel<1><<<gproj, 256, HG_SMEM>>>(h_h, wc2T + (size_t)i * D_ * DFF_,
            bc2 + i * D_, tok, tok, ROWS_, D_, DFF_, DFF_, DFF_);
        ln_kernel<<<ROWS_, 256>>>(tok, ln2_g + i * D_, ln2_b + i * D_, tok, tok_h);
    }

    bn_partial_kernel<<<256, 512>>>();
    bn_final_kernel<<<1, 512>>>(bn_g, bn_b);
    enc_transpose_kernel<<<BC_ * 32, dim3(32, 8)>>>();
    hgemm_kernel<4><<<ghead, 256, HG_SMEM>>>(enc_h, whT, nullptr, nullptr, hpart,
                                             BC_, T_, KCH_, KHEAD_, KHEAD_);
    head_final_kernel<<<BC_, T_>>>(b_head, out);
}

// round 7
// speedup vs baseline: 1.0622x; 1.0622x over previous
#include <cuda_runtime.h>
#include <cuda_fp16.h>
#include <math.h>
#include <stdint.h>

// ---------------- Problem constants ----------------
#define B_    32
#define T_    512
#define C_    32
#define D_    512
#define H_    8
#define E_    64
#define DFF_  2048
#define NL_   3
#define P_    16
#define N_    64
#define BC_   (B_*C_)          // 1024
#define ROWS_ ((BC_)*(N_))     // 65536
#define KSPLIT_ 8
#define KCH_    4096           // 32768 / 8
#define KHEAD_  (D_*N_)        // 32768

// ---------------- Scratch (device globals; no allocation) ----------------
__device__ float  g_mean[BC_];
__device__ float  g_std[BC_];
__device__ float  g_tok  [ROWS_ * D_];        // fp32 residual stream
__device__ __half g_tok_h[ROWS_ * D_];        // half copy (QKV input)
__device__ __half g_qkv_h[ROWS_ * 1536];      // fused QKV output
__device__ __half g_attn_h[ROWS_ * D_];       // attention output (O input)
__device__ __half g_y_h  [ROWS_ * D_];        // ln1 output (FF1 input)
__device__ __half g_h_h  [ROWS_ * DFF_];      // gelu output (FF2 input)
__device__ __half g_enc_h[BC_ * KHEAD_];      // head input
__device__ float  g_hpart[KSPLIT_ * BC_ * T_];
__device__ float  g_psum [256 * D_];
__device__ float  g_psq  [256 * D_];
__device__ float  g_bna  [D_];
__device__ float  g_bnb  [D_];
__device__ float  g_bqkv [NL_ * 1536];
// transposed half weights ([N,K] K-major)
__device__ __half g_wqkvT[NL_ * 1536 * D_];
__device__ __half g_woT  [NL_ * D_ * D_];
__device__ __half g_wc1T [NL_ * DFF_ * D_];
__device__ __half g_wc2T [NL_ * D_ * DFF_];
__device__ __half g_whT  [T_ * KHEAD_];

// ---------------- helpers ----------------
#define CP16(dst, src)  asm volatile("cp.async.cg.shared.global [%0], [%1], 16;\n" :: "r"(dst), "l"(src))
#define CP_COMMIT()     asm volatile("cp.async.commit_group;\n")
#define CP_WAIT1()      asm volatile("cp.async.wait_group 1;\n")
#define CP_WAIT0()      asm volatile("cp.async.wait_group 0;\n")

#define LDSM4(r0, r1, r2, r3, addr) \
    asm volatile("ldmatrix.sync.aligned.m8n8.x4.shared.b16 {%0,%1,%2,%3}, [%4];" \
        : "=r"(r0), "=r"(r1), "=r"(r2), "=r"(r3) : "r"(addr))

__device__ __forceinline__ uint32_t smem_u32(const void* p) {
    uint32_t a;
    asm("{ .reg .u64 t; cvta.to.shared.u64 t, %1; cvt.u32.u64 %0, t; }" : "=r"(a) : "l"(p));
    return a;
}

// ---------------- Weight transpose -> half ----------------
__global__ void whtrans_kernel(const float* __restrict__ W, __half* __restrict__ WT,
                               int K, int N) {
    __shared__ float s[32][33];
    int n0 = blockIdx.x * 32, k0 = blockIdx.y * 32;
    int tx = threadIdx.x, ty = threadIdx.y;   // 32 x 8
    #pragma unroll
    for (int j = 0; j < 32; j += 8)
        s[ty + j][tx] = W[(size_t)(k0 + ty + j) * N + n0 + tx];
    __syncthreads();
    #pragma unroll
    for (int j = 0; j < 32; j += 8)
        WT[(size_t)(n0 + ty + j) * K + k0 + tx] = __float2half_rn(s[tx][ty + j]);
}

__global__ void bqkv_kernel(const float* __restrict__ bq, const float* __restrict__ bk,
                            const float* __restrict__ bv) {
    int i = blockIdx.x, t = threadIdx.x;   // NL_ x 512
    g_bqkv[i * 1536 + t]        = bq[i * D_ + t];
    g_bqkv[i * 1536 + 512 + t]  = bk[i * D_ + t];
    g_bqkv[i * 1536 + 1024 + t] = bv[i * D_ + t];
}

// ---------------- Instance-norm stats over time ----------------
__global__ void inst_stats_kernel(const float* __restrict__ x_enc) {
    int bc = blockIdx.x;
    int b = bc >> 5, c = bc & 31;
    int tid = threadIdx.x;          // 256
    const float* p = x_enc + (size_t)b * T_ * C_ + c;
    float v0 = p[(size_t)tid * C_];
    float v1 = p[(size_t)(tid + 256) * C_];
    __shared__ float rs[256], rq[256];
    rs[tid] = v0 + v1; rq[tid] = v0 * v0 + v1 * v1;
    __syncthreads();
    for (int off = 128; off > 0; off >>= 1) {
        if (tid < off) { rs[tid] += rs[tid + off]; rq[tid] += rq[tid + off]; }
        __syncthreads();
    }
    if (tid == 0) {
        float mean = rs[0] / (float)T_;
        float var  = rq[0] / (float)T_ - mean * mean;
        g_mean[bc] = mean;
        g_std[bc]  = sqrtf(var + 1e-5f);
    }
}

// ---------------- Patch embedding + sinusoidal PE ----------------
__global__ void patch_embed_kernel(const float* __restrict__ x_enc,
                                   const float* __restrict__ W_val) {
    int bn = blockIdx.x;            // bc*64 + n
    int bc = bn >> 6, n = bn & 63;
    int b = bc >> 5, c = bc & 31;
    int d = threadIdx.x;            // 512
    __shared__ float pv[P_];
    if (d < P_) {
        int t = n * 8 + d;
        if (t > T_ - 1) t = T_ - 1;
        pv[d] = (x_enc[(size_t)(b * T_ + t) * C_ + c] - g_mean[bc]) / g_std[bc];
    }
    __syncthreads();
    int i2 = d >> 1;
    float div = expf(-(float)(2 * i2) * (logf(10000.0f) / (float)D_));
    float ang = (float)n * div;
    float acc = (d & 1) ? cosf(ang) : sinf(ang);
    #pragma unroll
    for (int p = 0; p < P_; p++)
        acc = fmaf(pv[p], W_val[p * D_ + d], acc);
    g_tok  [(size_t)bn * D_ + d] = acc;
    g_tok_h[(size_t)bn * D_ + d] = __float2half_rn(acc);
}

// ---------------- FP16 mma GEMM (m16n8k16 + ldmatrix), 128x128x32 tiles ----------------
// A: [M,K] half row-major; BT: [N,K] half row-major (= col-major B)
// EPI 0: Ch = h(A*B + bias)
// EPI 1: Cf = A*B + bias + res      (fp32 out)
// EPI 2: Ch = h(gelu(A*B + bias))
// EPI 4: Cf = A*B   (split-K partials via blockIdx.z)
#define HPITCH 40                    // halves per row (80B; ldmatrix conflict-free)
#define STGH   (2 * 128 * HPITCH)    // 10240 halves per stage (A+B)
#define NSTG   3
#define HG_SMEM (NSTG * STGH * 2)    // 61440 bytes

template<int EPI>
__global__ __launch_bounds__(256, 2)
void hgemm_kernel(const __half* __restrict__ A, const __half* __restrict__ BT,
                  const float* __restrict__ bias, const float* __restrict__ res,
                  void* __restrict__ Cv, int M, int N, int K, int lda, int ldb) {
    extern __shared__ __half smh[];
    const uint32_t sbase = smem_u32(smh);

    if (EPI == 4) {
        size_t z = blockIdx.z;
        A  += z * KCH_;
        BT += z * KCH_;
    }

    const int tid  = threadIdx.x;
    const int warp = tid >> 5, lane = tid & 31;
    const int wm = warp >> 1, wn = warp & 1;       // 4x2 warp grid (32x64 warp tile)
    const int lr = lane >> 2, lc = lane & 3;
    const int bm = blockIdx.y * 128, bn = blockIdx.x * 128;

    float acc[2][8][4];
    #pragma unroll
    for (int mt = 0; mt < 2; mt++)
        #pragma unroll
        for (int nt = 0; nt < 8; nt++)
            #pragma unroll
            for (int i = 0; i < 4; i++) acc[mt][nt][i] = 0.0f;

    // copy slots: per thread 2 A-chunks + 2 B-chunks of 16B (tile 128 x 32 halves)
    const __half* pA[2];
    const __half* pB[2];
    uint32_t aof[2], bof[2];
    #pragma unroll
    for (int j = 0; j < 2; j++) {
        int q = tid + j * 256;                 // 0..511
        int row = q >> 2, c16 = q & 3;
        pA[j] = A  + (size_t)(bm + row) * lda + c16 * 8;
        pB[j] = BT + (size_t)(bn + row) * ldb + c16 * 8;
        aof[j] = (uint32_t)(row * (HPITCH * 2) + c16 * 16);
        bof[j] = (uint32_t)(128 * HPITCH * 2 + row * (HPITCH * 2) + c16 * 16);
    }

    // ldmatrix base addresses (add s*stage + ks*32B at use site)
    uint32_t aBase[2], bBase[4];
    #pragma unroll
    for (int mt = 0; mt < 2; mt++)
        aBase[mt] = sbase + (uint32_t)(((wm * 32 + mt * 16 + (lane & 15)) * HPITCH
                                        + (lane >> 4) * 8) * 2);
    #pragma unroll
    for (int ng = 0; ng < 4; ng++)
        bBase[ng] = sbase + (uint32_t)(128 * HPITCH * 2)
                  + (uint32_t)(((wn * 64 + ng * 16 + (lane & 15)) * HPITCH
                                        + (lane >> 4) * 8) * 2);

    const int NIT = K >> 5;

    auto FILL = [&](int s, int k0) {
        uint32_t st = sbase + s * (STGH * 2);
        #pragma unroll
        for (int j = 0; j < 2; j++) {
            CP16(st + aof[j], pA[j] + k0);
            CP16(st + bof[j], pB[j] + k0);
        }
        CP_COMMIT();
    };

    FILL(0, 0);
    FILL(1, 32);

    for (int it = 0; it < NIT; ++it) {
        const int s = it % NSTG;
        if (it + 1 < NIT) { CP_WAIT1(); } else { CP_WAIT0(); }
        __syncthreads();
        if (it + 2 < NIT) FILL((it + 2) % NSTG, (it + 2) << 5);

        const uint32_t so = (uint32_t)(s * (STGH * 2));
        #pragma unroll
        for (int ks = 0; ks < 2; ks++) {
            const uint32_t kb = so + ks * 32;      // 16 halves = 32 bytes
            uint32_t af[2][4];
            #pragma unroll
            for (int mt = 0; mt < 2; mt++)
                LDSM4(af[mt][0], af[mt][1], af[mt][2], af[mt][3], aBase[mt] + kb);
            uint32_t bq[4][4];
            #pragma unroll
            for (int ng = 0; ng < 4; ng++)
                LDSM4(bq[ng][0], bq[ng][1], bq[ng][2], bq[ng][3], bBase[ng] + kb);
            #pragma unroll
            for (int mt = 0; mt < 2; mt++)
                #pragma unroll
                for (int nt = 0; nt < 8; nt++) {
                    uint32_t b0 = bq[nt >> 1][nt & 1];
                    uint32_t b1 = bq[nt >> 1][(nt & 1) + 2];
                    asm volatile(
                        "mma.sync.aligned.m16n8k16.row.col.f32.f16.f16.f32 "
                        "{%0,%1,%2,%3},{%4,%5,%6,%7},{%8,%9},{%0,%1,%2,%3};"
                        : "+f"(acc[mt][nt][0]), "+f"(acc[mt][nt][1]),
                          "+f"(acc[mt][nt][2]), "+f"(acc[mt][nt][3])
                        : "r"(af[mt][0]), "r"(af[mt][1]),
                          "r"(af[mt][2]), "r"(af[mt][3]),
                          "r"(b0), "r"(b1));
                }
        }
        __syncthreads();
    }

    // ---------------- epilogue ----------------
    float* Cf = (float*)Cv;
    __half* Ch = (__half*)Cv;
    if (EPI == 4) Cf += (size_t)blockIdx.z * M * N;

    #pragma unroll
    for (int mt = 0; mt < 2; mt++) {
        #pragma unroll
        for (int half = 0; half < 2; half++) {
            int m = bm + wm * 32 + mt * 16 + lr + half * 8;
            #pragma unroll
            for (int nt = 0; nt < 8; nt++) {
                int col = bn + wn * 64 + nt * 8 + lc * 2;
                float v0 = acc[mt][nt][half * 2 + 0];
                float v1 = acc[mt][nt][half * 2 + 1];
                if (EPI != 4) { v0 += bias[col]; v1 += bias[col + 1]; }
                if (EPI == 1) {
                    const float2 r2 = *(const float2*)(res + (size_t)m * N + col);
                    v0 += r2.x; v1 += r2.y;
                }
                if (EPI == 2) {
                    v0 = 0.5f * v0 * (1.0f + erff(v0 * 0.70710678118654752f));
                    v1 = 0.5f * v1 * (1.0f + erff(v1 * 0.70710678118654752f));
                }
                if (EPI == 0 || EPI == 2) {
                    __half2 hv;
                    hv.x = __float2half_rn(v0); hv.y = __float2half_rn(v1);
                    *(__half2*)(Ch + (size_t)m * N + col) = hv;
                } else {
                    *(float2*)(Cf + (size_t)m * N + col) = make_float2(v0, v1);
                }
            }
        }
    }
}

// ---------------- Attention (per bc, per head), register-tiled ----------------
#define ATTN_SMEM (4 * 64 * 68 * 4)
__global__ void attn_kernel() {
    int bh = blockIdx.x;
    int bc = bh >> 3, h = bh & 7;
    extern __shared__ float sm[];
    float* qs = sm;
    float* kt = qs + 64 * 68;
    float* vs = kt + 64 * 68;
    float* ss = vs + 64 * 68;
    int tid = threadIdx.x;   // 256
    const __half* Qb = g_qkv_h + (size_t)bc * 64 * 1536 + h * 64;
    const __half* Kb = Qb + 512;
    const __half* Vb = Qb + 1024;

    #pragma unroll
    for (int i = 0; i < 16; i++) {
        int flat = i * 256 + tid;
        int r = flat >> 6, e = flat & 63;
        qs[r * 68 + e] = __half2float(Qb[(size_t)r * 1536 + e]);
        kt[e * 68 + r] = __half2float(Kb[(size_t)r * 1536 + e]);   // transpose
        vs[r * 68 + e] = __half2float(Vb[(size_t)r * 1536 + e]);
    }
    __syncthreads();

    const int l  = tid >> 2;
    const int sq = tid & 3;
    const int s0 = sq << 4;

    float a[16];
    #pragma unroll
    for (int j = 0; j < 16; j++) a[j] = 0.0f;
    for (int e = 0; e < 64; e++) {
        float qv = qs[l * 68 + e];
        const float* kr = &kt[e * 68 + s0];
        float4 k0 = *(const float4*)(kr);
        float4 k1 = *(const float4*)(kr + 4);
        float4 k2 = *(const float4*)(kr + 8);
        float4 k3 = *(const float4*)(kr + 12);
        a[0]  = fmaf(qv, k0.x, a[0]);  a[1]  = fmaf(qv, k0.y, a[1]);
        a[2]  = fmaf(qv, k0.z, a[2]);  a[3]  = fmaf(qv, k0.w, a[3]);
        a[4]  = fmaf(qv, k1.x, a[4]);  a[5]  = fmaf(qv, k1.y, a[5]);
        a[6]  = fmaf(qv, k1.z, a[6]);  a[7]  = fmaf(qv, k1.w, a[7]);
        a[8]  = fmaf(qv, k2.x, a[8]);  a[9]  = fmaf(qv, k2.y, a[9]);
        a[10] = fmaf(qv, k2.z, a[10]); a[11] = fmaf(qv, k2.w, a[11]);
        a[12] = fmaf(qv, k3.x, a[12]); a[13] = fmaf(qv, k3.y, a[13]);
        a[14] = fmaf(qv, k3.z, a[14]); a[15] = fmaf(qv, k3.w, a[15]);
    }
    float mx = -1e30f;
    #pragma unroll
    for (int j = 0; j < 16; j++) { a[j] *= 0.125f; mx = fmaxf(mx, a[j]); }
    mx = fmaxf(mx, __shfl_xor_sync(0xffffffffu, mx, 1));
    mx = fmaxf(mx, __shfl_xor_sync(0xffffffffu, mx, 2));
    float sum = 0.0f;
    #pragma unroll
    for (int j = 0; j < 16; j++) { a[j] = expf(a[j] - mx); sum += a[j]; }
    sum += __shfl_xor_sync(0xffffffffu, sum, 1);
    sum += __shfl_xor_sync(0xffffffffu, sum, 2);
    float inv = 1.0f / sum;
    #pragma unroll
    for (int j = 0; j < 16; j++) ss[l * 68 + s0 + j] = a[j] * inv;
    __syncthreads();

    const int e0 = s0;
    float o[16];
    #pragma unroll
    for (int j = 0; j < 16; j++) o[j] = 0.0f;
    for (int s = 0; s < 64; s++) {
        float av = ss[l * 68 + s];
        const float* vr = &vs[s * 68 + e0];
        float4 v0 = *(const float4*)(vr);
        float4 v1 = *(const float4*)(vr + 4);
        float4 v2 = *(const float4*)(vr + 8);
        float4 v3 = *(const float4*)(vr + 12);
        o[0]  = fmaf(av, v0.x, o[0]);  o[1]  = fmaf(av, v0.y, o[1]);
        o[2]  = fmaf(av, v0.z, o[2]);  o[3]  = fmaf(av, v0.w, o[3]);
        o[4]  = fmaf(av, v1.x, o[4]);  o[5]  = fmaf(av, v1.y, o[5]);
        o[6]  = fmaf(av, v1.z, o[6]);  o[7]  = fmaf(av, v1.w, o[7]);
        o[8]  = fmaf(av, v2.x, o[8]);  o[9]  = fmaf(av, v2.y, o[9]);
        o[10] = fmaf(av, v2.z, o[10]); o[11] = fmaf(av, v2.w, o[11]);
        o[12] = fmaf(av, v3.x, o[12]); o[13] = fmaf(av, v3.y, o[13]);
        o[14] = fmaf(av, v3.z, o[14]); o[15] = fmaf(av, v3.w, o[15]);
    }
    __half* Ob = g_attn_h + ((size_t)bc * 64 + l) * D_ + h * 64 + e0;
    #pragma unroll
    for (int j = 0; j < 16; j += 2) {
        __half2 hv;
        hv.x = __float2half_rn(o[j]); hv.y = __float2half_rn(o[j + 1]);
        *(__half2*)(Ob + j) = hv;
    }
}

// ---------------- LayerNorm (row of 512) ----------------
__global__ void ln_kernel(const float* __restrict__ X,
                          const float* __restrict__ g, const float* __restrict__ b,
                          float* __restrict__ Yf, __half* __restrict__ Yh) {
    int row = blockIdx.x;
    int tid = threadIdx.x;  // 256
    const float* x = X + (size_t)row * D_;
    float v0 = x[tid], v1 = x[tid + 256];
    __shared__ float rs[256], rq[256];
    rs[tid] = v0 + v1;
    rq[tid] = v0 * v0 + v1 * v1;
    __syncthreads();
    for (int off = 128; off > 0; off >>= 1) {
        if (tid < off) { rs[tid] += rs[tid + off]; rq[tid] += rq[tid + off]; }
        __syncthreads();
    }
    __shared__ float s_mean, s_inv;
    if (tid == 0) {
        float mean = rs[0] / (float)D_;
        float var  = rq[0] / (float)D_ - mean * mean;
        s_mean = mean;
        s_inv  = rsqrtf(var + 1e-5f);
    }
    __syncthreads();
    float mean = s_mean, inv = s_inv;
    float o0 = (v0 - mean) * inv * g[tid]       + b[tid];
    float o1 = (v1 - mean) * inv * g[tid + 256] + b[tid + 256];
    if (Yf) {
        Yf[(size_t)row * D_ + tid]       = o0;
        Yf[(size_t)row * D_ + tid + 256] = o1;
    }
    if (Yh) {
        Yh[(size_t)row * D_ + tid]       = __float2half_rn(o0);
        Yh[(size_t)row * D_ + tid + 256] = __float2half_rn(o1);
    }
}

// ---------------- BatchNorm stats (deterministic 2-stage) ----------------
__global__ void bn_partial_kernel() {
    int blk = blockIdx.x;
    int d = threadIdx.x;      // 512
    float s = 0.0f, q = 0.0f;
    const float* base = g_tok + (size_t)blk * 256 * D_ + d;
    for (int r = 0; r < 256; r++) {
        float v = base[(size_t)r * D_];
        s += v; q += v * v;
    }
    g_psum[blk * D_ + d] = s;
    g_psq [blk * D_ + d] = q;
}

__global__ void bn_final_kernel(const float* __restrict__ gam,
                                const float* __restrict__ bet) {
    int d = threadIdx.x;      // 512, one block
    float s = 0.0f, q = 0.0f;
    for (int i = 0; i < 256; i++) {
        s += g_psum[i * D_ + d];
        q += g_psq [i * D_ + d];
    }
    float mean = s / (float)ROWS_;
    float var  = q / (float)ROWS_ - mean * mean;
    float a = gam[d] * rsqrtf(var + 1e-5f);
    g_bna[d] = a;
    g_bnb[d] = bet[d] - mean * a;
}

// ---------------- BN apply + (N,D)->(D,N) transpose into enc (half) ----------------
__global__ void enc_transpose_kernel() {
    __shared__ float sm[32][33];
    int bid = blockIdx.x;
    int bc = bid >> 5;
    int r = bid & 31;
    int dt = r >> 1, nt = r & 1;
    int tx = threadIdx.x, ty = threadIdx.y;   // 32 x 8
    int d0 = dt * 32, n0 = nt * 32;
    #pragma unroll
    for (int j = 0; j < 32; j += 8) {
        int n = n0 + ty + j;
        int d = d0 + tx;
        float v = g_tok[((size_t)bc * 64 + n) * D_ + d];
        sm[ty + j][tx] = v * g_bna[d] + g_bnb[d];
    }
    __syncthreads();
    #pragma unroll
    for (int j = 0; j < 32; j += 8) {
        int d = d0 + ty + j;
        int n = n0 + tx;
        g_enc_h[(size_t)bc * KHEAD_ + d * N_ + n] = __float2half_rn(sm[tx][ty + j]);
    }
}

// ---------------- head final: sum split-K partials + bias + denorm ----------------
__global__ void head_final_kernel(const float* __restrict__ b_head,
                                  float* __restrict__ out) {
    int m = blockIdx.x;        // bc
    int t = threadIdx.x;       // 512
    float v = b_head[t];
    #pragma unroll
    for (int z = 0; z < KSPLIT_; z++)
        v += g_hpart[((size_t)z * BC_ + m) * T_ + t];
    int b = m >> 5, c = m & 31;
    out[((size_t)b * T_ + t) * C_ + c] = v * g_std[m] + g_mean[m];
}

// ---------------- Launch ----------------
extern "C" void kernel_launch(void* const* d_in, const int* in_sizes, int n_in,
                              void* d_out, int out_size) {
    const float* x_enc = (const float*)d_in[0];
    const float* W_val = (const float*)d_in[1];
    const float* Wq    = (const float*)d_in[2];
    const float* bq    = (const float*)d_in[3];
    const float* Wk    = (const float*)d_in[4];
    const float* bk    = (const float*)d_in[5];
    const float* Wv    = (const float*)d_in[6];
    const float* bv    = (const float*)d_in[7];
    const float* Wo    = (const float*)d_in[8];
    const float* bo    = (const float*)d_in[9];
    const float* Wc1   = (const float*)d_in[10];
    const float* bc1   = (const float*)d_in[11];
    const float* Wc2   = (const float*)d_in[12];
    const float* bc2   = (const float*)d_in[13];
    const float* ln1_g = (const float*)d_in[14];
    const float* ln1_b = (const float*)d_in[15];
    const float* ln2_g = (const float*)d_in[16];
    const float* ln2_b = (const float*)d_in[17];
    const float* bn_g  = (const float*)d_in[18];
    const float* bn_b  = (const float*)d_in[19];
    const float* W_head= (const float*)d_in[20];
    const float* b_head= (const float*)d_in[21];
    float* out = (float*)d_out;

    float *tok, *hpart, *bqkv;
    __half *tok_h, *qkv_h, *attn_h, *y_h, *h_h, *enc_h;
    __half *wqkvT, *woT, *wc1T, *wc2T, *whT;
    cudaGetSymbolAddress((void**)&tok,    g_tok);
    cudaGetSymbolAddress((void**)&tok_h,  g_tok_h);
    cudaGetSymbolAddress((void**)&qkv_h,  g_qkv_h);
    cudaGetSymbolAddress((void**)&attn_h, g_attn_h);
    cudaGetSymbolAddress((void**)&y_h,    g_y_h);
    cudaGetSymbolAddress((void**)&h_h,    g_h_h);
    cudaGetSymbolAddress((void**)&enc_h,  g_enc_h);
    cudaGetSymbolAddress((void**)&hpart,  g_hpart);
    cudaGetSymbolAddress((void**)&bqkv,   g_bqkv);
    cudaGetSymbolAddress((void**)&wqkvT,  g_wqkvT);
    cudaGetSymbolAddress((void**)&woT,    g_woT);
    cudaGetSymbolAddress((void**)&wc1T,   g_wc1T);
    cudaGetSymbolAddress((void**)&wc2T,   g_wc2T);
    cudaGetSymbolAddress((void**)&whT,    g_whT);

    cudaFuncSetAttribute(attn_kernel, cudaFuncAttributeMaxDynamicSharedMemorySize, ATTN_SMEM);
    cudaFuncSetAttribute(hgemm_kernel<0>, cudaFuncAttributeMaxDynamicSharedMemorySize, HG_SMEM);
    cudaFuncSetAttribute(hgemm_kernel<1>, cudaFuncAttributeMaxDynamicSharedMemorySize, HG_SMEM);
    cudaFuncSetAttribute(hgemm_kernel<2>, cudaFuncAttributeMaxDynamicSharedMemorySize, HG_SMEM);
    cudaFuncSetAttribute(hgemm_kernel<4>, cudaFuncAttributeMaxDynamicSharedMemorySize, HG_SMEM);

    // ---- weight prep: transpose -> half ----
    dim3 tb32(32, 8);
    for (int i = 0; i < NL_; i++) {
        whtrans_kernel<<<dim3(16, 16), tb32>>>(Wq + (size_t)i * D_ * D_,
            wqkvT + (size_t)i * 1536 * D_, D_, D_);
        whtrans_kernel<<<dim3(16, 16), tb32>>>(Wk + (size_t)i * D_ * D_,
            wqkvT + (size_t)i * 1536 * D_ + (size_t)512 * D_, D_, D_);
        whtrans_kernel<<<dim3(16, 16), tb32>>>(Wv + (size_t)i * D_ * D_,
            wqkvT + (size_t)i * 1536 * D_ + (size_t)1024 * D_, D_, D_);
        whtrans_kernel<<<dim3(16, 16), tb32>>>(Wo + (size_t)i * D_ * D_,
            woT + (size_t)i * D_ * D_, D_, D_);
        whtrans_kernel<<<dim3(64, 16), tb32>>>(Wc1 + (size_t)i * D_ * DFF_,
            wc1T + (size_t)i * DFF_ * D_, D_, DFF_);
        whtrans_kernel<<<dim3(16, 64), tb32>>>(Wc2 + (size_t)i * DFF_ * D_,
            wc2T + (size_t)i * D_ * DFF_, DFF_, D_);
    }
    whtrans_kernel<<<dim3(16, 1024), tb32>>>(W_head, whT, KHEAD_, T_);
    bqkv_kernel<<<NL_, 512>>>(bq, bk, bv);

    inst_stats_kernel<<<BC_, 256>>>(x_enc);
    patch_embed_kernel<<<ROWS_, 512>>>(x_enc, W_val);

    dim3 gqkv(1536 / 128, ROWS_ / 128);       // (12, 512)
    dim3 gproj(D_ / 128, ROWS_ / 128);        // (4, 512)
    dim3 gff1(DFF_ / 128, ROWS_ / 128);       // (16, 512)
    dim3 ghead(T_ / 128, BC_ / 128, KSPLIT_); // (4, 8, 8)

    for (int i = 0; i < NL_; i++) {
        hgemm_kernel<0><<<gqkv, 256, HG_SMEM>>>(tok_h, wqkvT + (size_t)i * 1536 * D_,
            bqkv + i * 1536, nullptr, qkv_h, ROWS_, 1536, D_, D_, D_);
        attn_kernel<<<BC_ * H_, 256, ATTN_SMEM>>>();
        hgemm_kernel<1><<<gproj, 256, HG_SMEM>>>(attn_h, woT + (size_t)i * D_ * D_,
            bo + i * D_, tok, tok, ROWS_, D_, D_, D_, D_);
        ln_kernel<<<ROWS_, 256>>>(tok, ln1_g + i * D_, ln1_b + i * D_, nullptr, y_h);
        hgemm_kernel<2><<<gff1, 256, HG_SMEM>>>(y_h, wc1T + (size_t)i * DFF_ * D_,
            bc1 + i * DFF_, nullptr, h_h, ROWS_, DFF_, D_, D_, D_);
        hgemm_kernel<1><<<gproj, 256, HG_SMEM>>>(h_h, wc2T + (size_t)i * D_ * DFF_,
            bc2 + i * D_, tok, tok, ROWS_, D_, DFF_, DFF_, DFF_);
        ln_kernel<<<ROWS_, 256>>>(tok, ln2_g + i * D_, ln2_b + i * D_, tok, tok_h);
    }

    bn_partial_kernel<<<256, 512>>>();
    bn_final_kernel<<<1, 512>>>(bn_g, bn_b);
    enc_transpose_kernel<<<BC_ * 32, dim3(32, 8)>>>();
    hgemm_kernel<4><<<ghead, 256, HG_SMEM>>>(enc_h, whT, nullptr, nullptr, hpart,
                                             BC_, T_, KCH_, KHEAD_, KHEAD_);
    head_final_kernel<<<BC_, T_>>>(b_head, out);
}

// round 8
// speedup vs baseline: 1.2297x; 1.1577x over previous
#include <cuda_runtime.h>
#include <cuda_fp16.h>
#include <math.h>
#include <stdint.h>

// ---------------- Problem constants ----------------
#define B_    32
#define T_    512
#define C_    32
#define D_    512
#define H_    8
#define E_    64
#define DFF_  2048
#define NL_   3
#define P_    16
#define N_    64
#define BC_   (B_*C_)          // 1024
#define ROWS_ ((BC_)*(N_))     // 65536
#define KSPLIT_ 8
#define KCH_    4096           // 32768 / 8
#define KHEAD_  (D_*N_)        // 32768

// ---------------- Scratch (device globals; no allocation) ----------------
__device__ float  g_mean[BC_];
__device__ float  g_std[BC_];
__device__ float  g_tok  [ROWS_ * D_];                      // fp32 residual stream
__device__ __align__(256) __half g_tok_h[ROWS_ * D_];       // tiled half (QKV input)
__device__ __align__(256) __half g_qkv_h[ROWS_ * 1536];     // tiled QKV output
__device__ __align__(256) __half g_attn_h[ROWS_ * D_];      // tiled attn output
__device__ __align__(256) __half g_y_h  [ROWS_ * D_];       // tiled ln1 output
__device__ __align__(256) __half g_h_h  [ROWS_ * DFF_];     // tiled gelu output
__device__ __align__(256) __half g_enc_h[BC_ * KHEAD_];     // tiled head input
__device__ float  g_hpart[KSPLIT_ * BC_ * T_];
__device__ float  g_psum [256 * D_];
__device__ float  g_psq  [256 * D_];
__device__ float  g_bna  [D_];
__device__ float  g_bnb  [D_];
__device__ float  g_bqkv [NL_ * 1536];
// transposed half weights ([N,K] K-major, tiled layout)
__device__ __align__(256) __half g_wqkvT[NL_ * 1536 * D_];
__device__ __align__(256) __half g_woT  [NL_ * D_ * D_];
__device__ __align__(256) __half g_wc1T [NL_ * DFF_ * D_];
__device__ __align__(256) __half g_wc2T [NL_ * D_ * DFF_];
__device__ __align__(256) __half g_whT  [T_ * KHEAD_];

// ---------------- tiled-swizzled layout ----------------
// Matrix [R, K] half, stored as 128x32 blocks (8KB each), block-row-major.
// Within block: row rr, 16B-chunk c stored at chunk c' = c ^ ((rr>>1)&3).
__device__ __forceinline__ size_t tidx(int r, int k, int K) {
    int rr = r & 127;
    int kk = k & 31;
    int c  = ((kk >> 3) ^ ((rr >> 1) & 3));
    return (((size_t)(r >> 7) * (size_t)(K >> 5) + (size_t)(k >> 5)) << 12)
         + (size_t)(rr * 32 + c * 8 + (kk & 7));
}

// ---------------- helpers ----------------
#define LDSM4(r0, r1, r2, r3, addr) \
    asm volatile("ldmatrix.sync.aligned.m8n8.x4.shared.b16 {%0,%1,%2,%3}, [%4];" \
        : "=r"(r0), "=r"(r1), "=r"(r2), "=r"(r3) : "r"(addr))

#define MBAR_INIT(addr, cnt) \
    asm volatile("mbarrier.init.shared.b64 [%0], %1;" :: "r"(addr), "r"(cnt) : "memory")
#define MBAR_EXPECT(addr, bytes) \
    asm volatile("mbarrier.arrive.expect_tx.shared.b64 _, [%0], %1;" :: "r"(addr), "r"(bytes) : "memory")
#define BULK_G2S(dst, src, bytes, bar) \
    asm volatile("cp.async.bulk.shared::cta.global.mbarrier::complete_tx::bytes [%0], [%1], %2, [%3];" \
        :: "r"(dst), "l"(src), "r"(bytes), "r"(bar) : "memory")
#define MBAR_WAIT(addr, par) do { \
    uint32_t _m = (addr), _p = (par), _d; \
    asm volatile("{\n\t.reg .pred p;\n\t" \
        "mbarrier.try_wait.parity.acquire.cta.shared::cta.b64 p, [%1], %2;\n\t" \
        "selp.b32 %0, 1, 0, p;\n\t}" : "=r"(_d) : "r"(_m), "r"(_p) : "memory"); \
    if (!_d) { \
        asm volatile("{\n\t.reg .pred P1;\n\t" \
            "WL_%=:\n\t" \
            "mbarrier.try_wait.parity.acquire.cta.shared::cta.b64 P1, [%0], %1, 0x989680;\n\t" \
            "@P1 bra.uni WD_%=;\n\t" \
            "bra.uni WL_%=;\n\t" \
            "WD_%=:\n\t}" :: "r"(_m), "r"(_p) : "memory"); \
    } \
} while (0)

__device__ __forceinline__ uint32_t smem_u32(const void* p) {
    uint32_t a;
    asm("{ .reg .u64 t; cvta.to.shared.u64 t, %1; cvt.u32.u64 %0, t; }" : "=r"(a) : "l"(p));
    return a;
}

// ---------------- Weight transpose -> half (tiled output) ----------------
__global__ void whtrans_kernel(const float* __restrict__ W, __half* __restrict__ WT,
                               int K, int Ncols) {
    __shared__ float s[32][33];
    int n0 = blockIdx.x * 32, k0 = blockIdx.y * 32;
    int tx = threadIdx.x, ty = threadIdx.y;   // 32 x 8
    #pragma unroll
    for (int j = 0; j < 32; j += 8)
        s[ty + j][tx] = W[(size_t)(k0 + ty + j) * Ncols + n0 + tx];
    __syncthreads();
    #pragma unroll
    for (int j = 0; j < 32; j += 8)
        WT[tidx(n0 + ty + j, k0 + tx, K)] = __float2half_rn(s[tx][ty + j]);
}

// fused QKV weight transpose for one layer: z in {0,1,2} selects q/k/v
__global__ void qkvtrans_kernel(const float* __restrict__ Wq, const float* __restrict__ Wk,
                                const float* __restrict__ Wv, __half* __restrict__ WT) {
    __shared__ float s[32][33];
    int z = blockIdx.z;
    const float* W = (z == 0) ? Wq : (z == 1) ? Wk : Wv;
    int n0 = blockIdx.x * 32, k0 = blockIdx.y * 32;
    int tx = threadIdx.x, ty = threadIdx.y;   // 32 x 8
    #pragma unroll
    for (int j = 0; j < 32; j += 8)
        s[ty + j][tx] = W[(size_t)(k0 + ty + j) * D_ + n0 + tx];
    __syncthreads();
    #pragma unroll
    for (int j = 0; j < 32; j += 8)
        WT[tidx(z * 512 + n0 + ty + j, k0 + tx, D_)] = __float2half_rn(s[tx][ty + j]);
}

__global__ void bqkv_kernel(const float* __restrict__ bq, const float* __restrict__ bk,
                            const float* __restrict__ bv) {
    int i = blockIdx.x, t = threadIdx.x;   // NL_ x 512
    g_bqkv[i * 1536 + t]        = bq[i * D_ + t];
    g_bqkv[i * 1536 + 512 + t]  = bk[i * D_ + t];
    g_bqkv[i * 1536 + 1024 + t] = bv[i * D_ + t];
}

// ---------------- Instance-norm stats over time ----------------
__global__ void inst_stats_kernel(const float* __restrict__ x_enc) {
    int bc = blockIdx.x;
    int b = bc >> 5, c = bc & 31;
    int tid = threadIdx.x;          // 256
    const float* p = x_enc + (size_t)b * T_ * C_ + c;
    float v0 = p[(size_t)tid * C_];
    float v1 = p[(size_t)(tid + 256) * C_];
    __shared__ float rs[256], rq[256];
    rs[tid] = v0 + v1; rq[tid] = v0 * v0 + v1 * v1;
    __syncthreads();
    for (int off = 128; off > 0; off >>= 1) {
        if (tid < off) { rs[tid] += rs[tid + off]; rq[tid] += rq[tid + off]; }
        __syncthreads();
    }
    if (tid == 0) {
        float mean = rs[0] / (float)T_;
        float var  = rq[0] / (float)T_ - mean * mean;
        g_mean[bc] = mean;
        g_std[bc]  = sqrtf(var + 1e-5f);
    }
}

// ---------------- Patch embedding + sinusoidal PE ----------------
__global__ void patch_embed_kernel(const float* __restrict__ x_enc,
                                   const float* __restrict__ W_val) {
    int bn = blockIdx.x;            // global token row
    int bc = bn >> 6, n = bn & 63;
    int b = bc >> 5, c = bc & 31;
    int d = threadIdx.x;            // 512
    __shared__ float pv[P_];
    if (d < P_) {
        int t = n * 8 + d;
        if (t > T_ - 1) t = T_ - 1;
        pv[d] = (x_enc[(size_t)(b * T_ + t) * C_ + c] - g_mean[bc]) / g_std[bc];
    }
    __syncthreads();
    int i2 = d >> 1;
    float div = expf(-(float)(2 * i2) * (logf(10000.0f) / (float)D_));
    float ang = (float)n * div;
    float acc = (d & 1) ? cosf(ang) : sinf(ang);
    #pragma unroll
    for (int p = 0; p < P_; p++)
        acc = fmaf(pv[p], W_val[p * D_ + d], acc);
    g_tok  [(size_t)bn * D_ + d] = acc;
    g_tok_h[tidx(bn, d, D_)]     = __float2half_rn(acc);
}

// ---------------- FP16 mma GEMM: TMA-bulk staged, 128x128x32 tiles ----------------
// A: [M,K] half tiled; BT: [N,K] half tiled
// EPI 0: Ch = h(A*B + bias)      (tiled half out, K-layout = N)
// EPI 1: Cf = A*B + bias + res   (fp32 row-major out)
// EPI 2: Ch = h(gelu(A*B+bias))  (tiled half out)
// EPI 4: Cf = A*B  (fp32 row-major split-K partials via blockIdx.z)
#define NSTG   4
#define STG_B  16384
#define HG_SMEM (64 + NSTG * STG_B)     // 65600 bytes

template<int EPI>
__global__ __launch_bounds__(256, 2)
void hgemm_kernel(const __half* __restrict__ A, const __half* __restrict__ BT,
                  const float* __restrict__ bias, const float* __restrict__ res,
                  void* __restrict__ Cv, int M, int N, int K, int lda, int ldb) {
    extern __shared__ __half smh[];
    const uint32_t sbase = smem_u32(smh);
    const uint32_t stg0  = sbase + 64;

    int koff = 0;
    if (EPI == 4) koff = blockIdx.z * KCH_;

    const int tid  = threadIdx.x;
    const int warp = tid >> 5, lane = tid & 31;
    const int wm = warp >> 1, wn = warp & 1;       // 4x2 warps, 32x64 warp tile
    const int lr = lane >> 2, lc = lane & 3;
    const int bm = blockIdx.y * 128, bn = blockIdx.x * 128;
    const size_t aBlkRow = (size_t)(bm >> 7) * (size_t)(lda >> 5);
    const size_t bBlkRow = (size_t)(bn >> 7) * (size_t)(ldb >> 5);

    if (tid < NSTG) MBAR_INIT(sbase + tid * 8, 1);
    __syncthreads();

    float acc[2][8][4];
    #pragma unroll
    for (int mt = 0; mt < 2; mt++)
        #pragma unroll
        for (int nt = 0; nt < 8; nt++)
            #pragma unroll
            for (int i = 0; i < 4; i++) acc[mt][nt][i] = 0.0f;

    // ldmatrix per-lane precompute (byte offsets within stage + swizzle key)
    uint32_t aQ[2]; int aS[2];
    #pragma unroll
    for (int mt = 0; mt < 2; mt++) {
        int rr = wm * 32 + mt * 16 + (lane & 15);
        aQ[mt] = (uint32_t)(rr * 64);
        aS[mt] = (rr >> 1) & 3;
    }
    uint32_t bQ[4]; int bS[4];
    #pragma unroll
    for (int ng = 0; ng < 4; ng++) {
        int rr = wn * 64 + ng * 16 + (lane & 15);
        bQ[ng] = (uint32_t)(8192 + rr * 64);
        bS[ng] = (rr >> 1) & 3;
    }
    const int hs = lane >> 4;

    const int NIT = K >> 5;

    auto FILL = [&](int s, int k0) {
        if (tid == 0) {
            uint32_t bar = sbase + s * 8;
            MBAR_EXPECT(bar, 16384);
            const __half* sa = A  + ((aBlkRow + (size_t)((koff + k0) >> 5)) << 12);
            const __half* sb = BT + ((bBlkRow + (size_t)((koff + k0) >> 5)) << 12);
            uint32_t st = stg0 + s * STG_B;
            BULK_G2S(st,        sa, 8192, bar);
            BULK_G2S(st + 8192, sb, 8192, bar);
        }
    };

    FILL(0, 0); FILL(1, 32); FILL(2, 64);

    for (int it = 0; it < NIT; ++it) {
        const int s = it & 3;
        MBAR_WAIT(sbase + s * 8, (it >> 2) & 1);
        __syncthreads();
        if (it + 3 < NIT) FILL((it + 3) & 3, (it + 3) << 5);

        const uint32_t st = stg0 + s * STG_B;
        #pragma unroll
        for (int ks = 0; ks < 2; ks++) {
            uint32_t af[2][4];
            #pragma unroll
            for (int mt = 0; mt < 2; mt++)
                LDSM4(af[mt][0], af[mt][1], af[mt][2], af[mt][3],
                      st + aQ[mt] + (uint32_t)((((ks << 1) | hs) ^ aS[mt]) << 4));
            uint32_t bq[4][4];
            #pragma unroll
            for (int ng = 0; ng < 4; ng++)
                LDSM4(bq[ng][0], bq[ng][1], bq[ng][2], bq[ng][3],
                      st + bQ[ng] + (uint32_t)((((ks << 1) | hs) ^ bS[ng]) << 4));
            #pragma unroll
            for (int mt = 0; mt < 2; mt++)
                #pragma unroll
                for (int nt = 0; nt < 8; nt++) {
                    uint32_t b0 = bq[nt >> 1][nt & 1];
                    uint32_t b1 = bq[nt >> 1][(nt & 1) + 2];
                    asm volatile(
                        "mma.sync.aligned.m16n8k16.row.col.f32.f16.f16.f32 "
                        "{%0,%1,%2,%3},{%4,%5,%6,%7},{%8,%9},{%0,%1,%2,%3};"
                        : "+f"(acc[mt][nt][0]), "+f"(acc[mt][nt][1]),
                          "+f"(acc[mt][nt][2]), "+f"(acc[mt][nt][3])
                        : "r"(af[mt][0]), "r"(af[mt][1]),
                          "r"(af[mt][2]), "r"(af[mt][3]),
                          "r"(b0), "r"(b1));
                }
        }
        __syncthreads();
    }

    // ---------------- epilogue ----------------
    float* Cf = (float*)Cv;
    __half* Ch = (__half*)Cv;
    if (EPI == 4) Cf += (size_t)blockIdx.z * M * N;

    #pragma unroll
    for (int mt = 0; mt < 2; mt++) {
        #pragma unroll
        for (int half = 0; half < 2; half++) {
            int m = bm + wm * 32 + mt * 16 + lr + half * 8;
            #pragma unroll
            for (int nt = 0; nt < 8; nt++) {
                int col = bn + wn * 64 + nt * 8 + lc * 2;
                float v0 = acc[mt][nt][half * 2 + 0];
                float v1 = acc[mt][nt][half * 2 + 1];
                if (EPI != 4) { v0 += bias[col]; v1 += bias[col + 1]; }
                if (EPI == 1) {
                    const float2 r2 = *(const float2*)(res + (size_t)m * N + col);
                    v0 += r2.x; v1 += r2.y;
                }
                if (EPI == 2) {
                    v0 = 0.5f * v0 * (1.0f + erff(v0 * 0.70710678118654752f));
                    v1 = 0.5f * v1 * (1.0f + erff(v1 * 0.70710678118654752f));
                }
                if (EPI == 0 || EPI == 2) {
                    __half2 hv;
                    hv.x = __float2half_rn(v0); hv.y = __float2half_rn(v1);
                    *(__half2*)(Ch + tidx(m, col, N)) = hv;
                } else {
                    *(float2*)(Cf + (size_t)m * N + col) = make_float2(v0, v1);
                }
            }
        }
    }
}

// ---------------- Attention (per bc, per head), register-tiled ----------------
#define ATTN_SMEM (4 * 64 * 68 * 4)
__global__ void attn_kernel() {
    int bh = blockIdx.x;
    int bc = bh >> 3, h = bh & 7;
    extern __shared__ float sm[];
    float* qs = sm;
    float* kt = qs + 64 * 68;
    float* vs = kt + 64 * 68;
    float* ss = vs + 64 * 68;
    int tid = threadIdx.x;   // 256
    const int kq = h * 64, kk0 = 512 + h * 64, kv0 = 1024 + h * 64;

    #pragma unroll
    for (int i = 0; i < 16; i++) {
        int flat = i * 256 + tid;
        int r = flat >> 6, e = flat & 63;
        int R = bc * 64 + r;
        qs[r * 68 + e] = __half2float(g_qkv_h[tidx(R, kq  + e, 1536)]);
        kt[e * 68 + r] = __half2float(g_qkv_h[tidx(R, kk0 + e, 1536)]);
        vs[r * 68 + e] = __half2float(g_qkv_h[tidx(R, kv0 + e, 1536)]);
    }
    __syncthreads();

    const int l  = tid >> 2;
    const int sq = tid & 3;
    const int s0 = sq << 4;

    float a[16];
    #pragma unroll
    for (int j = 0; j < 16; j++) a[j] = 0.0f;
    for (int e = 0; e < 64; e++) {
        float qv = qs[l * 68 + e];
        const float* kr = &kt[e * 68 + s0];
        float4 k0 = *(const float4*)(kr);
        float4 k1 = *(const float4*)(kr + 4);
        float4 k2 = *(const float4*)(kr + 8);
        float4 k3 = *(const float4*)(kr + 12);
        a[0]  = fmaf(qv, k0.x, a[0]);  a[1]  = fmaf(qv, k0.y, a[1]);
        a[2]  = fmaf(qv, k0.z, a[2]);  a[3]  = fmaf(qv, k0.w, a[3]);
        a[4]  = fmaf(qv, k1.x, a[4]);  a[5]  = fmaf(qv, k1.y, a[5]);
        a[6]  = fmaf(qv, k1.z, a[6]);  a[7]  = fmaf(qv, k1.w, a[7]);
        a[8]  = fmaf(qv, k2.x, a[8]);  a[9]  = fmaf(qv, k2.y, a[9]);
        a[10] = fmaf(qv, k2.z, a[10]); a[11] = fmaf(qv, k2.w, a[11]);
        a[12] = fmaf(qv, k3.x, a[12]); a[13] = fmaf(qv, k3.y, a[13]);
        a[14] = fmaf(qv, k3.z, a[14]); a[15] = fmaf(qv, k3.w, a[15]);
    }
    float mx = -1e30f;
    #pragma unroll
    for (int j = 0; j < 16; j++) { a[j] *= 0.125f; mx = fmaxf(mx, a[j]); }
    mx = fmaxf(mx, __shfl_xor_sync(0xffffffffu, mx, 1));
    mx = fmaxf(mx, __shfl_xor_sync(0xffffffffu, mx, 2));
    float sum = 0.0f;
    #pragma unroll
    for (int j = 0; j < 16; j++) { a[j] = expf(a[j] - mx); sum += a[j]; }
    sum += __shfl_xor_sync(0xffffffffu, sum, 1);
    sum += __shfl_xor_sync(0xffffffffu, sum, 2);
    float inv = 1.0f / sum;
    #pragma unroll
    for (int j = 0; j < 16; j++) ss[l * 68 + s0 + j] = a[j] * inv;
    __syncthreads();

    const int e0 = s0;
    float o[16];
    #pragma unroll
    for (int j = 0; j < 16; j++) o[j] = 0.0f;
    for (int s = 0; s < 64; s++) {
        float av = ss[l * 68 + s];
        const float* vr = &vs[s * 68 + e0];
        float4 v0 = *(const float4*)(vr);
        float4 v1 = *(const float4*)(vr + 4);
        float4 v2 = *(const float4*)(vr + 8);
        float4 v3 = *(const float4*)(vr + 12);
        o[0]  = fmaf(av, v0.x, o[0]);  o[1]  = fmaf(av, v0.y, o[1]);
        o[2]  = fmaf(av, v0.z, o[2]);  o[3]  = fmaf(av, v0.w, o[3]);
        o[4]  = fmaf(av, v1.x, o[4]);  o[5]  = fmaf(av, v1.y, o[5]);
        o[6]  = fmaf(av, v1.z, o[6]);  o[7]  = fmaf(av, v1.w, o[7]);
        o[8]  = fmaf(av, v2.x, o[8]);  o[9]  = fmaf(av, v2.y, o[9]);
        o[10] = fmaf(av, v2.z, o[10]); o[11] = fmaf(av, v2.w, o[11]);
        o[12] = fmaf(av, v3.x, o[12]); o[13] = fmaf(av, v3.y, o[13]);
        o[14] = fmaf(av, v3.z, o[14]); o[15] = fmaf(av, v3.w, o[15]);
    }
    int Rw = bc * 64 + l;
    #pragma unroll
    for (int j = 0; j < 16; j += 2) {
        __half2 hv;
        hv.x = __float2half_rn(o[j]); hv.y = __float2half_rn(o[j + 1]);
        *(__half2*)(g_attn_h + tidx(Rw, h * 64 + e0 + j, D_)) = hv;
    }
}

// ---------------- LayerNorm (row of 512) ----------------
__global__ void ln_kernel(const float* __restrict__ X,
                          const float* __restrict__ g, const float* __restrict__ b,
                          float* __restrict__ Yf, __half* __restrict__ Yh) {
    int row = blockIdx.x;
    int tid = threadIdx.x;  // 256
    const float* x = X + (size_t)row * D_;
    float v0 = x[tid], v1 = x[tid + 256];
    __shared__ float rs[256], rq[256];
    rs[tid] = v0 + v1;
    rq[tid] = v0 * v0 + v1 * v1;
    __syncthreads();
    for (int off = 128; off > 0; off >>= 1) {
        if (tid < off) { rs[tid] += rs[tid + off]; rq[tid] += rq[tid + off]; }
        __syncthreads();
    }
    __shared__ float s_mean, s_inv;
    if (tid == 0) {
        float mean = rs[0] / (float)D_;
        float var  = rq[0] / (float)D_ - mean * mean;
        s_mean = mean;
        s_inv  = rsqrtf(var + 1e-5f);
    }
    __syncthreads();
    float mean = s_mean, inv = s_inv;
    float o0 = (v0 - mean) * inv * g[tid]       + b[tid];
    float o1 = (v1 - mean) * inv * g[tid + 256] + b[tid + 256];
    if (Yf) {
        Yf[(size_t)row * D_ + tid]       = o0;
        Yf[(size_t)row * D_ + tid + 256] = o1;
    }
    if (Yh) {
        Yh[tidx(row, tid, D_)]       = __float2half_rn(o0);
        Yh[tidx(row, tid + 256, D_)] = __float2half_rn(o1);
    }
}

// ---------------- BatchNorm stats (deterministic 2-stage) ----------------
__global__ void bn_partial_kernel() {
    int blk = blockIdx.x;
    int d = threadIdx.x;      // 512
    float s = 0.0f, q = 0.0f;
    const float* base = g_tok + (size_t)blk * 256 * D_ + d;
    for (int r = 0; r < 256; r++) {
        float v = base[(size_t)r * D_];
        s += v; q += v * v;
    }
    g_psum[blk * D_ + d] = s;
    g_psq [blk * D_ + d] = q;
}

__global__ void bn_final_kernel(const float* __restrict__ gam,
                                const float* __restrict__ bet) {
    int d = threadIdx.x;      // 512, one block
    float s = 0.0f, q = 0.0f;
    for (int i = 0; i < 256; i++) {
        s += g_psum[i * D_ + d];
        q += g_psq [i * D_ + d];
    }
    float mean = s / (float)ROWS_;
    float var  = q / (float)ROWS_ - mean * mean;
    float a = gam[d] * rsqrtf(var + 1e-5f);
    g_bna[d] = a;
    g_bnb[d] = bet[d] - mean * a;
}

// ---------------- BN apply + (N,D)->(D,N) transpose into enc (tiled half) ----------------
__global__ void enc_transpose_kernel() {
    __shared__ float sm[32][33];
    int bid = blockIdx.x;
    int bc = bid >> 5;
    int r = bid & 31;
    int dt = r >> 1, nt = r & 1;
    int tx = threadIdx.x, ty = threadIdx.y;   // 32 x 8
    int d0 = dt * 32, n0 = nt * 32;
    #pragma unroll
    for (int j = 0; j < 32; j += 8) {
        int n = n0 + ty + j;
        int d = d0 + tx;
        float v = g_tok[((size_t)bc * 64 + n) * D_ + d];
        sm[ty + j][tx] = v * g_bna[d] + g_bnb[d];
    }
    __syncthreads();
    #pragma unroll
    for (int j = 0; j < 32; j += 8) {
        int d = d0 + ty + j;
        int n = n0 + tx;
        g_enc_h[tidx(bc, d * N_ + n, KHEAD_)] = __float2half_rn(sm[tx][ty + j]);
    }
}

// ---------------- head final: sum split-K partials + bias + denorm ----------------
__global__ void head_final_kernel(const float* __restrict__ b_head,
                                  float* __restrict__ out) {
    int m = blockIdx.x;        // bc
    int t = threadIdx.x;       // 512
    float v = b_head[t];
    #pragma unroll
    for (int z = 0; z < KSPLIT_; z++)
        v += g_hpart[((size_t)z * BC_ + m) * T_ + t];
    int b = m >> 5, c = m & 31;
    out[((size_t)b * T_ + t) * C_ + c] = v * g_std[m] + g_mean[m];
}

// ---------------- Launch ----------------
extern "C" void kernel_launch(void* const* d_in, const int* in_sizes, int n_in,
                              void* d_out, int out_size) {
    const float* x_enc = (const float*)d_in[0];
    const float* W_val = (const float*)d_in[1];
    const float* Wq    = (const float*)d_in[2];
    const float* bq    = (const float*)d_in[3];
    const float* Wk    = (const float*)d_in[4];
    const float* bk    = (const float*)d_in[5];
    const float* Wv    = (const float*)d_in[6];
    const float* bv    = (const float*)d_in[7];
    const float* Wo    = (const float*)d_in[8];
    const float* bo    = (const float*)d_in[9];
    const float* Wc1   = (const float*)d_in[10];
    const float* bc1   = (const float*)d_in[11];
    const float* Wc2   = (const float*)d_in[12];
    const float* bc2   = (const float*)d_in[13];
    const float* ln1_g = (const float*)d_in[14];
    const float* ln1_b = (const float*)d_in[15];
    const float* ln2_g = (const float*)d_in[16];
    const float* ln2_b = (const float*)d_in[17];
    const float* bn_g  = (const float*)d_in[18];
    const float* bn_b  = (const float*)d_in[19];
    const float* W_head= (const float*)d_in[20];
    const float* b_head= (const float*)d_in[21];
    float* out = (float*)d_out;

    float *tok, *hpart, *bqkv;
    __half *tok_h, *qkv_h, *attn_h, *y_h, *h_h, *enc_h;
    __half *wqkvT, *woT, *wc1T, *wc2T, *whT;
    cudaGetSymbolAddress((void**)&tok,    g_tok);
    cudaGetSymbolAddress((void**)&tok_h,  g_tok_h);
    cudaGetSymbolAddress((void**)&qkv_h,  g_qkv_h);
    cudaGetSymbolAddress((void**)&attn_h, g_attn_h);
    cudaGetSymbolAddress((void**)&y_h,    g_y_h);
    cudaGetSymbolAddress((void**)&h_h,    g_h_h);
    cudaGetSymbolAddress((void**)&enc_h,  g_enc_h);
    cudaGetSymbolAddress((void**)&hpart,  g_hpart);
    cudaGetSymbolAddress((void**)&bqkv,   g_bqkv);
    cudaGetSymbolAddress((void**)&wqkvT,  g_wqkvT);
    cudaGetSymbolAddress((void**)&woT,    g_woT);
    cudaGetSymbolAddress((void**)&wc1T,   g_wc1T);
    cudaGetSymbolAddress((void**)&wc2T,   g_wc2T);
    cudaGetSymbolAddress((void**)&whT,    g_whT);

    cudaFuncSetAttribute(attn_kernel, cudaFuncAttributeMaxDynamicSharedMemorySize, ATTN_SMEM);
    cudaFuncSetAttribute(hgemm_kernel<0>, cudaFuncAttributeMaxDynamicSharedMemorySize, HG_SMEM);
    cudaFuncSetAttribute(hgemm_kernel<1>, cudaFuncAttributeMaxDynamicSharedMemorySize, HG_SMEM);
    cudaFuncSetAttribute(hgemm_kernel<2>, cudaFuncAttributeMaxDynamicSharedMemorySize, HG_SMEM);
    cudaFuncSetAttribute(hgemm_kernel<4>, cudaFuncAttributeMaxDynamicSharedMemorySize, HG_SMEM);

    dim3 tb32(32, 8);
    dim3 gqkv(1536 / 128, ROWS_ / 128);       // (12, 512)
    dim3 gproj(D_ / 128, ROWS_ / 128);        // (4, 512)
    dim3 gff1(DFF_ / 128, ROWS_ / 128);       // (16, 512)
    dim3 ghead(T_ / 128, BC_ / 128, KSPLIT_); // (4, 8, 8)

    // launches 1-5 (so launch #6 = hgemm<0> for ncu -s 5 -c 1)
    inst_stats_kernel<<<BC_, 256>>>(x_enc);                                       // 1
    patch_embed_kernel<<<ROWS_, 512>>>(x_enc, W_val);                             // 2
    bqkv_kernel<<<NL_, 512>>>(bq, bk, bv);                                        // 3
    qkvtrans_kernel<<<dim3(16, 16, 3), tb32>>>(Wq, Wk, Wv, wqkvT);                // 4 (L0)
    whtrans_kernel<<<dim3(16, 16), tb32>>>(Wo, woT, D_, D_);                      // 5 (L0)

    for (int i = 0; i < NL_; i++) {
        if (i > 0) {
            qkvtrans_kernel<<<dim3(16, 16, 3), tb32>>>(Wq + (size_t)i * D_ * D_,
                Wk + (size_t)i * D_ * D_, Wv + (size_t)i * D_ * D_,
                wqkvT + (size_t)i * 1536 * D_);
            whtrans_kernel<<<dim3(16, 16), tb32>>>(Wo + (size_t)i * D_ * D_,
                woT + (size_t)i * D_ * D_, D_, D_);
        }
        hgemm_kernel<0><<<gqkv, 256, HG_SMEM>>>(tok_h, wqkvT + (size_t)i * 1536 * D_,
            bqkv + i * 1536, nullptr, qkv_h, ROWS_, 1536, D_, D_, D_);            // 6 for i=0
        whtrans_kernel<<<dim3(64, 16), tb32>>>(Wc1 + (size_t)i * D_ * DFF_,
            wc1T + (size_t)i * DFF_ * D_, D_, DFF_);
        whtrans_kernel<<<dim3(16, 64), tb32>>>(Wc2 + (size_t)i * DFF_ * D_,
            wc2T + (size_t)i * D_ * DFF_, DFF_, D_);
        attn_kernel<<<BC_ * H_, 256, ATTN_SMEM>>>();
        hgemm_kernel<1><<<gproj, 256, HG_SMEM>>>(attn_h, woT + (size_t)i * D_ * D_,
            bo + i * D_, tok, tok, ROWS_, D_, D_, D_, D_);
        ln_kernel<<<ROWS_, 256>>>(tok, ln1_g + i * D_, ln1_b + i * D_, nullptr, y_h);
        hgemm_kernel<2><<<gff1, 256, HG_SMEM>>>(y_h, wc1T + (size_t)i * DFF_ * D_,
            bc1 + i * DFF_, nullptr, h_h, ROWS_, DFF_, D_, D_, D_);
        hgemm_kernel<1><<<gproj, 256, HG_SMEM>>>(h_h, wc2T + (size_t)i * D_ * DFF_,
            bc2 + i * D_, tok, tok, ROWS_, D_, DFF_, DFF_, DFF_);
        ln_kernel<<<ROWS_, 256>>>(tok, ln2_g + i * D_, ln2_b + i * D_, tok, tok_h);
    }

    whtrans_kernel<<<dim3(16, 1024), tb32>>>(W_head, whT, KHEAD_, T_);
    bn_partial_kernel<<<256, 512>>>();
    bn_final_kernel<<<1, 512>>>(bn_g, bn_b);
    enc_transpose_kernel<<<BC_ * 32, dim3(32, 8)>>>();
    hgemm_kernel<4><<<ghead, 256, HG_SMEM>>>(enc_h, whT, nullptr, nullptr, hpart,
                                             BC_, T_, KCH_, KHEAD_, KHEAD_);
    head_final_kernel<<<BC_, T_>>>(b_head, out);
}

// round 9
// speedup vs baseline: 2.0062x; 1.6314x over previous
#include <cuda_runtime.h>
#include <cuda_fp16.h>
#include <math.h>
#include <stdint.h>

// ---------------- Problem constants ----------------
#define B_    32
#define T_    512
#define C_    32
#define D_    512
#define H_    8
#define E_    64
#define DFF_  2048
#define NL_   3
#define P_    16
#define N_    64
#define BC_   (B_*C_)          // 1024
#define ROWS_ ((BC_)*(N_))     // 65536
#define KSPLIT_ 8
#define KCH_    4096           // 32768 / 8
#define KHEAD_  (D_*N_)        // 32768

// ---------------- Scratch (device globals; no allocation) ----------------
__device__ float  g_mean[BC_];
__device__ float  g_std[BC_];
__device__ float  g_tok  [ROWS_ * D_];                      // fp32 residual stream
__device__ __align__(256) __half g_tok_h[ROWS_ * D_];       // tiled half (QKV input)
__device__ __align__(256) __half g_qkv_h[ROWS_ * 1536];     // tiled QKV output
__device__ __align__(256) __half g_attn_h[ROWS_ * D_];      // tiled attn output
__device__ __align__(256) __half g_y_h  [ROWS_ * D_];       // tiled ln1 output
__device__ __align__(256) __half g_h_h  [ROWS_ * DFF_];     // tiled gelu output
__device__ __align__(256) __half g_enc_h[BC_ * KHEAD_];     // tiled head input
__device__ float  g_hpart[KSPLIT_ * BC_ * T_];
__device__ float  g_psum [256 * D_];
__device__ float  g_psq  [256 * D_];
__device__ float  g_bna  [D_];
__device__ float  g_bnb  [D_];
__device__ float  g_bqkv [NL_ * 1536];
// transposed half weights ([N,K] K-major, tiled layout)
__device__ __align__(256) __half g_wqkvT[NL_ * 1536 * D_];
__device__ __align__(256) __half g_woT  [NL_ * D_ * D_];
__device__ __align__(256) __half g_wc1T [NL_ * DFF_ * D_];
__device__ __align__(256) __half g_wc2T [NL_ * D_ * DFF_];
__device__ __align__(256) __half g_whT  [T_ * KHEAD_];

// ---------------- tiled-swizzled layout ----------------
// Matrix [R, K] half, stored as 128x32 blocks (8KB each), block-row-major.
// Within block: row rr, 16B-chunk c stored at chunk c' = c ^ ((rr>>1)&3).
__device__ __forceinline__ size_t tidx(int r, int k, int K) {
    int rr = r & 127;
    int kk = k & 31;
    int c  = ((kk >> 3) ^ ((rr >> 1) & 3));
    return (((size_t)(r >> 7) * (size_t)(K >> 5) + (size_t)(k >> 5)) << 12)
         + (size_t)(rr * 32 + c * 8 + (kk & 7));
}

// ---------------- helpers ----------------
#define LDSM4(r0, r1, r2, r3, addr) \
    asm volatile("ldmatrix.sync.aligned.m8n8.x4.shared.b16 {%0,%1,%2,%3}, [%4];" \
        : "=r"(r0), "=r"(r1), "=r"(r2), "=r"(r3) : "r"(addr))
#define LDSM4T(r0, r1, r2, r3, addr) \
    asm volatile("ldmatrix.sync.aligned.m8n8.x4.trans.shared.b16 {%0,%1,%2,%3}, [%4];" \
        : "=r"(r0), "=r"(r1), "=r"(r2), "=r"(r3) : "r"(addr))
#define HMMA(acc, a0, a1, a2, a3, b0, b1) \
    asm volatile("mma.sync.aligned.m16n8k16.row.col.f32.f16.f16.f32 " \
        "{%0,%1,%2,%3},{%4,%5,%6,%7},{%8,%9},{%0,%1,%2,%3};" \
        : "+f"((acc)[0]), "+f"((acc)[1]), "+f"((acc)[2]), "+f"((acc)[3]) \
        : "r"(a0), "r"(a1), "r"(a2), "r"(a3), "r"(b0), "r"(b1))

#define MBAR_INIT(addr, cnt) \
    asm volatile("mbarrier.init.shared.b64 [%0], %1;" :: "r"(addr), "r"(cnt) : "memory")
#define MBAR_EXPECT(addr, bytes) \
    asm volatile("mbarrier.arrive.expect_tx.shared.b64 _, [%0], %1;" :: "r"(addr), "r"(bytes) : "memory")
#define BULK_G2S(dst, src, bytes, bar) \
    asm volatile("cp.async.bulk.shared::cta.global.mbarrier::complete_tx::bytes [%0], [%1], %2, [%3];" \
        :: "r"(dst), "l"(src), "r"(bytes), "r"(bar) : "memory")
#define MBAR_WAIT(addr, par) do { \
    uint32_t _m = (addr), _p = (par), _d; \
    asm volatile("{\n\t.reg .pred p;\n\t" \
        "mbarrier.try_wait.parity.acquire.cta.shared::cta.b64 p, [%1], %2;\n\t" \
        "selp.b32 %0, 1, 0, p;\n\t}" : "=r"(_d) : "r"(_m), "r"(_p) : "memory"); \
    if (!_d) { \
        asm volatile("{\n\t.reg .pred P1;\n\t" \
            "WL_%=:\n\t" \
            "mbarrier.try_wait.parity.acquire.cta.shared::cta.b64 P1, [%0], %1, 0x989680;\n\t" \
            "@P1 bra.uni WD_%=;\n\t" \
            "bra.uni WL_%=;\n\t" \
            "WD_%=:\n\t}" :: "r"(_m), "r"(_p) : "memory"); \
    } \
} while (0)

__device__ __forceinline__ uint32_t smem_u32(const void* p) {
    uint32_t a;
    asm("{ .reg .u64 t; cvta.to.shared.u64 t, %1; cvt.u32.u64 %0, t; }" : "=r"(a) : "l"(p));
    return a;
}
__device__ __forceinline__ uint32_t h2pack(float x, float y) {
    __half2 h; h.x = __float2half_rn(x); h.y = __float2half_rn(y);
    return *(uint32_t*)&h;
}

// ---------------- Weight transpose -> half (tiled output) ----------------
__global__ void whtrans_kernel(const float* __restrict__ W, __half* __restrict__ WT,
                               int K, int Ncols) {
    __shared__ float s[32][33];
    int n0 = blockIdx.x * 32, k0 = blockIdx.y * 32;
    int tx = threadIdx.x, ty = threadIdx.y;   // 32 x 8
    #pragma unroll
    for (int j = 0; j < 32; j += 8)
        s[ty + j][tx] = W[(size_t)(k0 + ty + j) * Ncols + n0 + tx];
    __syncthreads();
    #pragma unroll
    for (int j = 0; j < 32; j += 8)
        WT[tidx(n0 + ty + j, k0 + tx, K)] = __float2half_rn(s[tx][ty + j]);
}

// fused QKV weight transpose for one layer: z in {0,1,2} selects q/k/v
__global__ void qkvtrans_kernel(const float* __restrict__ Wq, const float* __restrict__ Wk,
                                const float* __restrict__ Wv, __half* __restrict__ WT) {
    __shared__ float s[32][33];
    int z = blockIdx.z;
    const float* W = (z == 0) ? Wq : (z == 1) ? Wk : Wv;
    int n0 = blockIdx.x * 32, k0 = blockIdx.y * 32;
    int tx = threadIdx.x, ty = threadIdx.y;   // 32 x 8
    #pragma unroll
    for (int j = 0; j < 32; j += 8)
        s[ty + j][tx] = W[(size_t)(k0 + ty + j) * D_ + n0 + tx];
    __syncthreads();
    #pragma unroll
    for (int j = 0; j < 32; j += 8)
        WT[tidx(z * 512 + n0 + ty + j, k0 + tx, D_)] = __float2half_rn(s[tx][ty + j]);
}

__global__ void bqkv_kernel(const float* __restrict__ bq, const float* __restrict__ bk,
                            const float* __restrict__ bv) {
    int i = blockIdx.x, t = threadIdx.x;   // NL_ x 512
    g_bqkv[i * 1536 + t]        = bq[i * D_ + t];
    g_bqkv[i * 1536 + 512 + t]  = bk[i * D_ + t];
    g_bqkv[i * 1536 + 1024 + t] = bv[i * D_ + t];
}

// ---------------- Instance-norm stats over time ----------------
__global__ void inst_stats_kernel(const float* __restrict__ x_enc) {
    int bc = blockIdx.x;
    int b = bc >> 5, c = bc & 31;
    int tid = threadIdx.x;          // 256
    const float* p = x_enc + (size_t)b * T_ * C_ + c;
    float v0 = p[(size_t)tid * C_];
    float v1 = p[(size_t)(tid + 256) * C_];
    __shared__ float rs[256], rq[256];
    rs[tid] = v0 + v1; rq[tid] = v0 * v0 + v1 * v1;
    __syncthreads();
    for (int off = 128; off > 0; off >>= 1) {
        if (tid < off) { rs[tid] += rs[tid + off]; rq[tid] += rq[tid + off]; }
        __syncthreads();
    }
    if (tid == 0) {
        float mean = rs[0] / (float)T_;
        float var  = rq[0] / (float)T_ - mean * mean;
        g_mean[bc] = mean;
        g_std[bc]  = sqrtf(var + 1e-5f);
    }
}

// ---------------- Patch embedding + sinusoidal PE ----------------
__global__ void patch_embed_kernel(const float* __restrict__ x_enc,
                                   const float* __restrict__ W_val) {
    int bn = blockIdx.x;            // global token row
    int bc = bn >> 6, n = bn & 63;
    int b = bc >> 5, c = bc & 31;
    int d = threadIdx.x;            // 512
    __shared__ float pv[P_];
    if (d < P_) {
        int t = n * 8 + d;
        if (t > T_ - 1) t = T_ - 1;
        pv[d] = (x_enc[(size_t)(b * T_ + t) * C_ + c] - g_mean[bc]) / g_std[bc];
    }
    __syncthreads();
    int i2 = d >> 1;
    float div = expf(-(float)(2 * i2) * (logf(10000.0f) / (float)D_));
    float ang = (float)n * div;
    float acc = (d & 1) ? cosf(ang) : sinf(ang);
    #pragma unroll
    for (int p = 0; p < P_; p++)
        acc = fmaf(pv[p], W_val[p * D_ + d], acc);
    g_tok  [(size_t)bn * D_ + d] = acc;
    g_tok_h[tidx(bn, d, D_)]     = __float2half_rn(acc);
}

// ---------------- FP16 mma GEMM: TMA-bulk staged, 128x128x32 tiles ----------------
#define NSTG   4
#define STG_B  16384
#define HG_SMEM (64 + NSTG * STG_B)     // 65600 bytes

template<int EPI>
__global__ __launch_bounds__(256, 2)
void hgemm_kernel(const __half* __restrict__ A, const __half* __restrict__ BT,
                  const float* __restrict__ bias, const float* __restrict__ res,
                  void* __restrict__ Cv, int M, int N, int K, int lda, int ldb) {
    extern __shared__ __half smh[];
    const uint32_t sbase = smem_u32(smh);
    const uint32_t stg0  = sbase + 64;

    int koff = 0;
    if (EPI == 4) koff = blockIdx.z * KCH_;

    const int tid  = threadIdx.x;
    const int warp = tid >> 5, lane = tid & 31;
    const int wm = warp >> 1, wn = warp & 1;       // 4x2 warps, 32x64 warp tile
    const int lr = lane >> 2, lc = lane & 3;
    const int bm = blockIdx.y * 128, bn = blockIdx.x * 128;
    const size_t aBlkRow = (size_t)(bm >> 7) * (size_t)(lda >> 5);
    const size_t bBlkRow = (size_t)(bn >> 7) * (size_t)(ldb >> 5);

    if (tid < NSTG) MBAR_INIT(sbase + tid * 8, 1);
    __syncthreads();

    float acc[2][8][4];
    #pragma unroll
    for (int mt = 0; mt < 2; mt++)
        #pragma unroll
        for (int nt = 0; nt < 8; nt++)
            #pragma unroll
            for (int i = 0; i < 4; i++) acc[mt][nt][i] = 0.0f;

    uint32_t aQ[2]; int aS[2];
    #pragma unroll
    for (int mt = 0; mt < 2; mt++) {
        int rr = wm * 32 + mt * 16 + (lane & 15);
        aQ[mt] = (uint32_t)(rr * 64);
        aS[mt] = (rr >> 1) & 3;
    }
    uint32_t bQ[4]; int bS[4];
    #pragma unroll
    for (int ng = 0; ng < 4; ng++) {
        int rr = wn * 64 + ng * 16 + (lane & 15);
        bQ[ng] = (uint32_t)(8192 + rr * 64);
        bS[ng] = (rr >> 1) & 3;
    }
    const int hs = lane >> 4;

    const int NIT = K >> 5;

    auto FILL = [&](int s, int k0) {
        if (tid == 0) {
            uint32_t bar = sbase + s * 8;
            MBAR_EXPECT(bar, 16384);
            const __half* sa = A  + ((aBlkRow + (size_t)((koff + k0) >> 5)) << 12);
            const __half* sb = BT + ((bBlkRow + (size_t)((koff + k0) >> 5)) << 12);
            uint32_t st = stg0 + s * STG_B;
            BULK_G2S(st,        sa, 8192, bar);
            BULK_G2S(st + 8192, sb, 8192, bar);
        }
    };

    FILL(0, 0); FILL(1, 32); FILL(2, 64);

    for (int it = 0; it < NIT; ++it) {
        const int s = it & 3;
        MBAR_WAIT(sbase + s * 8, (it >> 2) & 1);

        const uint32_t st = stg0 + s * STG_B;
        #pragma unroll
        for (int ks = 0; ks < 2; ks++) {
            uint32_t af[2][4];
            #pragma unroll
            for (int mt = 0; mt < 2; mt++)
                LDSM4(af[mt][0], af[mt][1], af[mt][2], af[mt][3],
                      st + aQ[mt] + (uint32_t)((((ks << 1) | hs) ^ aS[mt]) << 4));
            uint32_t bq[4][4];
            #pragma unroll
            for (int ng = 0; ng < 4; ng++)
                LDSM4(bq[ng][0], bq[ng][1], bq[ng][2], bq[ng][3],
                      st + bQ[ng] + (uint32_t)((((ks << 1) | hs) ^ bS[ng]) << 4));
            #pragma unroll
            for (int mt = 0; mt < 2; mt++)
                #pragma unroll
                for (int nt = 0; nt < 8; nt++)
                    HMMA(acc[mt][nt], af[mt][0], af[mt][1], af[mt][2], af[mt][3],
                         bq[nt >> 1][nt & 1], bq[nt >> 1][(nt & 1) + 2]);
        }
        __syncthreads();
        if (it + 3 < NIT) FILL((it + 3) & 3, (it + 3) << 5);
    }

    // ---------------- epilogue ----------------
    float* Cf = (float*)Cv;
    __half* Ch = (__half*)Cv;
    if (EPI == 4) Cf += (size_t)blockIdx.z * M * N;

    #pragma unroll
    for (int mt = 0; mt < 2; mt++) {
        #pragma unroll
        for (int half = 0; half < 2; half++) {
            int m = bm + wm * 32 + mt * 16 + lr + half * 8;
            #pragma unroll
            for (int nt = 0; nt < 8; nt++) {
                int col = bn + wn * 64 + nt * 8 + lc * 2;
                float v0 = acc[mt][nt][half * 2 + 0];
                float v1 = acc[mt][nt][half * 2 + 1];
                if (EPI != 4) { v0 += bias[col]; v1 += bias[col + 1]; }
                if (EPI == 1) {
                    const float2 r2 = *(const float2*)(res + (size_t)m * N + col);
                    v0 += r2.x; v1 += r2.y;
                }
                if (EPI == 2) {
                    v0 = 0.5f * v0 * (1.0f + erff(v0 * 0.70710678118654752f));
                    v1 = 0.5f * v1 * (1.0f + erff(v1 * 0.70710678118654752f));
                }
                if (EPI == 0 || EPI == 2) {
                    __half2 hv;
                    hv.x = __float2half_rn(v0); hv.y = __float2half_rn(v1);
                    *(__half2*)(Ch + tidx(m, col, N)) = hv;
                } else {
                    *(float2*)(Cf + (size_t)m * N + col) = make_float2(v0, v1);
                }
            }
        }
    }
}

// ---------------- Attention: tensor-core (per bc,h block; 4 warps) ----------------
// smem: Q[64][64] @0, K @8192, V @16384 (half, 128B rows, chunk swz c^=(r&7))
#define ATTN_SMEM 24576
__global__ __launch_bounds__(128)
void attn_kernel() {
    int bh = blockIdx.x;
    int bc = bh >> 3, h = bh & 7;
    extern __shared__ __half smA[];
    const uint32_t sb = smem_u32(smA);
    const int tid = threadIdx.x, warp = tid >> 5, lane = tid & 31;
    const int kq = h * 64, kk0 = 512 + h * 64, kv0 = 1024 + h * 64;

    // load Q,K,V tiles (16B chunks; source chunks contiguous in tiled layout)
    #pragma unroll
    for (int j = 0; j < 4; j++) {
        int q = tid + j * 128;          // 0..511
        int r = q >> 3, c = q & 7;
        uint32_t doff = (uint32_t)(r * 128 + ((c ^ (r & 7)) << 4));
        int R = bc * 64 + r;
        *(uint4*)((char*)smA + doff)         = *(const uint4*)(g_qkv_h + tidx(R, kq  + c * 8, 1536));
        *(uint4*)((char*)smA + 8192 + doff)  = *(const uint4*)(g_qkv_h + tidx(R, kk0 + c * 8, 1536));
        *(uint4*)((char*)smA + 16384 + doff) = *(const uint4*)(g_qkv_h + tidx(R, kv0 + c * 8, 1536));
    }
    __syncthreads();

    const int rlo = lane & 15, hs = lane >> 4;

    // ---- S = Q K^T (warp handles rows warp*16..+15) ----
    float sacc[8][4];
    #pragma unroll
    for (int nt = 0; nt < 8; nt++)
        #pragma unroll
        for (int i = 0; i < 4; i++) sacc[nt][i] = 0.0f;

    #pragma unroll
    for (int ks = 0; ks < 4; ks++) {
        int cc = ks * 2 + hs;
        uint32_t a0, a1, a2, a3;
        {
            int r = warp * 16 + rlo;
            LDSM4(a0, a1, a2, a3, sb + (uint32_t)(r * 128 + ((cc ^ (r & 7)) << 4)));
        }
        #pragma unroll
        for (int ng = 0; ng < 4; ng++) {
            int r = ng * 16 + rlo;
            uint32_t b0, b1, b2, b3;
            LDSM4(b0, b1, b2, b3, sb + 8192 + (uint32_t)(r * 128 + ((cc ^ (r & 7)) << 4)));
            HMMA(sacc[2 * ng],     a0, a1, a2, a3, b0, b2);
            HMMA(sacc[2 * ng + 1], a0, a1, a2, a3, b1, b3);
        }
    }

    // ---- softmax (rows lr: idx 0,1; rows lr+8: idx 2,3), scale 0.125 ----
    float mx0 = -1e30f, mx1 = -1e30f;
    #pragma unroll
    for (int nt = 0; nt < 8; nt++) {
        #pragma unroll
        for (int i = 0; i < 4; i++) sacc[nt][i] *= 0.125f;
        mx0 = fmaxf(mx0, fmaxf(sacc[nt][0], sacc[nt][1]));
        mx1 = fmaxf(mx1, fmaxf(sacc[nt][2], sacc[nt][3]));
    }
    mx0 = fmaxf(mx0, __shfl_xor_sync(0xffffffffu, mx0, 1));
    mx0 = fmaxf(mx0, __shfl_xor_sync(0xffffffffu, mx0, 2));
    mx1 = fmaxf(mx1, __shfl_xor_sync(0xffffffffu, mx1, 1));
    mx1 = fmaxf(mx1, __shfl_xor_sync(0xffffffffu, mx1, 2));
    float s0 = 0.0f, s1 = 0.0f;
    #pragma unroll
    for (int nt = 0; nt < 8; nt++) {
        sacc[nt][0] = expf(sacc[nt][0] - mx0); s0 += sacc[nt][0];
        sacc[nt][1] = expf(sacc[nt][1] - mx0); s0 += sacc[nt][1];
        sacc[nt][2] = expf(sacc[nt][2] - mx1); s1 += sacc[nt][2];
        sacc[nt][3] = expf(sacc[nt][3] - mx1); s1 += sacc[nt][3];
    }
    s0 += __shfl_xor_sync(0xffffffffu, s0, 1);
    s0 += __shfl_xor_sync(0xffffffffu, s0, 2);
    s1 += __shfl_xor_sync(0xffffffffu, s1, 1);
    s1 += __shfl_xor_sync(0xffffffffu, s1, 2);
    float i0 = 1.0f / s0, i1 = 1.0f / s1;
    #pragma unroll
    for (int nt = 0; nt < 8; nt++) {
        sacc[nt][0] *= i0; sacc[nt][1] *= i0;
        sacc[nt][2] *= i1; sacc[nt][3] *= i1;
    }

    // ---- P half fragments: pa[ks] = A-frag for k-cols ks*16..+15 ----
    uint32_t pa[4][4];
    #pragma unroll
    for (int ks = 0; ks < 4; ks++) {
        pa[ks][0] = h2pack(sacc[2 * ks][0],     sacc[2 * ks][1]);
        pa[ks][1] = h2pack(sacc[2 * ks][2],     sacc[2 * ks][3]);
        pa[ks][2] = h2pack(sacc[2 * ks + 1][0], sacc[2 * ks + 1][1]);
        pa[ks][3] = h2pack(sacc[2 * ks + 1][2], sacc[2 * ks + 1][3]);
    }

    // ---- O = P V (V [s][e] row-major; ldmatrix.trans gives B-frags) ----
    float oacc[8][4];
    #pragma unroll
    for (int nt = 0; nt < 8; nt++)
        #pragma unroll
        for (int i = 0; i < 4; i++) oacc[nt][i] = 0.0f;

    #pragma unroll
    for (int ks = 0; ks < 4; ks++) {
        #pragma unroll
        for (int et = 0; et < 4; et++) {
            int r = ks * 16 + rlo;
            int cc = et * 2 + hs;
            uint32_t v0, v1, v2, v3;
            LDSM4T(v0, v1, v2, v3, sb + 16384 + (uint32_t)(r * 128 + ((cc ^ (r & 7)) << 4)));
            // trans regs: [b0_t0, b1_t0, b0_t1, b1_t1]
            HMMA(oacc[2 * et],     pa[ks][0], pa[ks][1], pa[ks][2], pa[ks][3], v0, v1);
            HMMA(oacc[2 * et + 1], pa[ks][0], pa[ks][1], pa[ks][2], pa[ks][3], v2, v3);
        }
    }

    // ---- store (tiled half) ----
    int r0w = bc * 64 + warp * 16 + (lane >> 2);
    #pragma unroll
    for (int nt = 0; nt < 8; nt++) {
        int col = h * 64 + nt * 8 + (lane & 3) * 2;
        *(__half2*)(g_attn_h + tidx(r0w,     col, D_)) = *(__half2*)&(uint32_t&)*(uint32_t[]){h2pack(oacc[nt][0], oacc[nt][1])};
        *(__half2*)(g_attn_h + tidx(r0w + 8, col, D_)) = *(__half2*)&(uint32_t&)*(uint32_t[]){h2pack(oacc[nt][2], oacc[nt][3])};
    }
}

// ---------------- LayerNorm (row of 512), shuffle reduction ----------------
__global__ void ln_kernel(const float* __restrict__ X,
                          const float* __restrict__ g, const float* __restrict__ b,
                          float* __restrict__ Yf, __half* __restrict__ Yh) {
    int row = blockIdx.x;
    int tid = threadIdx.x;  // 256
    int lane = tid & 31, warp = tid >> 5;
    const float* x = X + (size_t)row * D_;
    float v0 = x[tid], v1 = x[tid + 256];
    float s = v0 + v1, q = v0 * v0 + v1 * v1;
    #pragma unroll
    for (int o = 16; o > 0; o >>= 1) {
        s += __shfl_xor_sync(0xffffffffu, s, o);
        q += __shfl_xor_sync(0xffffffffu, q, o);
    }
    __shared__ float ws[8], wq[8];
    __shared__ float s_mean, s_inv;
    if (lane == 0) { ws[warp] = s; wq[warp] = q; }
    __syncthreads();
    if (tid == 0) {
        float S = 0.0f, Q = 0.0f;
        #pragma unroll
        for (int i = 0; i < 8; i++) { S += ws[i]; Q += wq[i]; }
        float mean = S / (float)D_;
        float var  = Q / (float)D_ - mean * mean;
        s_mean = mean;
        s_inv  = rsqrtf(var + 1e-5f);
    }
    __syncthreads();
    float mean = s_mean, inv = s_inv;
    float o0 = (v0 - mean) * inv * g[tid]       + b[tid];
    float o1 = (v1 - mean) * inv * g[tid + 256] + b[tid + 256];
    if (Yf) {
        Yf[(size_t)row * D_ + tid]       = o0;
        Yf[(size_t)row * D_ + tid + 256] = o1;
    }
    if (Yh) {
        Yh[tidx(row, tid, D_)]       = __float2half_rn(o0);
        Yh[tidx(row, tid + 256, D_)] = __float2half_rn(o1);
    }
}

// ---------------- BatchNorm stats (deterministic 2-stage) ----------------
__global__ void bn_partial_kernel() {
    int blk = blockIdx.x;
    int d = threadIdx.x;      // 512
    float s = 0.0f, q = 0.0f;
    const float* base = g_tok + (size_t)blk * 256 * D_ + d;
    for (int r = 0; r < 256; r++) {
        float v = base[(size_t)r * D_];
        s += v; q += v * v;
    }
    g_psum[blk * D_ + d] = s;
    g_psq [blk * D_ + d] = q;
}

__global__ void bn_final_kernel(const float* __restrict__ gam,
                                const float* __restrict__ bet) {
    int d = threadIdx.x;      // 512, one block
    float s = 0.0f, q = 0.0f;
    for (int i = 0; i < 256; i++) {
        s += g_psum[i * D_ + d];
        q += g_psq [i * D_ + d];
    }
    float mean = s / (float)ROWS_;
    float var  = q / (float)ROWS_ - mean * mean;
    float a = gam[d] * rsqrtf(var + 1e-5f);
    g_bna[d] = a;
    g_bnb[d] = bet[d] - mean * a;
}

// ---------------- BN apply + (N,D)->(D,N) transpose into enc (tiled half) ----------------
__global__ void enc_transpose_kernel() {
    __shared__ float sm[32][33];
    int bid = blockIdx.x;
    int bc = bid >> 5;
    int r = bid & 31;
    int dt = r >> 1, nt = r & 1;
    int tx = threadIdx.x, ty = threadIdx.y;   // 32 x 8
    int d0 = dt * 32, n0 = nt * 32;
    #pragma unroll
    for (int j = 0; j < 32; j += 8) {
        int n = n0 + ty + j;
        int d = d0 + tx;
        float v = g_tok[((size_t)bc * 64 + n) * D_ + d];
        sm[ty + j][tx] = v * g_bna[d] + g_bnb[d];
    }
    __syncthreads();
    #pragma unroll
    for (int j = 0; j < 32; j += 8) {
        int d = d0 + ty + j;
        int n = n0 + tx;
        g_enc_h[tidx(bc, d * N_ + n, KHEAD_)] = __float2half_rn(sm[tx][ty + j]);
    }
}

// ---------------- head final: sum split-K partials + bias + denorm ----------------
__global__ void head_final_kernel(const float* __restrict__ b_head,
                                  float* __restrict__ out) {
    int m = blockIdx.x;        // bc
    int t = threadIdx.x;       // 512
    float v = b_head[t];
    #pragma unroll
    for (int z = 0; z < KSPLIT_; z++)
        v += g_hpart[((size_t)z * BC_ + m) * T_ + t];
    int b = m >> 5, c = m & 31;
    out[((size_t)b * T_ + t) * C_ + c] = v * g_std[m] + g_mean[m];
}

// ---------------- Launch ----------------
extern "C" void kernel_launch(void* const* d_in, const int* in_sizes, int n_in,
                              void* d_out, int out_size) {
    const float* x_enc = (const float*)d_in[0];
    const float* W_val = (const float*)d_in[1];
    const float* Wq    = (const float*)d_in[2];
    const float* bq    = (const float*)d_in[3];
    const float* Wk    = (const float*)d_in[4];
    const float* bk    = (const float*)d_in[5];
    const float* Wv    = (const float*)d_in[6];
    const float* bv    = (const float*)d_in[7];
    const float* Wo    = (const float*)d_in[8];
    const float* bo    = (const float*)d_in[9];
    const float* Wc1   = (const float*)d_in[10];
    const float* bc1   = (const float*)d_in[11];
    const float* Wc2   = (const float*)d_in[12];
    const float* bc2   = (const float*)d_in[13];
    const float* ln1_g = (const float*)d_in[14];
    const float* ln1_b = (const float*)d_in[15];
    const float* ln2_g = (const float*)d_in[16];
    const float* ln2_b = (const float*)d_in[17];
    const float* bn_g  = (const float*)d_in[18];
    const float* bn_b  = (const float*)d_in[19];
    const float* W_head= (const float*)d_in[20];
    const float* b_head= (const float*)d_in[21];
    float* out = (float*)d_out;

    float *tok, *hpart, *bqkv;
    __half *tok_h, *qkv_h, *attn_h, *y_h, *h_h, *enc_h;
    __half *wqkvT, *woT, *wc1T, *wc2T, *whT;
    cudaGetSymbolAddress((void**)&tok,    g_tok);
    cudaGetSymbolAddress((void**)&tok_h,  g_tok_h);
    cudaGetSymbolAddress((void**)&qkv_h,  g_qkv_h);
    cudaGetSymbolAddress((void**)&attn_h, g_attn_h);
    cudaGetSymbolAddress((void**)&y_h,    g_y_h);
    cudaGetSymbolAddress((void**)&h_h,    g_h_h);
    cudaGetSymbolAddress((void**)&enc_h,  g_enc_h);
    cudaGetSymbolAddress((void**)&hpart,  g_hpart);
    cudaGetSymbolAddress((void**)&bqkv,   g_bqkv);
    cudaGetSymbolAddress((void**)&wqkvT,  g_wqkvT);
    cudaGetSymbolAddress((void**)&woT,    g_woT);
    cudaGetSymbolAddress((void**)&wc1T,   g_wc1T);
    cudaGetSymbolAddress((void**)&wc2T,   g_wc2T);
    cudaGetSymbolAddress((void**)&whT,    g_whT);

    cudaFuncSetAttribute(attn_kernel, cudaFuncAttributeMaxDynamicSharedMemorySize, ATTN_SMEM);
    cudaFuncSetAttribute(hgemm_kernel<0>, cudaFuncAttributeMaxDynamicSharedMemorySize, HG_SMEM);
    cudaFuncSetAttribute(hgemm_kernel<1>, cudaFuncAttributeMaxDynamicSharedMemorySize, HG_SMEM);
    cudaFuncSetAttribute(hgemm_kernel<2>, cudaFuncAttributeMaxDynamicSharedMemorySize, HG_SMEM);
    cudaFuncSetAttribute(hgemm_kernel<4>, cudaFuncAttributeMaxDynamicSharedMemorySize, HG_SMEM);

    dim3 tb32(32, 8);
    dim3 gqkv(1536 / 128, ROWS_ / 128);       // (12, 512)
    dim3 gproj(D_ / 128, ROWS_ / 128);        // (4, 512)
    dim3 gff1(DFF_ / 128, ROWS_ / 128);       // (16, 512)
    dim3 ghead(T_ / 128, BC_ / 128, KSPLIT_); // (4, 8, 8)

    inst_stats_kernel<<<BC_, 256>>>(x_enc);
    patch_embed_kernel<<<ROWS_, 512>>>(x_enc, W_val);
    bqkv_kernel<<<NL_, 512>>>(bq, bk, bv);
    qkvtrans_kernel<<<dim3(16, 16, 3), tb32>>>(Wq, Wk, Wv, wqkvT);
    whtrans_kernel<<<dim3(16, 16), tb32>>>(Wo, woT, D_, D_);

    for (int i = 0; i < NL_; i++) {
        if (i > 0) {
            qkvtrans_kernel<<<dim3(16, 16, 3), tb32>>>(Wq + (size_t)i * D_ * D_,
                Wk + (size_t)i * D_ * D_, Wv + (size_t)i * D_ * D_,
                wqkvT + (size_t)i * 1536 * D_);
            whtrans_kernel<<<dim3(16, 16), tb32>>>(Wo + (size_t)i * D_ * D_,
                woT + (size_t)i * D_ * D_, D_, D_);
        }
        hgemm_kernel<0><<<gqkv, 256, HG_SMEM>>>(tok_h, wqkvT + (size_t)i * 1536 * D_,
            bqkv + i * 1536, nullptr, qkv_h, ROWS_, 1536, D_, D_, D_);
        whtrans_kernel<<<dim3(64, 16), tb32>>>(Wc1 + (size_t)i * D_ * DFF_,
            wc1T + (size_t)i * DFF_ * D_, D_, DFF_);
        whtrans_kernel<<<dim3(16, 64), tb32>>>(Wc2 + (size_t)i * DFF_ * D_,
            wc2T + (size_t)i * D_ * DFF_, DFF_, D_);
        attn_kernel<<<BC_ * H_, 128, ATTN_SMEM>>>();
        hgemm_kernel<1><<<gproj, 256, HG_SMEM>>>(attn_h, woT + (size_t)i * D_ * D_,
            bo + i * D_, tok, tok, ROWS_, D_, D_, D_, D_);
        ln_kernel<<<ROWS_, 256>>>(tok, ln1_g + i * D_, ln1_b + i * D_, nullptr, y_h);
        hgemm_kernel<2><<<gff1, 256, HG_SMEM>>>(y_h, wc1T + (size_t)i * DFF_ * D_,
            bc1 + i * DFF_, nullptr, h_h, ROWS_, DFF_, D_, D_, D_);
        hgemm_kernel<1><<<gproj, 256, HG_SMEM>>>(h_h, wc2T + (size_t)i * D_ * DFF_,
            bc2 + i * D_, tok, tok, ROWS_, D_, DFF_, DFF_, DFF_);
        ln_kernel<<<ROWS_, 256>>>(tok, ln2_g + i * D_, ln2_b + i * D_, tok, tok_h);
    }

    whtrans_kernel<<<dim3(16, 1024), tb32>>>(W_head, whT, KHEAD_, T_);
    bn_partial_kernel<<<256, 512>>>();
    bn_final_kernel<<<1, 512>>>(bn_g, bn_b);
    enc_transpose_kernel<<<BC_ * 32, dim3(32, 8)>>>();
    hgemm_kernel<4><<<ghead, 256, HG_SMEM>>>(enc_h, whT, nullptr, nullptr, hpart,
                                             BC_, T_, KCH_, KHEAD_, KHEAD_);
    head_final_kernel<<<BC_, T_>>>(b_head, out);
}

// round 10
// speedup vs baseline: 2.2327x; 1.1129x over previous
#include <cuda_runtime.h>
#include <cuda_fp16.h>
#include <math.h>
#include <stdint.h>

// ---------------- Problem constants ----------------
#define B_    32
#define T_    512
#define C_    32
#define D_    512
#define H_    8
#define E_    64
#define DFF_  2048
#define NL_   3
#define P_    16
#define N_    64
#define BC_   (B_*C_)          // 1024
#define ROWS_ ((BC_)*(N_))     // 65536
#define KSPLIT_ 8
#define KCH_    4096           // 32768 / 8
#define KHEAD_  (D_*N_)        // 32768

// ---------------- Scratch (device globals; no allocation) ----------------
__device__ float  g_mean[BC_];
__device__ float  g_std[BC_];
__device__ float  g_pe  [N_ * D_];
__device__ float  g_tok  [ROWS_ * D_];                      // fp32 residual stream
__device__ __align__(256) __half g_tok_h[ROWS_ * D_];       // tiled half (QKV input)
__device__ __align__(256) __half g_qkv_h[ROWS_ * 1536];     // tiled QKV output
__device__ __align__(256) __half g_attn_h[ROWS_ * D_];      // tiled attn output
__device__ __align__(256) __half g_y_h  [ROWS_ * D_];       // tiled ln1 output
__device__ __align__(256) __half g_h_h  [ROWS_ * DFF_];     // tiled gelu output
__device__ __align__(256) __half g_enc_h[BC_ * KHEAD_];     // tiled head input
__device__ float  g_hpart[KSPLIT_ * BC_ * T_];
__device__ float  g_psum [256 * D_];
__device__ float  g_psq  [256 * D_];
__device__ float  g_bna  [D_];
__device__ float  g_bnb  [D_];
__device__ float  g_bqkv [NL_ * 1536];
// transposed half weights ([N,K] K-major, tiled layout)
__device__ __align__(256) __half g_wqkvT[NL_ * 1536 * D_];
__device__ __align__(256) __half g_woT  [NL_ * D_ * D_];
__device__ __align__(256) __half g_wc1T [NL_ * DFF_ * D_];
__device__ __align__(256) __half g_wc2T [NL_ * D_ * DFF_];
__device__ __align__(256) __half g_whT  [T_ * KHEAD_];

// ---------------- tiled-swizzled layout ----------------
// Matrix [R, K] half, stored as 128x32 blocks (8KB each), block-row-major.
// Within block: row rr, 16B-chunk c stored at chunk c' = c ^ ((rr>>1)&3).
__device__ __forceinline__ size_t tidx(int r, int k, int K) {
    int rr = r & 127;
    int kk = k & 31;
    int c  = ((kk >> 3) ^ ((rr >> 1) & 3));
    return (((size_t)(r >> 7) * (size_t)(K >> 5) + (size_t)(k >> 5)) << 12)
         + (size_t)(rr * 32 + c * 8 + (kk & 7));
}

// ---------------- helpers ----------------
#define LDSM4(r0, r1, r2, r3, addr) \
    asm volatile("ldmatrix.sync.aligned.m8n8.x4.shared.b16 {%0,%1,%2,%3}, [%4];" \
        : "=r"(r0), "=r"(r1), "=r"(r2), "=r"(r3) : "r"(addr))
#define LDSM4T(r0, r1, r2, r3, addr) \
    asm volatile("ldmatrix.sync.aligned.m8n8.x4.trans.shared.b16 {%0,%1,%2,%3}, [%4];" \
        : "=r"(r0), "=r"(r1), "=r"(r2), "=r"(r3) : "r"(addr))
#define HMMA(acc, a0, a1, a2, a3, b0, b1) \
    asm volatile("mma.sync.aligned.m16n8k16.row.col.f32.f16.f16.f32 " \
        "{%0,%1,%2,%3},{%4,%5,%6,%7},{%8,%9},{%0,%1,%2,%3};" \
        : "+f"((acc)[0]), "+f"((acc)[1]), "+f"((acc)[2]), "+f"((acc)[3]) \
        : "r"(a0), "r"(a1), "r"(a2), "r"(a3), "r"(b0), "r"(b1))

#define MBAR_INIT(addr, cnt) \
    asm volatile("mbarrier.init.shared.b64 [%0], %1;" :: "r"(addr), "r"(cnt) : "memory")
#define MBAR_EXPECT(addr, bytes) \
    asm volatile("mbarrier.arrive.expect_tx.shared.b64 _, [%0], %1;" :: "r"(addr), "r"(bytes) : "memory")
#define BULK_G2S(dst, src, bytes, bar) \
    asm volatile("cp.async.bulk.shared::cta.global.mbarrier::complete_tx::bytes [%0], [%1], %2, [%3];" \
        :: "r"(dst), "l"(src), "r"(bytes), "r"(bar) : "memory")
#define MBAR_WAIT(addr, par) do { \
    uint32_t _m = (addr), _p = (par), _d; \
    asm volatile("{\n\t.reg .pred p;\n\t" \
        "mbarrier.try_wait.parity.acquire.cta.shared::cta.b64 p, [%1], %2;\n\t" \
        "selp.b32 %0, 1, 0, p;\n\t}" : "=r"(_d) : "r"(_m), "r"(_p) : "memory"); \
    if (!_d) { \
        asm volatile("{\n\t.reg .pred P1;\n\t" \
            "WL_%=:\n\t" \
            "mbarrier.try_wait.parity.acquire.cta.shared::cta.b64 P1, [%0], %1, 0x989680;\n\t" \
            "@P1 bra.uni WD_%=;\n\t" \
            "bra.uni WL_%=;\n\t" \
            "WD_%=:\n\t}" :: "r"(_m), "r"(_p) : "memory"); \
    } \
} while (0)

__device__ __forceinline__ uint32_t smem_u32(const void* p) {
    uint32_t a;
    asm("{ .reg .u64 t; cvta.to.shared.u64 t, %1; cvt.u32.u64 %0, t; }" : "=r"(a) : "l"(p));
    return a;
}
__device__ __forceinline__ uint32_t h2pack(float x, float y) {
    __half2 h; h.x = __float2half_rn(x); h.y = __float2half_rn(y);
    return *(uint32_t*)&h;
}

// ---------------- Weight transpose -> half (tiled output) ----------------
__global__ void whtrans_kernel(const float* __restrict__ W, __half* __restrict__ WT,
                               int K, int Ncols) {
    __shared__ float s[32][33];
    int n0 = blockIdx.x * 32, k0 = blockIdx.y * 32;
    int tx = threadIdx.x, ty = threadIdx.y;   // 32 x 8
    #pragma unroll
    for (int j = 0; j < 32; j += 8)
        s[ty + j][tx] = W[(size_t)(k0 + ty + j) * Ncols + n0 + tx];
    __syncthreads();
    #pragma unroll
    for (int j = 0; j < 32; j += 8)
        WT[tidx(n0 + ty + j, k0 + tx, K)] = __float2half_rn(s[tx][ty + j]);
}

// fused QKV weight transpose for one layer: z in {0,1,2} selects q/k/v
__global__ void qkvtrans_kernel(const float* __restrict__ Wq, const float* __restrict__ Wk,
                                const float* __restrict__ Wv, __half* __restrict__ WT) {
    __shared__ float s[32][33];
    int z = blockIdx.z;
    const float* W = (z == 0) ? Wq : (z == 1) ? Wk : Wv;
    int n0 = blockIdx.x * 32, k0 = blockIdx.y * 32;
    int tx = threadIdx.x, ty = threadIdx.y;   // 32 x 8
    #pragma unroll
    for (int j = 0; j < 32; j += 8)
        s[ty + j][tx] = W[(size_t)(k0 + ty + j) * D_ + n0 + tx];
    __syncthreads();
    #pragma unroll
    for (int j = 0; j < 32; j += 8)
        WT[tidx(z * 512 + n0 + ty + j, k0 + tx, D_)] = __float2half_rn(s[tx][ty + j]);
}

__global__ void bqkv_kernel(const float* __restrict__ bq, const float* __restrict__ bk,
                            const float* __restrict__ bv) {
    int i = blockIdx.x, t = threadIdx.x;   // NL_ x 512
    g_bqkv[i * 1536 + t]        = bq[i * D_ + t];
    g_bqkv[i * 1536 + 512 + t]  = bk[i * D_ + t];
    g_bqkv[i * 1536 + 1024 + t] = bv[i * D_ + t];
}

// ---------------- PE table ----------------
__global__ void pe_kernel() {
    int n = blockIdx.x, d = threadIdx.x;   // 64 x 512
    int i2 = d >> 1;
    float div = expf(-(float)(2 * i2) * (logf(10000.0f) / (float)D_));
    float ang = (float)n * div;
    g_pe[n * D_ + d] = (d & 1) ? cosf(ang) : sinf(ang);
}

// ---------------- Instance-norm stats over time ----------------
__global__ void inst_stats_kernel(const float* __restrict__ x_enc) {
    int bc = blockIdx.x;
    int b = bc >> 5, c = bc & 31;
    int tid = threadIdx.x;          // 256
    const float* p = x_enc + (size_t)b * T_ * C_ + c;
    float v0 = p[(size_t)tid * C_];
    float v1 = p[(size_t)(tid + 256) * C_];
    __shared__ float rs[256], rq[256];
    rs[tid] = v0 + v1; rq[tid] = v0 * v0 + v1 * v1;
    __syncthreads();
    for (int off = 128; off > 0; off >>= 1) {
        if (tid < off) { rs[tid] += rs[tid + off]; rq[tid] += rq[tid + off]; }
        __syncthreads();
    }
    if (tid == 0) {
        float mean = rs[0] / (float)T_;
        float var  = rq[0] / (float)T_ - mean * mean;
        g_mean[bc] = mean;
        g_std[bc]  = sqrtf(var + 1e-5f);
    }
}

// ---------------- Patch embedding (+PE table) ----------------
__global__ void patch_embed_kernel(const float* __restrict__ x_enc,
                                   const float* __restrict__ W_val) {
    int bn = blockIdx.x;            // global token row
    int bc = bn >> 6, n = bn & 63;
    int b = bc >> 5, c = bc & 31;
    int d = threadIdx.x;            // 512
    __shared__ float pv[P_];
    if (d < P_) {
        int t = n * 8 + d;
        if (t > T_ - 1) t = T_ - 1;
        pv[d] = (x_enc[(size_t)(b * T_ + t) * C_ + c] - g_mean[bc]) / g_std[bc];
    }
    __syncthreads();
    float acc = g_pe[n * D_ + d];
    #pragma unroll
    for (int p = 0; p < P_; p++)
        acc = fmaf(pv[p], W_val[p * D_ + d], acc);
    g_tok  [(size_t)bn * D_ + d] = acc;
    g_tok_h[tidx(bn, d, D_)]     = __float2half_rn(acc);
}

// ---------------- FP16 mma GEMM: TMA-bulk staged, 128x128x64 tiles ----------------
#define NSTG   3
#define STG_B  32768
#define HG_SMEM (64 + NSTG * STG_B)     // 98368 bytes

template<int EPI>
__global__ __launch_bounds__(256, 2)
void hgemm_kernel(const __half* __restrict__ A, const __half* __restrict__ BT,
                  const float* __restrict__ bias, const float* __restrict__ res,
                  void* __restrict__ Cv, int M, int N, int K, int lda, int ldb) {
    extern __shared__ __half smh[];
    const uint32_t sbase = smem_u32(smh);
    const uint32_t stg0  = sbase + 64;

    int koff = 0;
    if (EPI == 4) koff = blockIdx.z * KCH_;

    const int tid  = threadIdx.x;
    const int warp = tid >> 5, lane = tid & 31;
    const int wm = warp >> 1, wn = warp & 1;       // 4x2 warps, 32x64 warp tile
    const int lr = lane >> 2, lc = lane & 3;
    const int bm = blockIdx.y * 128, bn = blockIdx.x * 128;
    const size_t aBlkRow = (size_t)(bm >> 7) * (size_t)(lda >> 5);
    const size_t bBlkRow = (size_t)(bn >> 7) * (size_t)(ldb >> 5);

    if (tid < NSTG) MBAR_INIT(sbase + tid * 8, 1);
    __syncthreads();

    float acc[2][8][4];
    #pragma unroll
    for (int mt = 0; mt < 2; mt++)
        #pragma unroll
        for (int nt = 0; nt < 8; nt++)
            #pragma unroll
            for (int i = 0; i < 4; i++) acc[mt][nt][i] = 0.0f;

    uint32_t aQ[2]; int aS[2];
    #pragma unroll
    for (int mt = 0; mt < 2; mt++) {
        int rr = wm * 32 + mt * 16 + (lane & 15);
        aQ[mt] = (uint32_t)(rr * 64);
        aS[mt] = (rr >> 1) & 3;
    }
    uint32_t bQ[4]; int bS[4];
    #pragma unroll
    for (int ng = 0; ng < 4; ng++) {
        int rr = wn * 64 + ng * 16 + (lane & 15);
        bQ[ng] = (uint32_t)(16384 + rr * 64);
        bS[ng] = (rr >> 1) & 3;
    }
    const int hs = lane >> 4;

    const int NIT = K >> 6;      // 64-K chunks

    auto FILL = [&](int s, int k0) {
        if (tid == 0) {
            uint32_t bar = sbase + s * 8;
            MBAR_EXPECT(bar, 32768);
            const __half* sa = A  + ((aBlkRow + (size_t)((koff + k0) >> 5)) << 12);
            const __half* sb = BT + ((bBlkRow + (size_t)((koff + k0) >> 5)) << 12);
            uint32_t st = stg0 + s * STG_B;
            BULK_G2S(st,         sa, 16384, bar);   // 2 consecutive A k-blocks
            BULK_G2S(st + 16384, sb, 16384, bar);   // 2 consecutive B k-blocks
        }
    };

    FILL(0, 0); FILL(1, 64);

    for (int it = 0; it < NIT; ++it) {
        const int s = it % 3;
        MBAR_WAIT(sbase + s * 8, (it / 3) & 1);

        const uint32_t st = stg0 + s * STG_B;
        #pragma unroll
        for (int ks = 0; ks < 4; ks++) {
            const uint32_t kblk = st + (uint32_t)((ks >> 1) * 8192);
            const int ksl = ks & 1;
            uint32_t af[2][4];
            #pragma unroll
            for (int mt = 0; mt < 2; mt++)
                LDSM4(af[mt][0], af[mt][1], af[mt][2], af[mt][3],
                      kblk + aQ[mt] + (uint32_t)((((ksl << 1) | hs) ^ aS[mt]) << 4));
            uint32_t bq[4][4];
            #pragma unroll
            for (int ng = 0; ng < 4; ng++)
                LDSM4(bq[ng][0], bq[ng][1], bq[ng][2], bq[ng][3],
                      kblk + bQ[ng] + (uint32_t)((((ksl << 1) | hs) ^ bS[ng]) << 4));
            #pragma unroll
            for (int mt = 0; mt < 2; mt++)
                #pragma unroll
                for (int nt = 0; nt < 8; nt++)
                    HMMA(acc[mt][nt], af[mt][0], af[mt][1], af[mt][2], af[mt][3],
                         bq[nt >> 1][nt & 1], bq[nt >> 1][(nt & 1) + 2]);
        }
        __syncthreads();
        if (it + 2 < NIT) FILL((it + 2) % 3, (it + 2) << 6);
    }

    // ---------------- epilogue ----------------
    float* Cf = (float*)Cv;
    __half* Ch = (__half*)Cv;
    if (EPI == 4) Cf += (size_t)blockIdx.z * M * N;

    #pragma unroll
    for (int mt = 0; mt < 2; mt++) {
        #pragma unroll
        for (int half = 0; half < 2; half++) {
            int m = bm + wm * 32 + mt * 16 + lr + half * 8;
            #pragma unroll
            for (int nt = 0; nt < 8; nt++) {
                int col = bn + wn * 64 + nt * 8 + lc * 2;
                float v0 = acc[mt][nt][half * 2 + 0];
                float v1 = acc[mt][nt][half * 2 + 1];
                if (EPI != 4) { v0 += bias[col]; v1 += bias[col + 1]; }
                if (EPI == 1) {
                    const float2 r2 = *(const float2*)(res + (size_t)m * N + col);
                    v0 += r2.x; v1 += r2.y;
                }
                if (EPI == 2) {
                    v0 = 0.5f * v0 * (1.0f + erff(v0 * 0.70710678118654752f));
                    v1 = 0.5f * v1 * (1.0f + erff(v1 * 0.70710678118654752f));
                }
                if (EPI == 0 || EPI == 2) {
                    __half2 hv;
                    hv.x = __float2half_rn(v0); hv.y = __float2half_rn(v1);
                    *(__half2*)(Ch + tidx(m, col, N)) = hv;
                } else {
                    *(float2*)(Cf + (size_t)m * N + col) = make_float2(v0, v1);
                }
            }
        }
    }
}

// ---------------- Attention: tensor-core (per bc,h block; 4 warps) ----------------
#define ATTN_SMEM 24576
__global__ __launch_bounds__(128)
void attn_kernel() {
    int bh = blockIdx.x;
    int bc = bh >> 3, h = bh & 7;
    extern __shared__ __half smA[];
    const uint32_t sb = smem_u32(smA);
    const int tid = threadIdx.x, warp = tid >> 5, lane = tid & 31;
    const int kq = h * 64, kk0 = 512 + h * 64, kv0 = 1024 + h * 64;

    #pragma unroll
    for (int j = 0; j < 4; j++) {
        int q = tid + j * 128;          // 0..511
        int r = q >> 3, c = q & 7;
        uint32_t doff = (uint32_t)(r * 128 + ((c ^ (r & 7)) << 4));
        int R = bc * 64 + r;
        *(uint4*)((char*)smA + doff)         = *(const uint4*)(g_qkv_h + tidx(R, kq  + c * 8, 1536));
        *(uint4*)((char*)smA + 8192 + doff)  = *(const uint4*)(g_qkv_h + tidx(R, kk0 + c * 8, 1536));
        *(uint4*)((char*)smA + 16384 + doff) = *(const uint4*)(g_qkv_h + tidx(R, kv0 + c * 8, 1536));
    }
    __syncthreads();

    const int rlo = lane & 15, hs = lane >> 4;

    float sacc[8][4];
    #pragma unroll
    for (int nt = 0; nt < 8; nt++)
        #pragma unroll
        for (int i = 0; i < 4; i++) sacc[nt][i] = 0.0f;

    #pragma unroll
    for (int ks = 0; ks < 4; ks++) {
        int cc = ks * 2 + hs;
        uint32_t a0, a1, a2, a3;
        {
            int r = warp * 16 + rlo;
            LDSM4(a0, a1, a2, a3, sb + (uint32_t)(r * 128 + ((cc ^ (r & 7)) << 4)));
        }
        #pragma unroll
        for (int ng = 0; ng < 4; ng++) {
            int r = ng * 16 + rlo;
            uint32_t b0, b1, b2, b3;
            LDSM4(b0, b1, b2, b3, sb + 8192 + (uint32_t)(r * 128 + ((cc ^ (r & 7)) << 4)));
            HMMA(sacc[2 * ng],     a0, a1, a2, a3, b0, b2);
            HMMA(sacc[2 * ng + 1], a0, a1, a2, a3, b1, b3);
        }
    }

    float mx0 = -1e30f, mx1 = -1e30f;
    #pragma unroll
    for (int nt = 0; nt < 8; nt++) {
        #pragma unroll
        for (int i = 0; i < 4; i++) sacc[nt][i] *= 0.125f;
        mx0 = fmaxf(mx0, fmaxf(sacc[nt][0], sacc[nt][1]));
        mx1 = fmaxf(mx1, fmaxf(sacc[nt][2], sacc[nt][3]));
    }
    mx0 = fmaxf(mx0, __shfl_xor_sync(0xffffffffu, mx0, 1));
    mx0 = fmaxf(mx0, __shfl_xor_sync(0xffffffffu, mx0, 2));
    mx1 = fmaxf(mx1, __shfl_xor_sync(0xffffffffu, mx1, 1));
    mx1 = fmaxf(mx1, __shfl_xor_sync(0xffffffffu, mx1, 2));
    float s0 = 0.0f, s1 = 0.0f;
    #pragma unroll
    for (int nt = 0; nt < 8; nt++) {
        sacc[nt][0] = expf(sacc[nt][0] - mx0); s0 += sacc[nt][0];
        sacc[nt][1] = expf(sacc[nt][1] - mx0); s0 += sacc[nt][1];
        sacc[nt][2] = expf(sacc[nt][2] - mx1); s1 += sacc[nt][2];
        sacc[nt][3] = expf(sacc[nt][3] - mx1); s1 += sacc[nt][3];
    }
    s0 += __shfl_xor_sync(0xffffffffu, s0, 1);
    s0 += __shfl_xor_sync(0xffffffffu, s0, 2);
    s1 += __shfl_xor_sync(0xffffffffu, s1, 1);
    s1 += __shfl_xor_sync(0xffffffffu, s1, 2);
    float i0 = 1.0f / s0, i1 = 1.0f / s1;
    #pragma unroll
    for (int nt = 0; nt < 8; nt++) {
        sacc[nt][0] *= i0; sacc[nt][1] *= i0;
        sacc[nt][2] *= i1; sacc[nt][3] *= i1;
    }

    uint32_t pa[4][4];
    #pragma unroll
    for (int ks = 0; ks < 4; ks++) {
        pa[ks][0] = h2pack(sacc[2 * ks][0],     sacc[2 * ks][1]);
        pa[ks][1] = h2pack(sacc[2 * ks][2],     sacc[2 * ks][3]);
        pa[ks][2] = h2pack(sacc[2 * ks + 1][0], sacc[2 * ks + 1][1]);
        pa[ks][3] = h2pack(sacc[2 * ks + 1][2], sacc[2 * ks + 1][3]);
    }

    float oacc[8][4];
    #pragma unroll
    for (int nt = 0; nt < 8; nt++)
        #pragma unroll
        for (int i = 0; i < 4; i++) oacc[nt][i] = 0.0f;

    #pragma unroll
    for (int ks = 0; ks < 4; ks++) {
        #pragma unroll
        for (int et = 0; et < 4; et++) {
            int r = ks * 16 + rlo;
            int cc = et * 2 + hs;
            uint32_t v0, v1, v2, v3;
            LDSM4T(v0, v1, v2, v3, sb + 16384 + (uint32_t)(r * 128 + ((cc ^ (r & 7)) << 4)));
            HMMA(oacc[2 * et],     pa[ks][0], pa[ks][1], pa[ks][2], pa[ks][3], v0, v1);
            HMMA(oacc[2 * et + 1], pa[ks][0], pa[ks][1], pa[ks][2], pa[ks][3], v2, v3);
        }
    }

    int r0w = bc * 64 + warp * 16 + (lane >> 2);
    #pragma unroll
    for (int nt = 0; nt < 8; nt++) {
        int col = h * 64 + nt * 8 + (lane & 3) * 2;
        uint32_t p0 = h2pack(oacc[nt][0], oacc[nt][1]);
        uint32_t p1 = h2pack(oacc[nt][2], oacc[nt][3]);
        *(uint32_t*)(g_attn_h + tidx(r0w,     col, D_)) = p0;
        *(uint32_t*)(g_attn_h + tidx(r0w + 8, col, D_)) = p1;
    }
}

// ---------------- LayerNorm: warp-per-row (8 rows/block) ----------------
__global__ void ln_kernel(const float* __restrict__ X,
                          const float* __restrict__ g, const float* __restrict__ b,
                          float* __restrict__ Yf, __half* __restrict__ Yh) {
    int warp = threadIdx.x >> 5, lane = threadIdx.x & 31;
    int row = blockIdx.x * 8 + warp;
    const float* x = X + (size_t)row * D_;
    float v[16];
    float s = 0.0f, q = 0.0f;
    #pragma unroll
    for (int j = 0; j < 4; j++) {
        float4 f = *(const float4*)(x + lane * 4 + j * 128);
        v[j * 4 + 0] = f.x; v[j * 4 + 1] = f.y; v[j * 4 + 2] = f.z; v[j * 4 + 3] = f.w;
        s += f.x + f.y + f.z + f.w;
        q += f.x * f.x + f.y * f.y + f.z * f.z + f.w * f.w;
    }
    #pragma unroll
    for (int o = 16; o > 0; o >>= 1) {
        s += __shfl_xor_sync(0xffffffffu, s, o);
        q += __shfl_xor_sync(0xffffffffu, q, o);
    }
    float mean = s / (float)D_;
    float inv  = rsqrtf(q / (float)D_ - mean * mean + 1e-5f);
    #pragma unroll
    for (int j = 0; j < 4; j++) {
        int c = lane * 4 + j * 128;
        float4 gg = *(const float4*)(g + c);
        float4 bb = *(const float4*)(b + c);
        float o0 = (v[j * 4 + 0] - mean) * inv * gg.x + bb.x;
        float o1 = (v[j * 4 + 1] - mean) * inv * gg.y + bb.y;
        float o2 = (v[j * 4 + 2] - mean) * inv * gg.z + bb.z;
        float o3 = (v[j * 4 + 3] - mean) * inv * gg.w + bb.w;
        if (Yf) *(float4*)(Yf + (size_t)row * D_ + c) = make_float4(o0, o1, o2, o3);
        // 4 consecutive halves stay within one 8-half chunk (c%8==0 or 4)
        uint32_t lo = h2pack(o0, o1), hi = h2pack(o2, o3);
        *(uint2*)(Yh + tidx(row, c, D_)) = make_uint2(lo, hi);
    }
}

// ---------------- BatchNorm stats (deterministic 2-stage) ----------------
__global__ void bn_partial_kernel() {
    int blk = blockIdx.x;
    int d = threadIdx.x;      // 512
    float s = 0.0f, q = 0.0f;
    const float* base = g_tok + (size_t)blk * 256 * D_ + d;
    for (int r = 0; r < 256; r++) {
        float v = base[(size_t)r * D_];
        s += v; q += v * v;
    }
    g_psum[blk * D_ + d] = s;
    g_psq [blk * D_ + d] = q;
}

__global__ void bn_final_kernel(const float* __restrict__ gam,
                                const float* __restrict__ bet) {
    int d = threadIdx.x;      // 512, one block
    float s = 0.0f, q = 0.0f;
    for (int i = 0; i < 256; i++) {
        s += g_psum[i * D_ + d];
        q += g_psq [i * D_ + d];
    }
    float mean = s / (float)ROWS_;
    float var  = q / (float)ROWS_ - mean * mean;
    float a = gam[d] * rsqrtf(var + 1e-5f);
    g_bna[d] = a;
    g_bnb[d] = bet[d] - mean * a;
}

// ---------------- BN apply + (N,D)->(D,N) transpose into enc (tiled half) ----------------
__global__ void enc_transpose_kernel() {
    __shared__ float sm[32][33];
    int bid = blockIdx.x;
    int bc = bid >> 5;
    int r = bid & 31;
    int dt = r >> 1, nt = r & 1;
    int tx = threadIdx.x, ty = threadIdx.y;   // 32 x 8
    int d0 = dt * 32, n0 = nt * 32;
    #pragma unroll
    for (int j = 0; j < 32; j += 8) {
        int n = n0 + ty + j;
        int d = d0 + tx;
        float v = g_tok[((size_t)bc * 64 + n) * D_ + d];
        sm[ty + j][tx] = v * g_bna[d] + g_bnb[d];
    }
    __syncthreads();
    #pragma unroll
    for (int j = 0; j < 32; j += 8) {
        int d = d0 + ty + j;
        int n = n0 + tx;
        g_enc_h[tidx(bc, d * N_ + n, KHEAD_)] = __float2half_rn(sm[tx][ty + j]);
    }
}

// ---------------- head final: sum split-K partials + bias + denorm ----------------
__global__ void head_final_kernel(const float* __restrict__ b_head,
                                  float* __restrict__ out) {
    int m = blockIdx.x;        // bc
    int t = threadIdx.x;       // 512
    float v = b_head[t];
    #pragma unroll
    for (int z = 0; z < KSPLIT_; z++)
        v += g_hpart[((size_t)z * BC_ + m) * T_ + t];
    int b = m >> 5, c = m & 31;
    out[((size_t)b * T_ + t) * C_ + c] = v * g_std[m] + g_mean[m];
}

// ---------------- Launch ----------------
extern "C" void kernel_launch(void* const* d_in, const int* in_sizes, int n_in,
                              void* d_out, int out_size) {
    const float* x_enc = (const float*)d_in[0];
    const float* W_val = (const float*)d_in[1];
    const float* Wq    = (const float*)d_in[2];
    const float* bq    = (const float*)d_in[3];
    const float* Wk    = (const float*)d_in[4];
    const float* bk    = (const float*)d_in[5];
    const float* Wv    = (const float*)d_in[6];
    const float* bv    = (const float*)d_in[7];
    const float* Wo    = (const float*)d_in[8];
    const float* bo    = (const float*)d_in[9];
    const float* Wc1   = (const float*)d_in[10];
    const float* bc1   = (const float*)d_in[11];
    const float* Wc2   = (const float*)d_in[12];
    const float* bc2   = (const float*)d_in[13];
    const float* ln1_g = (const float*)d_in[14];
    const float* ln1_b = (const float*)d_in[15];
    const float* ln2_g = (const float*)d_in[16];
    const float* ln2_b = (const float*)d_in[17];
    const float* bn_g  = (const float*)d_in[18];
    const float* bn_b  = (const float*)d_in[19];
    const float* W_head= (const float*)d_in[20];
    const float* b_head= (const float*)d_in[21];
    float* out = (float*)d_out;

    float *tok, *hpart, *bqkv;
    __half *tok_h, *qkv_h, *attn_h, *y_h, *h_h, *enc_h;
    __half *wqkvT, *woT, *wc1T, *wc2T, *whT;
    cudaGetSymbolAddress((void**)&tok,    g_tok);
    cudaGetSymbolAddress((void**)&tok_h,  g_tok_h);
    cudaGetSymbolAddress((void**)&qkv_h,  g_qkv_h);
    cudaGetSymbolAddress((void**)&attn_h, g_attn_h);
    cudaGetSymbolAddress((void**)&y_h,    g_y_h);
    cudaGetSymbolAddress((void**)&h_h,    g_h_h);
    cudaGetSymbolAddress((void**)&enc_h,  g_enc_h);
    cudaGetSymbolAddress((void**)&hpart,  g_hpart);
    cudaGetSymbolAddress((void**)&bqkv,   g_bqkv);
    cudaGetSymbolAddress((void**)&wqkvT,  g_wqkvT);
    cudaGetSymbolAddress((void**)&woT,    g_woT);
    cudaGetSymbolAddress((void**)&wc1T,   g_wc1T);
    cudaGetSymbolAddress((void**)&wc2T,   g_wc2T);
    cudaGetSymbolAddress((void**)&whT,    g_whT);

    cudaFuncSetAttribute(attn_kernel, cudaFuncAttributeMaxDynamicSharedMemorySize, ATTN_SMEM);
    cudaFuncSetAttribute(hgemm_kernel<0>, cudaFuncAttributeMaxDynamicSharedMemorySize, HG_SMEM);
    cudaFuncSetAttribute(hgemm_kernel<1>, cudaFuncAttributeMaxDynamicSharedMemorySize, HG_SMEM);
    cudaFuncSetAttribute(hgemm_kernel<2>, cudaFuncAttributeMaxDynamicSharedMemorySize, HG_SMEM);
    cudaFuncSetAttribute(hgemm_kernel<4>, cudaFuncAttributeMaxDynamicSharedMemorySize, HG_SMEM);

    dim3 tb32(32, 8);
    dim3 gqkv(1536 / 128, ROWS_ / 128);       // (12, 512)
    dim3 gproj(D_ / 128, ROWS_ / 128);        // (4, 512)
    dim3 gff1(DFF_ / 128, ROWS_ / 128);       // (16, 512)
    dim3 ghead(T_ / 128, BC_ / 128, KSPLIT_); // (4, 8, 8)

    inst_stats_kernel<<<BC_, 256>>>(x_enc);
    pe_kernel<<<N_, D_>>>();
    patch_embed_kernel<<<ROWS_, 512>>>(x_enc, W_val);
    bqkv_kernel<<<NL_, 512>>>(bq, bk, bv);
    qkvtrans_kernel<<<dim3(16, 16, 3), tb32>>>(Wq, Wk, Wv, wqkvT);
    whtrans_kernel<<<dim3(16, 16), tb32>>>(Wo, woT, D_, D_);

    for (int i = 0; i < NL_; i++) {
        if (i > 0) {
            qkvtrans_kernel<<<dim3(16, 16, 3), tb32>>>(Wq + (size_t)i * D_ * D_,
                Wk + (size_t)i * D_ * D_, Wv + (size_t)i * D_ * D_,
                wqkvT + (size_t)i * 1536 * D_);
            whtrans_kernel<<<dim3(16, 16), tb32>>>(Wo + (size_t)i * D_ * D_,
                woT + (size_t)i * D_ * D_, D_, D_);
        }
        hgemm_kernel<0><<<gqkv, 256, HG_SMEM>>>(tok_h, wqkvT + (size_t)i * 1536 * D_,
            bqkv + i * 1536, nullptr, qkv_h, ROWS_, 1536, D_, D_, D_);
        whtrans_kernel<<<dim3(64, 16), tb32>>>(Wc1 + (size_t)i * D_ * DFF_,
            wc1T + (size_t)i * DFF_ * D_, D_, DFF_);
        whtrans_kernel<<<dim3(16, 64), tb32>>>(Wc2 + (size_t)i * DFF_ * D_,
            wc2T + (size_t)i * D_ * DFF_, DFF_, D_);
        attn_kernel<<<BC_ * H_, 128, ATTN_SMEM>>>();
        hgemm_kernel<1><<<gproj, 256, HG_SMEM>>>(attn_h, woT + (size_t)i * D_ * D_,
            bo + i * D_, tok, tok, ROWS_, D_, D_, D_, D_);
        ln_kernel<<<ROWS_ / 8, 256>>>(tok, ln1_g + i * D_, ln1_b + i * D_, nullptr, y_h);
        hgemm_kernel<2><<<gff1, 256, HG_SMEM>>>(y_h, wc1T + (size_t)i * DFF_ * D_,
            bc1 + i * DFF_, nullptr, h_h, ROWS_, DFF_, D_, D_, D_);
        hgemm_kernel<1><<<gproj, 256, HG_SMEM>>>(h_h, wc2T + (size_t)i * D_ * DFF_,
            bc2 + i * D_, tok, tok, ROWS_, D_, DFF_, DFF_, DFF_);
        ln_kernel<<<ROWS_ / 8, 256>>>(tok, ln2_g + i * D_, ln2_b + i * D_, tok, tok_h);
    }

    whtrans_kernel<<<dim3(16, 1024), tb32>>>(W_head, whT, KHEAD_, T_);
    bn_partial_kernel<<<256, 512>>>();
    bn_final_kernel<<<1, 512>>>(bn_g, bn_b);
    enc_transpose_kernel<<<BC_ * 32, dim3(32, 8)>>>();
    hgemm_kernel<4><<<ghead, 256, HG_SMEM>>>(enc_h, whT, nullptr, nullptr, hpart,
                                             BC_, T_, KCH_, KHEAD_, KHEAD_);
    head_final_kernel<<<BC_, T_>>>(b_head, out);
}

// round 11
// speedup vs baseline: 2.2711x; 1.0172x over previous
#include <cuda_runtime.h>
#include <cuda_fp16.h>
#include <math.h>
#include <stdint.h>

// ---------------- Problem constants ----------------
#define B_    32
#define T_    512
#define C_    32
#define D_    512
#define H_    8
#define E_    64
#define DFF_  2048
#define NL_   3
#define P_    16
#define N_    64
#define PAD_  8
#define BC_   (B_*C_)          // 1024
#define ROWS_ ((BC_)*(N_))     // 65536
#define KSPLIT_ 8
#define KCH_    4096           // 32768 / 8
#define KHEAD_  (D_*N_)        // 32768

// ---------------- Scratch (device globals; no allocation) ----------------
__device__ float  g_mean[BC_];
__device__ float  g_std[BC_];
__device__ float  g_pe  [N_ * D_];
__device__ float  g_tok  [ROWS_ * D_];                      // fp32 residual stream
__device__ __align__(256) __half g_tok_h[ROWS_ * D_];       // tiled half (QKV input)
__device__ __align__(256) __half g_qkv_h[ROWS_ * 1536];     // tiled QKV output
__device__ __align__(256) __half g_attn_h[ROWS_ * D_];      // tiled attn output
__device__ __align__(256) __half g_y_h  [ROWS_ * D_];       // tiled ln1 output
__device__ __align__(256) __half g_h_h  [ROWS_ * DFF_];     // tiled gelu output
__device__ __align__(256) __half g_enc_h[BC_ * KHEAD_];     // tiled head input
__device__ float  g_hpart[KSPLIT_ * BC_ * T_];
__device__ float  g_psum [256 * D_];
__device__ float  g_psq  [256 * D_];
__device__ float  g_bna  [D_];
__device__ float  g_bnb  [D_];
__device__ float  g_bqkv [NL_ * 1536];
// transposed half weights ([N,K] K-major, tiled layout)
__device__ __align__(256) __half g_wqkvT[NL_ * 1536 * D_];
__device__ __align__(256) __half g_woT  [NL_ * D_ * D_];
__device__ __align__(256) __half g_wc1T [NL_ * DFF_ * D_];
__device__ __align__(256) __half g_wc2T [NL_ * D_ * DFF_];
__device__ __align__(256) __half g_whT  [T_ * KHEAD_];

// ---------------- tiled-swizzled layout ----------------
// Matrix [R, K] half, stored as 128x32 blocks (8KB each), block-row-major.
// Within block: row rr, 16B-chunk c stored at chunk c' = c ^ ((rr>>1)&3).
__device__ __forceinline__ size_t tidx(int r, int k, int K) {
    int rr = r & 127;
    int kk = k & 31;
    int c  = ((kk >> 3) ^ ((rr >> 1) & 3));
    return (((size_t)(r >> 7) * (size_t)(K >> 5) + (size_t)(k >> 5)) << 12)
         + (size_t)(rr * 32 + c * 8 + (kk & 7));
}

// ---------------- helpers ----------------
#define LDSM4(r0, r1, r2, r3, addr) \
    asm volatile("ldmatrix.sync.aligned.m8n8.x4.shared.b16 {%0,%1,%2,%3}, [%4];" \
        : "=r"(r0), "=r"(r1), "=r"(r2), "=r"(r3) : "r"(addr))
#define LDSM4T(r0, r1, r2, r3, addr) \
    asm volatile("ldmatrix.sync.aligned.m8n8.x4.trans.shared.b16 {%0,%1,%2,%3}, [%4];" \
        : "=r"(r0), "=r"(r1), "=r"(r2), "=r"(r3) : "r"(addr))
#define HMMA(acc, a0, a1, a2, a3, b0, b1) \
    asm volatile("mma.sync.aligned.m16n8k16.row.col.f32.f16.f16.f32 " \
        "{%0,%1,%2,%3},{%4,%5,%6,%7},{%8,%9},{%0,%1,%2,%3};" \
        : "+f"((acc)[0]), "+f"((acc)[1]), "+f"((acc)[2]), "+f"((acc)[3]) \
        : "r"(a0), "r"(a1), "r"(a2), "r"(a3), "r"(b0), "r"(b1))

#define MBAR_INIT(addr, cnt) \
    asm volatile("mbarrier.init.shared.b64 [%0], %1;" :: "r"(addr), "r"(cnt) : "memory")
#define MBAR_EXPECT(addr, bytes) \
    asm volatile("mbarrier.arrive.expect_tx.shared.b64 _, [%0], %1;" :: "r"(addr), "r"(bytes) : "memory")
#define BULK_G2S(dst, src, bytes, bar) \
    asm volatile("cp.async.bulk.shared::cta.global.mbarrier::complete_tx::bytes [%0], [%1], %2, [%3];" \
        :: "r"(dst), "l"(src), "r"(bytes), "r"(bar) : "memory")
#define MBAR_WAIT(addr, par) do { \
    uint32_t _m = (addr), _p = (par), _d; \
    asm volatile("{\n\t.reg .pred p;\n\t" \
        "mbarrier.try_wait.parity.acquire.cta.shared::cta.b64 p, [%1], %2;\n\t" \
        "selp.b32 %0, 1, 0, p;\n\t}" : "=r"(_d) : "r"(_m), "r"(_p) : "memory"); \
    if (!_d) { \
        asm volatile("{\n\t.reg .pred P1;\n\t" \
            "WL_%=:\n\t" \
            "mbarrier.try_wait.parity.acquire.cta.shared::cta.b64 P1, [%0], %1, 0x989680;\n\t" \
            "@P1 bra.uni WD_%=;\n\t" \
            "bra.uni WL_%=;\n\t" \
            "WD_%=:\n\t}" :: "r"(_m), "r"(_p) : "memory"); \
    } \
} while (0)

__device__ __forceinline__ uint32_t smem_u32(const void* p) {
    uint32_t a;
    asm("{ .reg .u64 t; cvta.to.shared.u64 t, %1; cvt.u32.u64 %0, t; }" : "=r"(a) : "l"(p));
    return a;
}
__device__ __forceinline__ uint32_t h2pack(float x, float y) {
    __half2 h; h.x = __float2half_rn(x); h.y = __float2half_rn(y);
    return *(uint32_t*)&h;
}

// ---------------- Weight transpose -> half (tiled output) ----------------
__global__ void whtrans_kernel(const float* __restrict__ W, __half* __restrict__ WT,
                               int K, int Ncols) {
    __shared__ float s[32][33];
    int n0 = blockIdx.x * 32, k0 = blockIdx.y * 32;
    int tx = threadIdx.x, ty = threadIdx.y;   // 32 x 8
    #pragma unroll
    for (int j = 0; j < 32; j += 8)
        s[ty + j][tx] = W[(size_t)(k0 + ty + j) * Ncols + n0 + tx];
    __syncthreads();
    #pragma unroll
    for (int j = 0; j < 32; j += 8)
        WT[tidx(n0 + ty + j, k0 + tx, K)] = __float2half_rn(s[tx][ty + j]);
}

// fused QKV weight transpose for one layer: z in {0,1,2} selects q/k/v
__global__ void qkvtrans_kernel(const float* __restrict__ Wq, const float* __restrict__ Wk,
                                const float* __restrict__ Wv, __half* __restrict__ WT) {
    __shared__ float s[32][33];
    int z = blockIdx.z;
    const float* W = (z == 0) ? Wq : (z == 1) ? Wk : Wv;
    int n0 = blockIdx.x * 32, k0 = blockIdx.y * 32;
    int tx = threadIdx.x, ty = threadIdx.y;   // 32 x 8
    #pragma unroll
    for (int j = 0; j < 32; j += 8)
        s[ty + j][tx] = W[(size_t)(k0 + ty + j) * D_ + n0 + tx];
    __syncthreads();
    #pragma unroll
    for (int j = 0; j < 32; j += 8)
        WT[tidx(z * 512 + n0 + ty + j, k0 + tx, D_)] = __float2half_rn(s[tx][ty + j]);
}

__global__ void bqkv_kernel(const float* __restrict__ bq, const float* __restrict__ bk,
                            const float* __restrict__ bv) {
    int i = blockIdx.x, t = threadIdx.x;   // NL_ x 512
    g_bqkv[i * 1536 + t]        = bq[i * D_ + t];
    g_bqkv[i * 1536 + 512 + t]  = bk[i * D_ + t];
    g_bqkv[i * 1536 + 1024 + t] = bv[i * D_ + t];
}

// ---------------- PE table ----------------
__global__ void pe_kernel() {
    int n = blockIdx.x, d = threadIdx.x;   // 64 x 512
    int i2 = d >> 1;
    float div = expf(-(float)(2 * i2) * (logf(10000.0f) / (float)D_));
    float ang = (float)n * div;
    g_pe[n * D_ + d] = (d & 1) ? cosf(ang) : sinf(ang);
}

// ---------------- Instance-norm stats over time ----------------
__global__ void inst_stats_kernel(const float* __restrict__ x_enc) {
    int bc = blockIdx.x;
    int b = bc >> 5, c = bc & 31;
    int tid = threadIdx.x;          // 256
    const float* p = x_enc + (size_t)b * T_ * C_ + c;
    float v0 = p[(size_t)tid * C_];
    float v1 = p[(size_t)(tid + 256) * C_];
    __shared__ float rs[256], rq[256];
    rs[tid] = v0 + v1; rq[tid] = v0 * v0 + v1 * v1;
    __syncthreads();
    for (int off = 128; off > 0; off >>= 1) {
        if (tid < off) { rs[tid] += rs[tid + off]; rq[tid] += rq[tid + off]; }
        __syncthreads();
    }
    if (tid == 0) {
        float mean = rs[0] / (float)T_;
        float var  = rq[0] / (float)T_ - mean * mean;
        g_mean[bc] = mean;
        g_std[bc]  = sqrtf(var + 1e-5f);
    }
}

// ---------------- Patch embedding: one block per sequence (bc) ----------------
__global__ void patch_embed_kernel(const float* __restrict__ x_enc,
                                   const float* __restrict__ W_val) {
    int bc = blockIdx.x;            // 1024
    int b = bc >> 5, c = bc & 31;
    int d = threadIdx.x;            // 512
    __shared__ float xv[T_ + PAD_];
    float mean = g_mean[bc], istd = 1.0f / g_std[bc];
    xv[d] = (x_enc[(size_t)(b * T_ + d) * C_ + c] - mean) * istd;
    __syncthreads();
    if (d < PAD_) xv[T_ + d] = xv[T_ - 1];
    __syncthreads();

    float w[P_];
    #pragma unroll
    for (int p = 0; p < P_; p++) w[p] = W_val[p * D_ + d];

    for (int n = 0; n < N_; n++) {
        float acc = g_pe[n * D_ + d];
        const float* pv = &xv[n * 8];
        #pragma unroll
        for (int p = 0; p < P_; p++)
            acc = fmaf(pv[p], w[p], acc);
        int bn = bc * 64 + n;
        g_tok  [(size_t)bn * D_ + d] = acc;
        g_tok_h[tidx(bn, d, D_)]     = __float2half_rn(acc);
    }
}

// ---------------- FP16 mma GEMM: TMA-bulk staged, 128x128x64 tiles ----------------
#define NSTG   3
#define STG_B  32768
#define HG_SMEM (64 + NSTG * STG_B)     // 98368 bytes

template<int EPI>
__global__ __launch_bounds__(256, 2)
void hgemm_kernel(const __half* __restrict__ A, const __half* __restrict__ BT,
                  const float* __restrict__ bias, const float* __restrict__ res,
                  void* __restrict__ Cv, int M, int N, int K, int lda, int ldb) {
    extern __shared__ __half smh[];
    const uint32_t sbase = smem_u32(smh);
    const uint32_t stg0  = sbase + 64;

    int koff = 0;
    if (EPI == 4) koff = blockIdx.z * KCH_;

    const int tid  = threadIdx.x;
    const int warp = tid >> 5, lane = tid & 31;
    const int wm = warp >> 1, wn = warp & 1;       // 4x2 warps, 32x64 warp tile
    const int lr = lane >> 2, lc = lane & 3;
    const int bm = blockIdx.y * 128, bn = blockIdx.x * 128;
    const size_t aBlkRow = (size_t)(bm >> 7) * (size_t)(lda >> 5);
    const size_t bBlkRow = (size_t)(bn >> 7) * (size_t)(ldb >> 5);

    if (tid < NSTG) MBAR_INIT(sbase + tid * 8, 1);
    __syncthreads();

    float acc[2][8][4];
    #pragma unroll
    for (int mt = 0; mt < 2; mt++)
        #pragma unroll
        for (int nt = 0; nt < 8; nt++)
            #pragma unroll
            for (int i = 0; i < 4; i++) acc[mt][nt][i] = 0.0f;

    uint32_t aQ[2]; int aS[2];
    #pragma unroll
    for (int mt = 0; mt < 2; mt++) {
        int rr = wm * 32 + mt * 16 + (lane & 15);
        aQ[mt] = (uint32_t)(rr * 64);
        aS[mt] = (rr >> 1) & 3;
    }
    uint32_t bQ[4]; int bS[4];
    #pragma unroll
    for (int ng = 0; ng < 4; ng++) {
        int rr = wn * 64 + ng * 16 + (lane & 15);
        bQ[ng] = (uint32_t)(16384 + rr * 64);
        bS[ng] = (rr >> 1) & 3;
    }
    const int hs = lane >> 4;

    const int NIT = K >> 6;      // 64-K chunks

    auto FILL = [&](int s, int k0) {
        if (tid == 0) {
            uint32_t bar = sbase + s * 8;
            MBAR_EXPECT(bar, 32768);
            const __half* sa = A  + ((aBlkRow + (size_t)((koff + k0) >> 5)) << 12);
            const __half* sb = BT + ((bBlkRow + (size_t)((koff + k0) >> 5)) << 12);
            uint32_t st = stg0 + s * STG_B;
            BULK_G2S(st,         sa, 16384, bar);
            BULK_G2S(st + 16384, sb, 16384, bar);
        }
    };

    FILL(0, 0); FILL(1, 64);

    for (int it = 0; it < NIT; ++it) {
        const int s = it % 3;
        MBAR_WAIT(sbase + s * 8, (it / 3) & 1);

        const uint32_t st = stg0 + s * STG_B;
        #pragma unroll
        for (int ks = 0; ks < 4; ks++) {
            const uint32_t kblk = st + (uint32_t)((ks >> 1) * 8192);
            const int ksl = ks & 1;
            uint32_t af[2][4];
            #pragma unroll
            for (int mt = 0; mt < 2; mt++)
                LDSM4(af[mt][0], af[mt][1], af[mt][2], af[mt][3],
                      kblk + aQ[mt] + (uint32_t)((((ksl << 1) | hs) ^ aS[mt]) << 4));
            uint32_t bq[4][4];
            #pragma unroll
            for (int ng = 0; ng < 4; ng++)
                LDSM4(bq[ng][0], bq[ng][1], bq[ng][2], bq[ng][3],
                      kblk + bQ[ng] + (uint32_t)((((ksl << 1) | hs) ^ bS[ng]) << 4));
            #pragma unroll
            for (int mt = 0; mt < 2; mt++)
                #pragma unroll
                for (int nt = 0; nt < 8; nt++)
                    HMMA(acc[mt][nt], af[mt][0], af[mt][1], af[mt][2], af[mt][3],
                         bq[nt >> 1][nt & 1], bq[nt >> 1][(nt & 1) + 2]);
        }
        __syncthreads();
        if (it + 2 < NIT) FILL((it + 2) % 3, (it + 2) << 6);
    }

    // ---------------- epilogue ----------------
    float* Cf = (float*)Cv;
    __half* Ch = (__half*)Cv;
    if (EPI == 4) Cf += (size_t)blockIdx.z * M * N;

    #pragma unroll
    for (int mt = 0; mt < 2; mt++) {
        #pragma unroll
        for (int half = 0; half < 2; half++) {
            int m = bm + wm * 32 + mt * 16 + lr + half * 8;
            #pragma unroll
            for (int nt = 0; nt < 8; nt++) {
                int col = bn + wn * 64 + nt * 8 + lc * 2;
                float v0 = acc[mt][nt][half * 2 + 0];
                float v1 = acc[mt][nt][half * 2 + 1];
                if (EPI != 4) { v0 += bias[col]; v1 += bias[col + 1]; }
                if (EPI == 1) {
                    const float2 r2 = *(const float2*)(res + (size_t)m * N + col);
                    v0 += r2.x; v1 += r2.y;
                }
                if (EPI == 2) {
                    v0 = 0.5f * v0 * (1.0f + erff(v0 * 0.70710678118654752f));
                    v1 = 0.5f * v1 * (1.0f + erff(v1 * 0.70710678118654752f));
                }
                if (EPI == 0 || EPI == 2) {
                    __half2 hv;
                    hv.x = __float2half_rn(v0); hv.y = __float2half_rn(v1);
                    *(__half2*)(Ch + tidx(m, col, N)) = hv;
                } else {
                    *(float2*)(Cf + (size_t)m * N + col) = make_float2(v0, v1);
                }
            }
        }
    }
}

// ---------------- Attention: tensor-core (per bc,h block; 4 warps) ----------------
#define ATTN_SMEM 24576
__global__ __launch_bounds__(128)
void attn_kernel() {
    int bh = blockIdx.x;
    int bc = bh >> 3, h = bh & 7;
    extern __shared__ __half smA[];
    const uint32_t sb = smem_u32(smA);
    const int tid = threadIdx.x, warp = tid >> 5, lane = tid & 31;
    const int kq = h * 64, kk0 = 512 + h * 64, kv0 = 1024 + h * 64;

    #pragma unroll
    for (int j = 0; j < 4; j++) {
        int q = tid + j * 128;          // 0..511
        int r = q >> 3, c = q & 7;
        uint32_t doff = (uint32_t)(r * 128 + ((c ^ (r & 7)) << 4));
        int R = bc * 64 + r;
        *(uint4*)((char*)smA + doff)         = *(const uint4*)(g_qkv_h + tidx(R, kq  + c * 8, 1536));
        *(uint4*)((char*)smA + 8192 + doff)  = *(const uint4*)(g_qkv_h + tidx(R, kk0 + c * 8, 1536));
        *(uint4*)((char*)smA + 16384 + doff) = *(const uint4*)(g_qkv_h + tidx(R, kv0 + c * 8, 1536));
    }
    __syncthreads();

    const int rlo = lane & 15, hs = lane >> 4;

    float sacc[8][4];
    #pragma unroll
    for (int nt = 0; nt < 8; nt++)
        #pragma unroll
        for (int i = 0; i < 4; i++) sacc[nt][i] = 0.0f;

    #pragma unroll
    for (int ks = 0; ks < 4; ks++) {
        int cc = ks * 2 + hs;
        uint32_t a0, a1, a2, a3;
        {
            int r = warp * 16 + rlo;
            LDSM4(a0, a1, a2, a3, sb + (uint32_t)(r * 128 + ((cc ^ (r & 7)) << 4)));
        }
        #pragma unroll
        for (int ng = 0; ng < 4; ng++) {
            int r = ng * 16 + rlo;
            uint32_t b0, b1, b2, b3;
            LDSM4(b0, b1, b2, b3, sb + 8192 + (uint32_t)(r * 128 + ((cc ^ (r & 7)) << 4)));
            HMMA(sacc[2 * ng],     a0, a1, a2, a3, b0, b2);
            HMMA(sacc[2 * ng + 1], a0, a1, a2, a3, b1, b3);
        }
    }

    float mx0 = -1e30f, mx1 = -1e30f;
    #pragma unroll
    for (int nt = 0; nt < 8; nt++) {
        #pragma unroll
        for (int i = 0; i < 4; i++) sacc[nt][i] *= 0.125f;
        mx0 = fmaxf(mx0, fmaxf(sacc[nt][0], sacc[nt][1]));
        mx1 = fmaxf(mx1, fmaxf(sacc[nt][2], sacc[nt][3]));
    }
    mx0 = fmaxf(mx0, __shfl_xor_sync(0xffffffffu, mx0, 1));
    mx0 = fmaxf(mx0, __shfl_xor_sync(0xffffffffu, mx0, 2));
    mx1 = fmaxf(mx1, __shfl_xor_sync(0xffffffffu, mx1, 1));
    mx1 = fmaxf(mx1, __shfl_xor_sync(0xffffffffu, mx1, 2));
    float s0 = 0.0f, s1 = 0.0f;
    #pragma unroll
    for (int nt = 0; nt < 8; nt++) {
        sacc[nt][0] = expf(sacc[nt][0] - mx0); s0 += sacc[nt][0];
        sacc[nt][1] = expf(sacc[nt][1] - mx0); s0 += sacc[nt][1];
        sacc[nt][2] = expf(sacc[nt][2] - mx1); s1 += sacc[nt][2];
        sacc[nt][3] = expf(sacc[nt][3] - mx1); s1 += sacc[nt][3];
    }
    s0 += __shfl_xor_sync(0xffffffffu, s0, 1);
    s0 += __shfl_xor_sync(0xffffffffu, s0, 2);
    s1 += __shfl_xor_sync(0xffffffffu, s1, 1);
    s1 += __shfl_xor_sync(0xffffffffu, s1, 2);
    float i0 = 1.0f / s0, i1 = 1.0f / s1;
    #pragma unroll
    for (int nt = 0; nt < 8; nt++) {
        sacc[nt][0] *= i0; sacc[nt][1] *= i0;
        sacc[nt][2] *= i1; sacc[nt][3] *= i1;
    }

    uint32_t pa[4][4];
    #pragma unroll
    for (int ks = 0; ks < 4; ks++) {
        pa[ks][0] = h2pack(sacc[2 * ks][0],     sacc[2 * ks][1]);
        pa[ks][1] = h2pack(sacc[2 * ks][2],     sacc[2 * ks][3]);
        pa[ks][2] = h2pack(sacc[2 * ks + 1][0], sacc[2 * ks + 1][1]);
        pa[ks][3] = h2pack(sacc[2 * ks + 1][2], sacc[2 * ks + 1][3]);
    }

    float oacc[8][4];
    #pragma unroll
    for (int nt = 0; nt < 8; nt++)
        #pragma unroll
        for (int i = 0; i < 4; i++) oacc[nt][i] = 0.0f;

    #pragma unroll
    for (int ks = 0; ks < 4; ks++) {
        #pragma unroll
        for (int et = 0; et < 4; et++) {
            int r = ks * 16 + rlo;
            int cc = et * 2 + hs;
            uint32_t v0, v1, v2, v3;
            LDSM4T(v0, v1, v2, v3, sb + 16384 + (uint32_t)(r * 128 + ((cc ^ (r & 7)) << 4)));
            HMMA(oacc[2 * et],     pa[ks][0], pa[ks][1], pa[ks][2], pa[ks][3], v0, v1);
            HMMA(oacc[2 * et + 1], pa[ks][0], pa[ks][1], pa[ks][2], pa[ks][3], v2, v3);
        }
    }

    int r0w = bc * 64 + warp * 16 + (lane >> 2);
    #pragma unroll
    for (int nt = 0; nt < 8; nt++) {
        int col = h * 64 + nt * 8 + (lane & 3) * 2;
        uint32_t p0 = h2pack(oacc[nt][0], oacc[nt][1]);
        uint32_t p1 = h2pack(oacc[nt][2], oacc[nt][3]);
        *(uint32_t*)(g_attn_h + tidx(r0w,     col, D_)) = p0;
        *(uint32_t*)(g_attn_h + tidx(r0w + 8, col, D_)) = p1;
    }
}

// ---------------- LayerNorm: warp-per-row (8 rows/block) ----------------
__global__ void ln_kernel(const float* __restrict__ X,
                          const float* __restrict__ g, const float* __restrict__ b,
                          float* __restrict__ Yf, __half* __restrict__ Yh) {
    int warp = threadIdx.x >> 5, lane = threadIdx.x & 31;
    int row = blockIdx.x * 8 + warp;
    const float* x = X + (size_t)row * D_;
    float v[16];
    float s = 0.0f, q = 0.0f;
    #pragma unroll
    for (int j = 0; j < 4; j++) {
        float4 f = *(const float4*)(x + lane * 4 + j * 128);
        v[j * 4 + 0] = f.x; v[j * 4 + 1] = f.y; v[j * 4 + 2] = f.z; v[j * 4 + 3] = f.w;
        s += f.x + f.y + f.z + f.w;
        q += f.x * f.x + f.y * f.y + f.z * f.z + f.w * f.w;
    }
    #pragma unroll
    for (int o = 16; o > 0; o >>= 1) {
        s += __shfl_xor_sync(0xffffffffu, s, o);
        q += __shfl_xor_sync(0xffffffffu, q, o);
    }
    float mean = s / (float)D_;
    float inv  = rsqrtf(q / (float)D_ - mean * mean + 1e-5f);
    #pragma unroll
    for (int j = 0; j < 4; j++) {
        int c = lane * 4 + j * 128;
        float4 gg = *(const float4*)(g + c);
        float4 bb = *(const float4*)(b + c);
        float o0 = (v[j * 4 + 0] - mean) * inv * gg.x + bb.x;
        float o1 = (v[j * 4 + 1] - mean) * inv * gg.y + bb.y;
        float o2 = (v[j * 4 + 2] - mean) * inv * gg.z + bb.z;
        float o3 = (v[j * 4 + 3] - mean) * inv * gg.w + bb.w;
        if (Yf) *(float4*)(Yf + (size_t)row * D_ + c) = make_float4(o0, o1, o2, o3);
        uint32_t lo = h2pack(o0, o1), hi = h2pack(o2, o3);
        *(uint2*)(Yh + tidx(row, c, D_)) = make_uint2(lo, hi);
    }
}

// ---------------- BatchNorm stats (deterministic 2-stage) ----------------
__global__ void bn_partial_kernel() {
    int blk = blockIdx.x;
    int d = threadIdx.x;      // 512
    float s = 0.0f, q = 0.0f;
    const float* base = g_tok + (size_t)blk * 256 * D_ + d;
    for (int r = 0; r < 256; r++) {
        float v = base[(size_t)r * D_];
        s += v; q += v * v;
    }
    g_psum[blk * D_ + d] = s;
    g_psq [blk * D_ + d] = q;
}

__global__ void bn_final_kernel(const float* __restrict__ gam,
                                const float* __restrict__ bet) {
    int d = threadIdx.x;      // 512, one block
    float s = 0.0f, q = 0.0f;
    for (int i = 0; i < 256; i++) {
        s += g_psum[i * D_ + d];
        q += g_psq [i * D_ + d];
    }
    float mean = s / (float)ROWS_;
    float var  = q / (float)ROWS_ - mean * mean;
    float a = gam[d] * rsqrtf(var + 1e-5f);
    g_bna[d] = a;
    g_bnb[d] = bet[d] - mean * a;
}

// ---------------- BN apply + (N,D)->(D,N) transpose into enc (tiled half) ----------------
__global__ void enc_transpose_kernel() {
    __shared__ float sm[32][33];
    int bid = blockIdx.x;
    int bc = bid >> 5;
    int r = bid & 31;
    int dt = r >> 1, nt = r & 1;
    int tx = threadIdx.x, ty = threadIdx.y;   // 32 x 8
    int d0 = dt * 32, n0 = nt * 32;
    #pragma unroll
    for (int j = 0; j < 32; j += 8) {
        int n = n0 + ty + j;
        int d = d0 + tx;
        float v = g_tok[((size_t)bc * 64 + n) * D_ + d];
        sm[ty + j][tx] = v * g_bna[d] + g_bnb[d];
    }
    __syncthreads();
    #pragma unroll
    for (int j = 0; j < 32; j += 8) {
        int d = d0 + ty + j;
        int n = n0 + tx;
        g_enc_h[tidx(bc, d * N_ + n, KHEAD_)] = __float2half_rn(sm[tx][ty + j]);
    }
}

// ---------------- head final: sum split-K partials + bias + denorm ----------------
__global__ void head_final_kernel(const float* __restrict__ b_head,
                                  float* __restrict__ out) {
    int m = blockIdx.x;        // bc
    int t = threadIdx.x;       // 512
    float v = b_head[t];
    #pragma unroll
    for (int z = 0; z < KSPLIT_; z++)
        v += g_hpart[((size_t)z * BC_ + m) * T_ + t];
    int b = m >> 5, c = m & 31;
    out[((size_t)b * T_ + t) * C_ + c] = v * g_std[m] + g_mean[m];
}

// ---------------- Launch ----------------
extern "C" void kernel_launch(void* const* d_in, const int* in_sizes, int n_in,
                              void* d_out, int out_size) {
    const float* x_enc = (const float*)d_in[0];
    const float* W_val = (const float*)d_in[1];
    const float* Wq    = (const float*)d_in[2];
    const float* bq    = (const float*)d_in[3];
    const float* Wk    = (const float*)d_in[4];
    const float* bk    = (const float*)d_in[5];
    const float* Wv    = (const float*)d_in[6];
    const float* bv    = (const float*)d_in[7];
    const float* Wo    = (const float*)d_in[8];
    const float* bo    = (const float*)d_in[9];
    const float* Wc1   = (const float*)d_in[10];
    const float* bc1   = (const float*)d_in[11];
    const float* Wc2   = (const float*)d_in[12];
    const float* bc2   = (const float*)d_in[13];
    const float* ln1_g = (const float*)d_in[14];
    const float* ln1_b = (const float*)d_in[15];
    const float* ln2_g = (const float*)d_in[16];
    const float* ln2_b = (const float*)d_in[17];
    const float* bn_g  = (const float*)d_in[18];
    const float* bn_b  = (const float*)d_in[19];
    const float* W_head= (const float*)d_in[20];
    const float* b_head= (const float*)d_in[21];
    float* out = (float*)d_out;

    float *tok, *hpart, *bqkv;
    __half *tok_h, *qkv_h, *attn_h, *y_h, *h_h, *enc_h;
    __half *wqkvT, *woT, *wc1T, *wc2T, *whT;
    cudaGetSymbolAddress((void**)&tok,    g_tok);
    cudaGetSymbolAddress((void**)&tok_h,  g_tok_h);
    cudaGetSymbolAddress((void**)&qkv_h,  g_qkv_h);
    cudaGetSymbolAddress((void**)&attn_h, g_attn_h);
    cudaGetSymbolAddress((void**)&y_h,    g_y_h);
    cudaGetSymbolAddress((void**)&h_h,    g_h_h);
    cudaGetSymbolAddress((void**)&enc_h,  g_enc_h);
    cudaGetSymbolAddress((void**)&hpart,  g_hpart);
    cudaGetSymbolAddress((void**)&bqkv,   g_bqkv);
    cudaGetSymbolAddress((void**)&wqkvT,  g_wqkvT);
    cudaGetSymbolAddress((void**)&woT,    g_woT);
    cudaGetSymbolAddress((void**)&wc1T,   g_wc1T);
    cudaGetSymbolAddress((void**)&wc2T,   g_wc2T);
    cudaGetSymbolAddress((void**)&whT,    g_whT);

    cudaFuncSetAttribute(attn_kernel, cudaFuncAttributeMaxDynamicSharedMemorySize, ATTN_SMEM);
    cudaFuncSetAttribute(hgemm_kernel<0>, cudaFuncAttributeMaxDynamicSharedMemorySize, HG_SMEM);
    cudaFuncSetAttribute(hgemm_kernel<1>, cudaFuncAttributeMaxDynamicSharedMemorySize, HG_SMEM);
    cudaFuncSetAttribute(hgemm_kernel<2>, cudaFuncAttributeMaxDynamicSharedMemorySize, HG_SMEM);
    cudaFuncSetAttribute(hgemm_kernel<4>, cudaFuncAttributeMaxDynamicSharedMemorySize, HG_SMEM);

    dim3 tb32(32, 8);
    dim3 gqkv(1536 / 128, ROWS_ / 128);       // (12, 512)
    dim3 gproj(D_ / 128, ROWS_ / 128);        // (4, 512)
    dim3 gff1(DFF_ / 128, ROWS_ / 128);       // (16, 512)
    dim3 ghead(T_ / 128, BC_ / 128, KSPLIT_); // (4, 8, 8)

    // launches 1-5; #6 = first hgemm<0> (ncu -s 5 -c 1 profiles it)
    inst_stats_kernel<<<BC_, 256>>>(x_enc);                                       // 1
    pe_kernel<<<N_, D_>>>();                                                      // 2
    patch_embed_kernel<<<BC_, 512>>>(x_enc, W_val);                               // 3
    bqkv_kernel<<<NL_, 512>>>(bq, bk, bv);                                        // 4
    qkvtrans_kernel<<<dim3(16, 16, 3), tb32>>>(Wq, Wk, Wv, wqkvT);                // 5

    for (int i = 0; i < NL_; i++) {
        if (i > 0)
            qkvtrans_kernel<<<dim3(16, 16, 3), tb32>>>(Wq + (size_t)i * D_ * D_,
                Wk + (size_t)i * D_ * D_, Wv + (size_t)i * D_ * D_,
                wqkvT + (size_t)i * 1536 * D_);
        hgemm_kernel<0><<<gqkv, 256, HG_SMEM>>>(tok_h, wqkvT + (size_t)i * 1536 * D_,
            bqkv + i * 1536, nullptr, qkv_h, ROWS_, 1536, D_, D_, D_);            // #6 for i=0
        whtrans_kernel<<<dim3(16, 16), tb32>>>(Wo + (size_t)i * D_ * D_,
            woT + (size_t)i * D_ * D_, D_, D_);
        whtrans_kernel<<<dim3(64, 16), tb32>>>(Wc1 + (size_t)i * D_ * DFF_,
            wc1T + (size_t)i * DFF_ * D_, D_, DFF_);
        whtrans_kernel<<<dim3(16, 64), tb32>>>(Wc2 + (size_t)i * DFF_ * D_,
            wc2T + (size_t)i * D_ * DFF_, DFF_, D_);
        attn_kernel<<<BC_ * H_, 128, ATTN_SMEM>>>();
        hgemm_kernel<1><<<gproj, 256, HG_SMEM>>>(attn_h, woT + (size_t)i * D_ * D_,
            bo + i * D_, tok, tok, ROWS_, D_, D_, D_, D_);
        ln_kernel<<<ROWS_ / 8, 256>>>(tok, ln1_g + i * D_, ln1_b + i * D_, nullptr, y_h);
        hgemm_kernel<2><<<gff1, 256, HG_SMEM>>>(y_h, wc1T + (size_t)i * DFF_ * D_,
            bc1 + i * DFF_, nullptr, h_h, ROWS_, DFF_, D_, D_, D_);
        hgemm_kernel<1><<<gproj, 256, HG_SMEM>>>(h_h, wc2T + (size_t)i * D_ * DFF_,
            bc2 + i * D_, tok, tok, ROWS_, D_, DFF_, DFF_, DFF_);
        ln_kernel<<<ROWS_ / 8, 256>>>(tok, ln2_g + i * D_, ln2_b + i * D_, tok, tok_h);
    }

    whtrans_kernel<<<dim3(16, 1024), tb32>>>(W_head, whT, KHEAD_, T_);
    bn_partial_kernel<<<256, 512>>>();
    bn_final_kernel<<<1, 512>>>(bn_g, bn_b);
    enc_transpose_kernel<<<BC_ * 32, dim3(32, 8)>>>();
    hgemm_kernel<4><<<ghead, 256, HG_SMEM>>>(enc_h, whT, nullptr, nullptr, hpart,
                                             BC_, T_, KCH_, KHEAD_, KHEAD_);
    head_final_kernel<<<BC_, T_>>>(b_head, out);
}

// round 12
// speedup vs baseline: 2.2837x; 1.0056x over previous
#include <cuda_runtime.h>
#include <cuda_fp16.h>
#include <math.h>
#include <stdint.h>

// ---------------- Problem constants ----------------
#define B_    32
#define T_    512
#define C_    32
#define D_    512
#define H_    8
#define E_    64
#define DFF_  2048
#define NL_   3
#define P_    16
#define N_    64
#define PAD_  8
#define BC_   (B_*C_)          // 1024
#define ROWS_ ((BC_)*(N_))     // 65536
#define KSPLIT_ 8
#define KCH_    4096           // 32768 / 8
#define KHEAD_  (D_*N_)        // 32768

// ---------------- Scratch (device globals; no allocation) ----------------
__device__ float  g_mean[BC_];
__device__ float  g_std[BC_];
__device__ float  g_pe  [N_ * D_];
__device__ float  g_tok  [ROWS_ * D_];                      // fp32 residual stream
__device__ __align__(256) __half g_tok_h[ROWS_ * D_];       // tiled half (QKV input)
__device__ __align__(256) __half g_qkv_h[ROWS_ * 1536];     // tiled QKV output
__device__ __align__(256) __half g_attn_h[ROWS_ * D_];      // tiled attn output
__device__ __align__(256) __half g_y_h  [ROWS_ * D_];       // tiled ln1 output
__device__ __align__(256) __half g_h_h  [ROWS_ * DFF_];     // tiled gelu output
__device__ __align__(256) __half g_enc_h[BC_ * KHEAD_];     // tiled head input
__device__ float  g_hpart[KSPLIT_ * BC_ * T_];
__device__ float  g_psum [256 * D_];
__device__ float  g_psq  [256 * D_];
__device__ float  g_bna  [D_];
__device__ float  g_bnb  [D_];
__device__ float  g_bqkv [NL_ * 1536];
// transposed half weights ([N,K] K-major, tiled layout)
__device__ __align__(256) __half g_wqkvT[NL_ * 1536 * D_];
__device__ __align__(256) __half g_woT  [NL_ * D_ * D_];
__device__ __align__(256) __half g_wc1T [NL_ * DFF_ * D_];
__device__ __align__(256) __half g_wc2T [NL_ * D_ * DFF_];
__device__ __align__(256) __half g_whT  [T_ * KHEAD_];

// ---------------- tiled-swizzled layout ----------------
__device__ __forceinline__ size_t tidx(int r, int k, int K) {
    int rr = r & 127;
    int kk = k & 31;
    int c  = ((kk >> 3) ^ ((rr >> 1) & 3));
    return (((size_t)(r >> 7) * (size_t)(K >> 5) + (size_t)(k >> 5)) << 12)
         + (size_t)(rr * 32 + c * 8 + (kk & 7));
}

// ---------------- helpers ----------------
#define LDSM4(r0, r1, r2, r3, addr) \
    asm volatile("ldmatrix.sync.aligned.m8n8.x4.shared.b16 {%0,%1,%2,%3}, [%4];" \
        : "=r"(r0), "=r"(r1), "=r"(r2), "=r"(r3) : "r"(addr))
#define LDSM4T(r0, r1, r2, r3, addr) \
    asm volatile("ldmatrix.sync.aligned.m8n8.x4.trans.shared.b16 {%0,%1,%2,%3}, [%4];" \
        : "=r"(r0), "=r"(r1), "=r"(r2), "=r"(r3) : "r"(addr))
#define HMMA(acc, a0, a1, a2, a3, b0, b1) \
    asm volatile("mma.sync.aligned.m16n8k16.row.col.f32.f16.f16.f32 " \
        "{%0,%1,%2,%3},{%4,%5,%6,%7},{%8,%9},{%0,%1,%2,%3};" \
        : "+f"((acc)[0]), "+f"((acc)[1]), "+f"((acc)[2]), "+f"((acc)[3]) \
        : "r"(a0), "r"(a1), "r"(a2), "r"(a3), "r"(b0), "r"(b1))

#define MBAR_INIT(addr, cnt) \
    asm volatile("mbarrier.init.shared.b64 [%0], %1;" :: "r"(addr), "r"(cnt) : "memory")
#define MBAR_EXPECT(addr, bytes) \
    asm volatile("mbarrier.arrive.expect_tx.shared.b64 _, [%0], %1;" :: "r"(addr), "r"(bytes) : "memory")
#define BULK_G2S(dst, src, bytes, bar) \
    asm volatile("cp.async.bulk.shared::cta.global.mbarrier::complete_tx::bytes [%0], [%1], %2, [%3];" \
        :: "r"(dst), "l"(src), "r"(bytes), "r"(bar) : "memory")
#define MBAR_WAIT(addr, par) do { \
    uint32_t _m = (addr), _p = (par), _d; \
    asm volatile("{\n\t.reg .pred p;\n\t" \
        "mbarrier.try_wait.parity.acquire.cta.shared::cta.b64 p, [%1], %2;\n\t" \
        "selp.b32 %0, 1, 0, p;\n\t}" : "=r"(_d) : "r"(_m), "r"(_p) : "memory"); \
    if (!_d) { \
        asm volatile("{\n\t.reg .pred P1;\n\t" \
            "WL_%=:\n\t" \
            "mbarrier.try_wait.parity.acquire.cta.shared::cta.b64 P1, [%0], %1, 0x989680;\n\t" \
            "@P1 bra.uni WD_%=;\n\t" \
            "bra.uni WL_%=;\n\t" \
            "WD_%=:\n\t}" :: "r"(_m), "r"(_p) : "memory"); \
    } \
} while (0)

__device__ __forceinline__ uint32_t smem_u32(const void* p) {
    uint32_t a;
    asm("{ .reg .u64 t; cvta.to.shared.u64 t, %1; cvt.u32.u64 %0, t; }" : "=r"(a) : "l"(p));
    return a;
}
__device__ __forceinline__ uint32_t h2pack(float x, float y) {
    __half2 h; h.x = __float2half_rn(x); h.y = __float2half_rn(y);
    return *(uint32_t*)&h;
}

// ---------------- Weight transpose -> half (tiled output), z = layer ----------------
__global__ void whtrans_kernel(const float* __restrict__ W, __half* __restrict__ WT,
                               int K, int Ncols) {
    __shared__ float s[32][33];
    int L = blockIdx.z;
    W  += (size_t)L * K * Ncols;
    WT += (size_t)L * K * Ncols;
    int n0 = blockIdx.x * 32, k0 = blockIdx.y * 32;
    int tx = threadIdx.x, ty = threadIdx.y;   // 32 x 8
    #pragma unroll
    for (int j = 0; j < 32; j += 8)
        s[ty + j][tx] = W[(size_t)(k0 + ty + j) * Ncols + n0 + tx];
    __syncthreads();
    #pragma unroll
    for (int j = 0; j < 32; j += 8)
        WT[tidx(n0 + ty + j, k0 + tx, K)] = __float2half_rn(s[tx][ty + j]);
}

// fused QKV weight transpose, ALL layers (z = layer*3 + m), + bias pack
__global__ void qkvtrans_kernel(const float* __restrict__ Wq, const float* __restrict__ Wk,
                                const float* __restrict__ Wv,
                                const float* __restrict__ bq, const float* __restrict__ bk,
                                const float* __restrict__ bv) {
    __shared__ float s[32][33];
    int L = blockIdx.z / 3, m = blockIdx.z % 3;
    const float* W = ((m == 0) ? Wq : (m == 1) ? Wk : Wv) + (size_t)L * D_ * D_;
    __half* WT = g_wqkvT + (size_t)L * 1536 * D_;
    int n0 = blockIdx.x * 32, k0 = blockIdx.y * 32;
    int tx = threadIdx.x, ty = threadIdx.y;   // 32 x 8
    #pragma unroll
    for (int j = 0; j < 32; j += 8)
        s[ty + j][tx] = W[(size_t)(k0 + ty + j) * D_ + n0 + tx];
    __syncthreads();
    #pragma unroll
    for (int j = 0; j < 32; j += 8)
        WT[tidx(m * 512 + n0 + ty + j, k0 + tx, D_)] = __float2half_rn(s[tx][ty + j]);
    // bias pack: one block per layer does it
    if (m == 0 && blockIdx.x == 0 && blockIdx.y == 0) {
        int t = ty * 32 + tx;                // 0..255
        #pragma unroll
        for (int u = 0; u < 2; u++) {
            int d = t + u * 256;
            g_bqkv[L * 1536 + d]        = bq[L * D_ + d];
            g_bqkv[L * 1536 + 512 + d]  = bk[L * D_ + d];
            g_bqkv[L * 1536 + 1024 + d] = bv[L * D_ + d];
        }
    }
}

// ---------------- Instance-norm stats + PE table (blocks 0..63 fill PE row) ----------------
__global__ void inst_stats_kernel(const float* __restrict__ x_enc) {
    int bc = blockIdx.x;
    int b = bc >> 5, c = bc & 31;
    int tid = threadIdx.x;          // 256
    const float* p = x_enc + (size_t)b * T_ * C_ + c;
    float v0 = p[(size_t)tid * C_];
    float v1 = p[(size_t)(tid + 256) * C_];
    __shared__ float rs[256], rq[256];
    rs[tid] = v0 + v1; rq[tid] = v0 * v0 + v1 * v1;
    __syncthreads();
    for (int off = 128; off > 0; off >>= 1) {
        if (tid < off) { rs[tid] += rs[tid + off]; rq[tid] += rq[tid + off]; }
        __syncthreads();
    }
    if (tid == 0) {
        float mean = rs[0] / (float)T_;
        float var  = rq[0] / (float)T_ - mean * mean;
        g_mean[bc] = mean;
        g_std[bc]  = sqrtf(var + 1e-5f);
    }
    if (bc < N_) {
        #pragma unroll
        for (int u = 0; u < 2; u++) {
            int d = tid + u * 256;
            int i2 = d >> 1;
            float div = expf(-(float)(2 * i2) * (logf(10000.0f) / (float)D_));
            float ang = (float)bc * div;
            g_pe[bc * D_ + d] = (d & 1) ? cosf(ang) : sinf(ang);
        }
    }
}

// ---------------- Patch embedding: one block per sequence (bc) ----------------
__global__ void patch_embed_kernel(const float* __restrict__ x_enc,
                                   const float* __restrict__ W_val) {
    int bc = blockIdx.x;            // 1024
    int b = bc >> 5, c = bc & 31;
    int d = threadIdx.x;            // 512
    __shared__ float xv[T_ + PAD_];
    float mean = g_mean[bc], istd = 1.0f / g_std[bc];
    xv[d] = (x_enc[(size_t)(b * T_ + d) * C_ + c] - mean) * istd;
    __syncthreads();
    if (d < PAD_) xv[T_ + d] = xv[T_ - 1];
    __syncthreads();

    float w[P_];
    #pragma unroll
    for (int p = 0; p < P_; p++) w[p] = W_val[p * D_ + d];

    for (int n = 0; n < N_; n++) {
        float acc = g_pe[n * D_ + d];
        const float* pv = &xv[n * 8];
        #pragma unroll
        for (int p = 0; p < P_; p++)
            acc = fmaf(pv[p], w[p], acc);
        int bn = bc * 64 + n;
        g_tok  [(size_t)bn * D_ + d] = acc;
        g_tok_h[tidx(bn, d, D_)]     = __float2half_rn(acc);
    }
}

// ---------------- FP16 mma GEMM: TMA-bulk staged, 128x128x64 tiles ----------------
#define NSTG   3
#define STG_B  32768
#define HG_SMEM (64 + NSTG * STG_B)     // 98368 bytes

template<int EPI>
__global__ __launch_bounds__(256, 2)
void hgemm_kernel(const __half* __restrict__ A, const __half* __restrict__ BT,
                  const float* __restrict__ bias, const float* __restrict__ res,
                  void* __restrict__ Cv, int M, int N, int K, int lda, int ldb) {
    extern __shared__ __half smh[];
    const uint32_t sbase = smem_u32(smh);
    const uint32_t stg0  = sbase + 64;

    int koff = 0;
    if (EPI == 4) koff = blockIdx.z * KCH_;

    const int tid  = threadIdx.x;
    const int warp = tid >> 5, lane = tid & 31;
    const int wm = warp >> 1, wn = warp & 1;       // 4x2 warps, 32x64 warp tile
    const int lr = lane >> 2, lc = lane & 3;
    const int bm = blockIdx.y * 128, bn = blockIdx.x * 128;
    const size_t aBlkRow = (size_t)(bm >> 7) * (size_t)(lda >> 5);
    const size_t bBlkRow = (size_t)(bn >> 7) * (size_t)(ldb >> 5);

    if (tid < NSTG) MBAR_INIT(sbase + tid * 8, 1);
    __syncthreads();

    float acc[2][8][4];
    #pragma unroll
    for (int mt = 0; mt < 2; mt++)
        #pragma unroll
        for (int nt = 0; nt < 8; nt++)
            #pragma unroll
            for (int i = 0; i < 4; i++) acc[mt][nt][i] = 0.0f;

    uint32_t aQ[2]; int aS[2];
    #pragma unroll
    for (int mt = 0; mt < 2; mt++) {
        int rr = wm * 32 + mt * 16 + (lane & 15);
        aQ[mt] = (uint32_t)(rr * 64);
        aS[mt] = (rr >> 1) & 3;
    }
    uint32_t bQ[4]; int bS[4];
    #pragma unroll
    for (int ng = 0; ng < 4; ng++) {
        int rr = wn * 64 + ng * 16 + (lane & 15);
        bQ[ng] = (uint32_t)(16384 + rr * 64);
        bS[ng] = (rr >> 1) & 3;
    }
    const int hs = lane >> 4;

    const int NIT = K >> 6;      // 64-K chunks

    auto FILL = [&](int s, int k0) {
        if (tid == 0) {
            uint32_t bar = sbase + s * 8;
            MBAR_EXPECT(bar, 32768);
            const __half* sa = A  + ((aBlkRow + (size_t)((koff + k0) >> 5)) << 12);
            const __half* sb = BT + ((bBlkRow + (size_t)((koff + k0) >> 5)) << 12);
            uint32_t st = stg0 + s * STG_B;
            BULK_G2S(st,         sa, 16384, bar);
            BULK_G2S(st + 16384, sb, 16384, bar);
        }
    };

    FILL(0, 0); FILL(1, 64);

    for (int it = 0; it < NIT; ++it) {
        const int s = it % 3;
        MBAR_WAIT(sbase + s * 8, (it / 3) & 1);

        const uint32_t st = stg0 + s * STG_B;
        #pragma unroll
        for (int ks = 0; ks < 4; ks++) {
            const uint32_t kblk = st + (uint32_t)((ks >> 1) * 8192);
            const int ksl = ks & 1;
            uint32_t af[2][4];
            #pragma unroll
            for (int mt = 0; mt < 2; mt++)
                LDSM4(af[mt][0], af[mt][1], af[mt][2], af[mt][3],
                      kblk + aQ[mt] + (uint32_t)((((ksl << 1) | hs) ^ aS[mt]) << 4));
            uint32_t bq[4][4];
            #pragma unroll
            for (int ng = 0; ng < 4; ng++)
                LDSM4(bq[ng][0], bq[ng][1], bq[ng][2], bq[ng][3],
                      kblk + bQ[ng] + (uint32_t)((((ksl << 1) | hs) ^ bS[ng]) << 4));
            #pragma unroll
            for (int mt = 0; mt < 2; mt++)
                #pragma unroll
                for (int nt = 0; nt < 8; nt++)
                    HMMA(acc[mt][nt], af[mt][0], af[mt][1], af[mt][2], af[mt][3],
                         bq[nt >> 1][nt & 1], bq[nt >> 1][(nt & 1) + 2]);
        }
        __syncthreads();
        if (it + 2 < NIT) FILL((it + 2) % 3, (it + 2) << 6);
    }

    // ---------------- epilogue ----------------
    float* Cf = (float*)Cv;
    __half* Ch = (__half*)Cv;
    if (EPI == 4) Cf += (size_t)blockIdx.z * M * N;

    #pragma unroll
    for (int mt = 0; mt < 2; mt++) {
        #pragma unroll
        for (int half = 0; half < 2; half++) {
            int m = bm + wm * 32 + mt * 16 + lr + half * 8;
            #pragma unroll
            for (int nt = 0; nt < 8; nt++) {
                int col = bn + wn * 64 + nt * 8 + lc * 2;
                float v0 = acc[mt][nt][half * 2 + 0];
                float v1 = acc[mt][nt][half * 2 + 1];
                if (EPI != 4) { v0 += bias[col]; v1 += bias[col + 1]; }
                if (EPI == 1) {
                    const float2 r2 = *(const float2*)(res + (size_t)m * N + col);
                    v0 += r2.x; v1 += r2.y;
                }
                if (EPI == 2) {
                    v0 = 0.5f * v0 * (1.0f + erff(v0 * 0.70710678118654752f));
                    v1 = 0.5f * v1 * (1.0f + erff(v1 * 0.70710678118654752f));
                }
                if (EPI == 0 || EPI == 2) {
                    __half2 hv;
                    hv.x = __float2half_rn(v0); hv.y = __float2half_rn(v1);
                    *(__half2*)(Ch + tidx(m, col, N)) = hv;
                } else {
                    *(float2*)(Cf + (size_t)m * N + col) = make_float2(v0, v1);
                }
            }
        }
    }
}

// ---------------- Attention: tensor-core (per bc,h block; 4 warps) ----------------
#define ATTN_SMEM 24576
__global__ __launch_bounds__(128)
void attn_kernel() {
    int bh = blockIdx.x;
    int bc = bh >> 3, h = bh & 7;
    extern __shared__ __half smA[];
    const uint32_t sb = smem_u32(smA);
    const int tid = threadIdx.x, warp = tid >> 5, lane = tid & 31;
    const int kq = h * 64, kk0 = 512 + h * 64, kv0 = 1024 + h * 64;

    #pragma unroll
    for (int j = 0; j < 4; j++) {
        int q = tid + j * 128;          // 0..511
        int r = q >> 3, c = q & 7;
        uint32_t doff = (uint32_t)(r * 128 + ((c ^ (r & 7)) << 4));
        int R = bc * 64 + r;
        *(uint4*)((char*)smA + doff)         = *(const uint4*)(g_qkv_h + tidx(R, kq  + c * 8, 1536));
        *(uint4*)((char*)smA + 8192 + doff)  = *(const uint4*)(g_qkv_h + tidx(R, kk0 + c * 8, 1536));
        *(uint4*)((char*)smA + 16384 + doff) = *(const uint4*)(g_qkv_h + tidx(R, kv0 + c * 8, 1536));
    }
    __syncthreads();

    const int rlo = lane & 15, hs = lane >> 4;

    float sacc[8][4];
    #pragma unroll
    for (int nt = 0; nt < 8; nt++)
        #pragma unroll
        for (int i = 0; i < 4; i++) sacc[nt][i] = 0.0f;

    #pragma unroll
    for (int ks = 0; ks < 4; ks++) {
        int cc = ks * 2 + hs;
        uint32_t a0, a1, a2, a3;
        {
            int r = warp * 16 + rlo;
            LDSM4(a0, a1, a2, a3, sb + (uint32_t)(r * 128 + ((cc ^ (r & 7)) << 4)));
        }
        #pragma unroll
        for (int ng = 0; ng < 4; ng++) {
            int r = ng * 16 + rlo;
            uint32_t b0, b1, b2, b3;
            LDSM4(b0, b1, b2, b3, sb + 8192 + (uint32_t)(r * 128 + ((cc ^ (r & 7)) << 4)));
            HMMA(sacc[2 * ng],     a0, a1, a2, a3, b0, b2);
            HMMA(sacc[2 * ng + 1], a0, a1, a2, a3, b1, b3);
        }
    }

    float mx0 = -1e30f, mx1 = -1e30f;
    #pragma unroll
    for (int nt = 0; nt < 8; nt++) {
        #pragma unroll
        for (int i = 0; i < 4; i++) sacc[nt][i] *= 0.125f;
        mx0 = fmaxf(mx0, fmaxf(sacc[nt][0], sacc[nt][1]));
        mx1 = fmaxf(mx1, fmaxf(sacc[nt][2], sacc[nt][3]));
    }
    mx0 = fmaxf(mx0, __shfl_xor_sync(0xffffffffu, mx0, 1));
    mx0 = fmaxf(mx0, __shfl_xor_sync(0xffffffffu, mx0, 2));
    mx1 = fmaxf(mx1, __shfl_xor_sync(0xffffffffu, mx1, 1));
    mx1 = fmaxf(mx1, __shfl_xor_sync(0xffffffffu, mx1, 2));
    float s0 = 0.0f, s1 = 0.0f;
    #pragma unroll
    for (int nt = 0; nt < 8; nt++) {
        sacc[nt][0] = expf(sacc[nt][0] - mx0); s0 += sacc[nt][0];
        sacc[nt][1] = expf(sacc[nt][1] - mx0); s0 += sacc[nt][1];
        sacc[nt][2] = expf(sacc[nt][2] - mx1); s1 += sacc[nt][2];
        sacc[nt][3] = expf(sacc[nt][3] - mx1); s1 += sacc[nt][3];
    }
    s0 += __shfl_xor_sync(0xffffffffu, s0, 1);
    s0 += __shfl_xor_sync(0xffffffffu, s0, 2);
    s1 += __shfl_xor_sync(0xffffffffu, s1, 1);
    s1 += __shfl_xor_sync(0xffffffffu, s1, 2);
    float i0 = 1.0f / s0, i1 = 1.0f / s1;
    #pragma unroll
    for (int nt = 0; nt < 8; nt++) {
        sacc[nt][0] *= i0; sacc[nt][1] *= i0;
        sacc[nt][2] *= i1; sacc[nt][3] *= i1;
    }

    uint32_t pa[4][4];
    #pragma unroll
    for (int ks = 0; ks < 4; ks++) {
        pa[ks][0] = h2pack(sacc[2 * ks][0],     sacc[2 * ks][1]);
        pa[ks][1] = h2pack(sacc[2 * ks][2],     sacc[2 * ks][3]);
        pa[ks][2] = h2pack(sacc[2 * ks + 1][0], sacc[2 * ks + 1][1]);
        pa[ks][3] = h2pack(sacc[2 * ks + 1][2], sacc[2 * ks + 1][3]);
    }

    float oacc[8][4];
    #pragma unroll
    for (int nt = 0; nt < 8; nt++)
        #pragma unroll
        for (int i = 0; i < 4; i++) oacc[nt][i] = 0.0f;

    #pragma unroll
    for (int ks = 0; ks < 4; ks++) {
        #pragma unroll
        for (int et = 0; et < 4; et++) {
            int r = ks * 16 + rlo;
            int cc = et * 2 + hs;
            uint32_t v0, v1, v2, v3;
            LDSM4T(v0, v1, v2, v3, sb + 16384 + (uint32_t)(r * 128 + ((cc ^ (r & 7)) << 4)));
            HMMA(oacc[2 * et],     pa[ks][0], pa[ks][1], pa[ks][2], pa[ks][3], v0, v1);
            HMMA(oacc[2 * et + 1], pa[ks][0], pa[ks][1], pa[ks][2], pa[ks][3], v2, v3);
        }
    }

    int r0w = bc * 64 + warp * 16 + (lane >> 2);
    #pragma unroll
    for (int nt = 0; nt < 8; nt++) {
        int col = h * 64 + nt * 8 + (lane & 3) * 2;
        uint32_t p0 = h2pack(oacc[nt][0], oacc[nt][1]);
        uint32_t p1 = h2pack(oacc[nt][2], oacc[nt][3]);
        *(uint32_t*)(g_attn_h + tidx(r0w,     col, D_)) = p0;
        *(uint32_t*)(g_attn_h + tidx(r0w + 8, col, D_)) = p1;
    }
}

// ---------------- LayerNorm: warp-per-row (8 rows/block) ----------------
__global__ void ln_kernel(const float* __restrict__ X,
                          const float* __restrict__ g, const float* __restrict__ b,
                          float* __restrict__ Yf, __half* __restrict__ Yh) {
    int warp = threadIdx.x >> 5, lane = threadIdx.x & 31;
    int row = blockIdx.x * 8 + warp;
    const float* x = X + (size_t)row * D_;
    float v[16];
    float s = 0.0f, q = 0.0f;
    #pragma unroll
    for (int j = 0; j < 4; j++) {
        float4 f = *(const float4*)(x + lane * 4 + j * 128);
        v[j * 4 + 0] = f.x; v[j * 4 + 1] = f.y; v[j * 4 + 2] = f.z; v[j * 4 + 3] = f.w;
        s += f.x + f.y + f.z + f.w;
        q += f.x * f.x + f.y * f.y + f.z * f.z + f.w * f.w;
    }
    #pragma unroll
    for (int o = 16; o > 0; o >>= 1) {
        s += __shfl_xor_sync(0xffffffffu, s, o);
        q += __shfl_xor_sync(0xffffffffu, q, o);
    }
    float mean = s / (float)D_;
    float inv  = rsqrtf(q / (float)D_ - mean * mean + 1e-5f);
    #pragma unroll
    for (int j = 0; j < 4; j++) {
        int c = lane * 4 + j * 128;
        float4 gg = *(const float4*)(g + c);
        float4 bb = *(const float4*)(b + c);
        float o0 = (v[j * 4 + 0] - mean) * inv * gg.x + bb.x;
        float o1 = (v[j * 4 + 1] - mean) * inv * gg.y + bb.y;
        float o2 = (v[j * 4 + 2] - mean) * inv * gg.z + bb.z;
        float o3 = (v[j * 4 + 3] - mean) * inv * gg.w + bb.w;
        if (Yf) *(float4*)(Yf + (size_t)row * D_ + c) = make_float4(o0, o1, o2, o3);
        uint32_t lo = h2pack(o0, o1), hi = h2pack(o2, o3);
        *(uint2*)(Yh + tidx(row, c, D_)) = make_uint2(lo, hi);
    }
}

// ---------------- BatchNorm stats (deterministic 2-stage) ----------------
__global__ void bn_partial_kernel() {
    int blk = blockIdx.x;
    int d = threadIdx.x;      // 512
    float s = 0.0f, q = 0.0f;
    const float* base = g_tok + (size_t)blk * 256 * D_ + d;
    for (int r = 0; r < 256; r++) {
        float v = base[(size_t)r * D_];
        s += v; q += v * v;
    }
    g_psum[blk * D_ + d] = s;
    g_psq [blk * D_ + d] = q;
}

__global__ void bn_final_kernel(const float* __restrict__ gam,
                                const float* __restrict__ bet) {
    int d = threadIdx.x;      // 512, one block
    float s = 0.0f, q = 0.0f;
    for (int i = 0; i < 256; i++) {
        s += g_psum[i * D_ + d];
        q += g_psq [i * D_ + d];
    }
    float mean = s / (float)ROWS_;
    float var  = q / (float)ROWS_ - mean * mean;
    float a = gam[d] * rsqrtf(var + 1e-5f);
    g_bna[d] = a;
    g_bnb[d] = bet[d] - mean * a;
}

// ---------------- BN apply + (N,D)->(D,N) transpose into enc (tiled half) ----------------
__global__ void enc_transpose_kernel() {
    __shared__ float sm[32][33];
    int bid = blockIdx.x;
    int bc = bid >> 5;
    int r = bid & 31;
    int dt = r >> 1, nt = r & 1;
    int tx = threadIdx.x, ty = threadIdx.y;   // 32 x 8
    int d0 = dt * 32, n0 = nt * 32;
    #pragma unroll
    for (int j = 0; j < 32; j += 8) {
        int n = n0 + ty + j;
        int d = d0 + tx;
        float v = g_tok[((size_t)bc * 64 + n) * D_ + d];
        sm[ty + j][tx] = v * g_bna[d] + g_bnb[d];
    }
    __syncthreads();
    #pragma unroll
    for (int j = 0; j < 32; j += 8) {
        int d = d0 + ty + j;
        int n = n0 + tx;
        g_enc_h[tidx(bc, d * N_ + n, KHEAD_)] = __float2half_rn(sm[tx][ty + j]);
    }
}

// ---------------- head final: sum split-K partials + bias + denorm ----------------
__global__ void head_final_kernel(const float* __restrict__ b_head,
                                  float* __restrict__ out) {
    int m = blockIdx.x;        // bc
    int t = threadIdx.x;       // 512
    float v = b_head[t];
    #pragma unroll
    for (int z = 0; z < KSPLIT_; z++)
        v += g_hpart[((size_t)z * BC_ + m) * T_ + t];
    int b = m >> 5, c = m & 31;
    out[((size_t)b * T_ + t) * C_ + c] = v * g_std[m] + g_mean[m];
}

// ---------------- Launch ----------------
extern "C" void kernel_launch(void* const* d_in, const int* in_sizes, int n_in,
                              void* d_out, int out_size) {
    const float* x_enc = (const float*)d_in[0];
    const float* W_val = (const float*)d_in[1];
    const float* Wq    = (const float*)d_in[2];
    const float* bq    = (const float*)d_in[3];
    const float* Wk    = (const float*)d_in[4];
    const float* bk    = (const float*)d_in[5];
    const float* Wv    = (const float*)d_in[6];
    const float* bv    = (const float*)d_in[7];
    const float* Wo    = (const float*)d_in[8];
    const float* bo    = (const float*)d_in[9];
    const float* Wc1   = (const float*)d_in[10];
    const float* bc1   = (const float*)d_in[11];
    const float* Wc2   = (const float*)d_in[12];
    const float* bc2   = (const float*)d_in[13];
    const float* ln1_g = (const float*)d_in[14];
    const float* ln1_b = (const float*)d_in[15];
    const float* ln2_g = (const float*)d_in[16];
    const float* ln2_b = (const float*)d_in[17];
    const float* bn_g  = (const float*)d_in[18];
    const float* bn_b  = (const float*)d_in[19];
    const float* W_head= (const float*)d_in[20];
    const float* b_head= (const float*)d_in[21];
    float* out = (float*)d_out;

    float *tok, *hpart, *bqkv_p;
    __half *tok_h, *qkv_h, *attn_h, *y_h, *h_h, *enc_h;
    __half *wqkvT, *woT, *wc1T, *wc2T, *whT;
    cudaGetSymbolAddress((void**)&tok,    g_tok);
    cudaGetSymbolAddress((void**)&tok_h,  g_tok_h);
    cudaGetSymbolAddress((void**)&qkv_h,  g_qkv_h);
    cudaGetSymbolAddress((void**)&attn_h, g_attn_h);
    cudaGetSymbolAddress((void**)&y_h,    g_y_h);
    cudaGetSymbolAddress((void**)&h_h,    g_h_h);
    cudaGetSymbolAddress((void**)&enc_h,  g_enc_h);
    cudaGetSymbolAddress((void**)&hpart,  g_hpart);
    cudaGetSymbolAddress((void**)&bqkv_p, g_bqkv);
    cudaGetSymbolAddress((void**)&wqkvT,  g_wqkvT);
    cudaGetSymbolAddress((void**)&woT,    g_woT);
    cudaGetSymbolAddress((void**)&wc1T,   g_wc1T);
    cudaGetSymbolAddress((void**)&wc2T,   g_wc2T);
    cudaGetSymbolAddress((void**)&whT,    g_whT);

    cudaFuncSetAttribute(attn_kernel, cudaFuncAttributeMaxDynamicSharedMemorySize, ATTN_SMEM);
    cudaFuncSetAttribute(hgemm_kernel<0>, cudaFuncAttributeMaxDynamicSharedMemorySize, HG_SMEM);
    cudaFuncSetAttribute(hgemm_kernel<1>, cudaFuncAttributeMaxDynamicSharedMemorySize, HG_SMEM);
    cudaFuncSetAttribute(hgemm_kernel<2>, cudaFuncAttributeMaxDynamicSharedMemorySize, HG_SMEM);
    cudaFuncSetAttribute(hgemm_kernel<4>, cudaFuncAttributeMaxDynamicSharedMemorySize, HG_SMEM);

    dim3 tb32(32, 8);
    dim3 gqkv(1536 / 128, ROWS_ / 128);       // (12, 512)
    dim3 gproj(D_ / 128, ROWS_ / 128);        // (4, 512)
    dim3 gff1(DFF_ / 128, ROWS_ / 128);       // (16, 512)
    dim3 ghead(T_ / 128, BC_ / 128, KSPLIT_); // (4, 8, 8)

    // my launches 1-3; #4 = first hgemm<0> (profiled slot)
    inst_stats_kernel<<<BC_, 256>>>(x_enc);                                       // 1 (+PE)
    patch_embed_kernel<<<BC_, 512>>>(x_enc, W_val);                               // 2
    qkvtrans_kernel<<<dim3(16, 16, 9), tb32>>>(Wq, Wk, Wv, bq, bk, bv);           // 3 (all layers + bias)

    for (int i = 0; i < NL_; i++) {
        hgemm_kernel<0><<<gqkv, 256, HG_SMEM>>>(tok_h, wqkvT + (size_t)i * 1536 * D_,
            bqkv_p + i * 1536, nullptr, qkv_h, ROWS_, 1536, D_, D_, D_);          // #4 for i=0
        if (i == 0) {
            whtrans_kernel<<<dim3(16, 16, 3), tb32>>>(Wo,  woT,  D_, D_);
            whtrans_kernel<<<dim3(64, 16, 3), tb32>>>(Wc1, wc1T, D_, DFF_);
            whtrans_kernel<<<dim3(16, 64, 3), tb32>>>(Wc2, wc2T, DFF_, D_);
        }
        attn_kernel<<<BC_ * H_, 128, ATTN_SMEM>>>();
        hgemm_kernel<1><<<gproj, 256, HG_SMEM>>>(attn_h, woT + (size_t)i * D_ * D_,
            bo + i * D_, tok, tok, ROWS_, D_, D_, D_, D_);
        ln_kernel<<<ROWS_ / 8, 256>>>(tok, ln1_g + i * D_, ln1_b + i * D_, nullptr, y_h);
        hgemm_kernel<2><<<gff1, 256, HG_SMEM>>>(y_h, wc1T + (size_t)i * DFF_ * D_,
            bc1 + i * DFF_, nullptr, h_h, ROWS_, DFF_, D_, D_, D_);
        hgemm_kernel<1><<<gproj, 256, HG_SMEM>>>(h_h, wc2T + (size_t)i * D_ * DFF_,
            bc2 + i * D_, tok, tok, ROWS_, D_, DFF_, DFF_, DFF_);
        ln_kernel<<<ROWS_ / 8, 256>>>(tok, ln2_g + i * D_, ln2_b + i * D_, tok, tok_h);
    }

    whtrans_kernel<<<dim3(16, 1024, 1), tb32>>>(W_head, whT, KHEAD_, T_);
    bn_partial_kernel<<<256, 512>>>();
    bn_final_kernel<<<1, 512>>>(bn_g, bn_b);
    enc_transpose_kernel<<<BC_ * 32, dim3(32, 8)>>>();
    hgemm_kernel<4><<<ghead, 256, HG_SMEM>>>(enc_h, whT, nullptr, nullptr, hpart,
                                             BC_, T_, KCH_, KHEAD_, KHEAD_);
    head_final_kernel<<<BC_, T_>>>(b_head, out);
}

// round 13
// speedup vs baseline: 2.3259x; 1.0185x over previous
#include <cuda_runtime.h>
#include <cuda_fp16.h>
#include <math.h>
#include <stdint.h>

// ---------------- Problem constants ----------------
#define B_    32
#define T_    512
#define C_    32
#define D_    512
#define H_    8
#define E_    64
#define DFF_  2048
#define NL_   3
#define P_    16
#define N_    64
#define PAD_  8
#define BC_   (B_*C_)          // 1024
#define ROWS_ ((BC_)*(N_))     // 65536
#define KSPLIT_ 8
#define KCH_    4096           // 32768 / 8
#define KHEAD_  (D_*N_)        // 32768

// ---------------- Scratch (device globals; no allocation) ----------------
__device__ float  g_mean[BC_];
__device__ float  g_std[BC_];
__device__ float  g_pe  [N_ * D_];
__device__ float  g_tok  [ROWS_ * D_];                      // fp32 residual stream
__device__ __align__(256) __half g_tok_h[ROWS_ * D_];       // tiled half (QKV input)
__device__ __align__(256) __half g_qkv_h[ROWS_ * 1536];     // tiled QKV output
__device__ __align__(256) __half g_attn_h[ROWS_ * D_];      // tiled attn output
__device__ __align__(256) __half g_y_h  [ROWS_ * D_];       // tiled ln1 output
__device__ __align__(256) __half g_h_h  [ROWS_ * DFF_];     // tiled gelu output
__device__ __align__(256) __half g_enc_h[BC_ * KHEAD_];     // tiled head input
__device__ float  g_hpart[KSPLIT_ * BC_ * T_];
__device__ float  g_psum [256 * D_];
__device__ float  g_psq  [256 * D_];
__device__ float  g_bna  [D_];
__device__ float  g_bnb  [D_];
__device__ float  g_bqkv [NL_ * 1536];
// transposed half weights ([N,K] K-major, tiled layout)
__device__ __align__(256) __half g_wqkvT[NL_ * 1536 * D_];
__device__ __align__(256) __half g_woT  [NL_ * D_ * D_];
__device__ __align__(256) __half g_wc1T [NL_ * DFF_ * D_];
__device__ __align__(256) __half g_wc2T [NL_ * D_ * DFF_];
__device__ __align__(256) __half g_whT  [T_ * KHEAD_];

// ---------------- tiled-swizzled layout ----------------
__device__ __forceinline__ size_t tidx(int r, int k, int K) {
    int rr = r & 127;
    int kk = k & 31;
    int c  = ((kk >> 3) ^ ((rr >> 1) & 3));
    return (((size_t)(r >> 7) * (size_t)(K >> 5) + (size_t)(k >> 5)) << 12)
         + (size_t)(rr * 32 + c * 8 + (kk & 7));
}

// ---------------- helpers ----------------
#define LDSM4(r0, r1, r2, r3, addr) \
    asm volatile("ldmatrix.sync.aligned.m8n8.x4.shared.b16 {%0,%1,%2,%3}, [%4];" \
        : "=r"(r0), "=r"(r1), "=r"(r2), "=r"(r3) : "r"(addr))
#define LDSM4T(r0, r1, r2, r3, addr) \
    asm volatile("ldmatrix.sync.aligned.m8n8.x4.trans.shared.b16 {%0,%1,%2,%3}, [%4];" \
        : "=r"(r0), "=r"(r1), "=r"(r2), "=r"(r3) : "r"(addr))
#define HMMA(acc, a0, a1, a2, a3, b0, b1) \
    asm volatile("mma.sync.aligned.m16n8k16.row.col.f32.f16.f16.f32 " \
        "{%0,%1,%2,%3},{%4,%5,%6,%7},{%8,%9},{%0,%1,%2,%3};" \
        : "+f"((acc)[0]), "+f"((acc)[1]), "+f"((acc)[2]), "+f"((acc)[3]) \
        : "r"(a0), "r"(a1), "r"(a2), "r"(a3), "r"(b0), "r"(b1))

#define MBAR_INIT(addr, cnt) \
    asm volatile("mbarrier.init.shared.b64 [%0], %1;" :: "r"(addr), "r"(cnt) : "memory")
#define MBAR_EXPECT(addr, bytes) \
    asm volatile("mbarrier.arrive.expect_tx.shared.b64 _, [%0], %1;" :: "r"(addr), "r"(bytes) : "memory")
#define MBAR_ARRIVE(addr) \
    asm volatile("mbarrier.arrive.shared.b64 _, [%0];" :: "r"(addr) : "memory")
#define BULK_G2S(dst, src, bytes, bar) \
    asm volatile("cp.async.bulk.shared::cta.global.mbarrier::complete_tx::bytes [%0], [%1], %2, [%3];" \
        :: "r"(dst), "l"(src), "r"(bytes), "r"(bar) : "memory")
#define MBAR_WAIT(addr, par) do { \
    uint32_t _m = (addr), _p = (par), _d; \
    asm volatile("{\n\t.reg .pred p;\n\t" \
        "mbarrier.try_wait.parity.acquire.cta.shared::cta.b64 p, [%1], %2;\n\t" \
        "selp.b32 %0, 1, 0, p;\n\t}" : "=r"(_d) : "r"(_m), "r"(_p) : "memory"); \
    if (!_d) { \
        asm volatile("{\n\t.reg .pred P1;\n\t" \
            "WL_%=:\n\t" \
            "mbarrier.try_wait.parity.acquire.cta.shared::cta.b64 P1, [%0], %1, 0x989680;\n\t" \
            "@P1 bra.uni WD_%=;\n\t" \
            "bra.uni WL_%=;\n\t" \
            "WD_%=:\n\t}" :: "r"(_m), "r"(_p) : "memory"); \
    } \
} while (0)

__device__ __forceinline__ uint32_t smem_u32(const void* p) {
    uint32_t a;
    asm("{ .reg .u64 t; cvta.to.shared.u64 t, %1; cvt.u32.u64 %0, t; }" : "=r"(a) : "l"(p));
    return a;
}
__device__ __forceinline__ uint32_t h2pack(float x, float y) {
    __half2 h; h.x = __float2half_rn(x); h.y = __float2half_rn(y);
    return *(uint32_t*)&h;
}

// ---------------- Weight transpose -> half (tiled output), z = layer ----------------
__global__ void whtrans_kernel(const float* __restrict__ W, __half* __restrict__ WT,
                               int K, int Ncols) {
    __shared__ float s[32][33];
    int L = blockIdx.z;
    W  += (size_t)L * K * Ncols;
    WT += (size_t)L * K * Ncols;
    int n0 = blockIdx.x * 32, k0 = blockIdx.y * 32;
    int tx = threadIdx.x, ty = threadIdx.y;   // 32 x 8
    #pragma unroll
    for (int j = 0; j < 32; j += 8)
        s[ty + j][tx] = W[(size_t)(k0 + ty + j) * Ncols + n0 + tx];
    __syncthreads();
    #pragma unroll
    for (int j = 0; j < 32; j += 8)
        WT[tidx(n0 + ty + j, k0 + tx, K)] = __float2half_rn(s[tx][ty + j]);
}

// fused QKV weight transpose, ALL layers (z = layer*3 + m), + bias pack
__global__ void qkvtrans_kernel(const float* __restrict__ Wq, const float* __restrict__ Wk,
                                const float* __restrict__ Wv,
                                const float* __restrict__ bq, const float* __restrict__ bk,
                                const float* __restrict__ bv) {
    __shared__ float s[32][33];
    int L = blockIdx.z / 3, m = blockIdx.z % 3;
    const float* W = ((m == 0) ? Wq : (m == 1) ? Wk : Wv) + (size_t)L * D_ * D_;
    __half* WT = g_wqkvT + (size_t)L * 1536 * D_;
    int n0 = blockIdx.x * 32, k0 = blockIdx.y * 32;
    int tx = threadIdx.x, ty = threadIdx.y;   // 32 x 8
    #pragma unroll
    for (int j = 0; j < 32; j += 8)
        s[ty + j][tx] = W[(size_t)(k0 + ty + j) * D_ + n0 + tx];
    __syncthreads();
    #pragma unroll
    for (int j = 0; j < 32; j += 8)
        WT[tidx(m * 512 + n0 + ty + j, k0 + tx, D_)] = __float2half_rn(s[tx][ty + j]);
    if (m == 0 && blockIdx.x == 0 && blockIdx.y == 0) {
        int t = ty * 32 + tx;                // 0..255
        #pragma unroll
        for (int u = 0; u < 2; u++) {
            int d = t + u * 256;
            g_bqkv[L * 1536 + d]        = bq[L * D_ + d];
            g_bqkv[L * 1536 + 512 + d]  = bk[L * D_ + d];
            g_bqkv[L * 1536 + 1024 + d] = bv[L * D_ + d];
        }
    }
}

// ---------------- Instance-norm stats + PE table (blocks 0..63 fill PE row) ----------------
__global__ void inst_stats_kernel(const float* __restrict__ x_enc) {
    int bc = blockIdx.x;
    int b = bc >> 5, c = bc & 31;
    int tid = threadIdx.x;          // 256
    const float* p = x_enc + (size_t)b * T_ * C_ + c;
    float v0 = p[(size_t)tid * C_];
    float v1 = p[(size_t)(tid + 256) * C_];
    __shared__ float rs[256], rq[256];
    rs[tid] = v0 + v1; rq[tid] = v0 * v0 + v1 * v1;
    __syncthreads();
    for (int off = 128; off > 0; off >>= 1) {
        if (tid < off) { rs[tid] += rs[tid + off]; rq[tid] += rq[tid + off]; }
        __syncthreads();
    }
    if (tid == 0) {
        float mean = rs[0] / (float)T_;
        float var  = rq[0] / (float)T_ - mean * mean;
        g_mean[bc] = mean;
        g_std[bc]  = sqrtf(var + 1e-5f);
    }
    if (bc < N_) {
        #pragma unroll
        for (int u = 0; u < 2; u++) {
            int d = tid + u * 256;
            int i2 = d >> 1;
            float div = expf(-(float)(2 * i2) * (logf(10000.0f) / (float)D_));
            float ang = (float)bc * div;
            g_pe[bc * D_ + d] = (d & 1) ? cosf(ang) : sinf(ang);
        }
    }
}

// ---------------- Patch embedding: one block per sequence (bc) ----------------
__global__ void patch_embed_kernel(const float* __restrict__ x_enc,
                                   const float* __restrict__ W_val) {
    int bc = blockIdx.x;            // 1024
    int b = bc >> 5, c = bc & 31;
    int d = threadIdx.x;            // 512
    __shared__ float xv[T_ + PAD_];
    float mean = g_mean[bc], istd = 1.0f / g_std[bc];
    xv[d] = (x_enc[(size_t)(b * T_ + d) * C_ + c] - mean) * istd;
    __syncthreads();
    if (d < PAD_) xv[T_ + d] = xv[T_ - 1];
    __syncthreads();

    float w[P_];
    #pragma unroll
    for (int p = 0; p < P_; p++) w[p] = W_val[p * D_ + d];

    for (int n = 0; n < N_; n++) {
        float acc = g_pe[n * D_ + d];
        const float* pv = &xv[n * 8];
        #pragma unroll
        for (int p = 0; p < P_; p++)
            acc = fmaf(pv[p], w[p], acc);
        int bn = bc * 64 + n;
        g_tok  [(size_t)bn * D_ + d] = acc;
        g_tok_h[tidx(bn, d, D_)]     = __float2half_rn(acc);
    }
}

// ---------------- FP16 mma GEMM: TMA-bulk staged, 128x128x64 tiles ----------------
// producer/consumer mbarrier pipeline (no __syncthreads in main loop):
//   full[s] (arrive 1, TMA tx)  at sbase + s*8
//   empty[s] (arrive 8 warps)   at sbase + 24 + s*8
#define NSTG   3
#define STG_B  32768
#define HG_SMEM (64 + NSTG * STG_B)     // 98368 bytes

template<int EPI>
__global__ __launch_bounds__(256, 2)
void hgemm_kernel(const __half* __restrict__ A, const __half* __restrict__ BT,
                  const float* __restrict__ bias, const float* __restrict__ res,
                  void* __restrict__ Cv, int M, int N, int K, int lda, int ldb) {
    extern __shared__ __half smh[];
    const uint32_t sbase = smem_u32(smh);
    const uint32_t stg0  = sbase + 64;

    int koff = 0;
    if (EPI == 4) koff = blockIdx.z * KCH_;

    const int tid  = threadIdx.x;
    const int warp = tid >> 5, lane = tid & 31;
    const int wm = warp >> 1, wn = warp & 1;       // 4x2 warps, 32x64 warp tile
    const int lr = lane >> 2, lc = lane & 3;
    const int bm = blockIdx.y * 128, bn = blockIdx.x * 128;
    const size_t aBlkRow = (size_t)(bm >> 7) * (size_t)(lda >> 5);
    const size_t bBlkRow = (size_t)(bn >> 7) * (size_t)(ldb >> 5);

    if (tid < NSTG) MBAR_INIT(sbase + tid * 8, 1);
    else if (tid < 2 * NSTG) MBAR_INIT(sbase + 24 + (tid - NSTG) * 8, 8);
    __syncthreads();

    float acc[2][8][4];
    #pragma unroll
    for (int mt = 0; mt < 2; mt++)
        #pragma unroll
        for (int nt = 0; nt < 8; nt++)
            #pragma unroll
            for (int i = 0; i < 4; i++) acc[mt][nt][i] = 0.0f;

    uint32_t aQ[2]; int aS[2];
    #pragma unroll
    for (int mt = 0; mt < 2; mt++) {
        int rr = wm * 32 + mt * 16 + (lane & 15);
        aQ[mt] = (uint32_t)(rr * 64);
        aS[mt] = (rr >> 1) & 3;
    }
    uint32_t bQ[4]; int bS[4];
    #pragma unroll
    for (int ng = 0; ng < 4; ng++) {
        int rr = wn * 64 + ng * 16 + (lane & 15);
        bQ[ng] = (uint32_t)(16384 + rr * 64);
        bS[ng] = (rr >> 1) & 3;
    }
    const int hs = lane >> 4;

    const int NIT = K >> 6;      // 64-K chunks

    auto FILL = [&](int s, int k0, int fn) {
        if (tid == 0) {
            if (fn >= NSTG) MBAR_WAIT(sbase + 24 + s * 8, (fn / 3 + 1) & 1);
            uint32_t bar = sbase + s * 8;
            MBAR_EXPECT(bar, 32768);
            const __half* sa = A  + ((aBlkRow + (size_t)((koff + k0) >> 5)) << 12);
            const __half* sb = BT + ((bBlkRow + (size_t)((koff + k0) >> 5)) << 12);
            uint32_t st = stg0 + s * STG_B;
            BULK_G2S(st,         sa, 16384, bar);
            BULK_G2S(st + 16384, sb, 16384, bar);
        }
    };

    FILL(0, 0, 0); FILL(1, 64, 1);

    for (int it = 0; it < NIT; ++it) {
        const int s = it % 3;
        MBAR_WAIT(sbase + s * 8, (it / 3) & 1);

        const uint32_t st = stg0 + s * STG_B;
        #pragma unroll
        for (int ks = 0; ks < 4; ks++) {
            const uint32_t kblk = st + (uint32_t)((ks >> 1) * 8192);
            const int ksl = ks & 1;
            uint32_t af[2][4];
            #pragma unroll
            for (int mt = 0; mt < 2; mt++)
                LDSM4(af[mt][0], af[mt][1], af[mt][2], af[mt][3],
                      kblk + aQ[mt] + (uint32_t)((((ksl << 1) | hs) ^ aS[mt]) << 4));
            uint32_t bq[4][4];
            #pragma unroll
            for (int ng = 0; ng < 4; ng++)
                LDSM4(bq[ng][0], bq[ng][1], bq[ng][2], bq[ng][3],
                      kblk + bQ[ng] + (uint32_t)((((ksl << 1) | hs) ^ bS[ng]) << 4));
            #pragma unroll
            for (int mt = 0; mt < 2; mt++)
                #pragma unroll
                for (int nt = 0; nt < 8; nt++)
                    HMMA(acc[mt][nt], af[mt][0], af[mt][1], af[mt][2], af[mt][3],
                         bq[nt >> 1][nt & 1], bq[nt >> 1][(nt & 1) + 2]);
        }
        if (lane == 0) MBAR_ARRIVE(sbase + 24 + s * 8);   // warp done with stage s
        if (it + 2 < NIT) FILL((it + 2) % 3, (it + 2) << 6, it + 2);
    }

    // ---------------- epilogue ----------------
    float* Cf = (float*)Cv;
    __half* Ch = (__half*)Cv;
    if (EPI == 4) Cf += (size_t)blockIdx.z * M * N;

    #pragma unroll
    for (int mt = 0; mt < 2; mt++) {
        #pragma unroll
        for (int half = 0; half < 2; half++) {
            int m = bm + wm * 32 + mt * 16 + lr + half * 8;
            #pragma unroll
            for (int nt = 0; nt < 8; nt++) {
                int col = bn + wn * 64 + nt * 8 + lc * 2;
                float v0 = acc[mt][nt][half * 2 + 0];
                float v1 = acc[mt][nt][half * 2 + 1];
                if (EPI != 4) { v0 += bias[col]; v1 += bias[col + 1]; }
                if (EPI == 1) {
                    const float2 r2 = *(const float2*)(res + (size_t)m * N + col);
                    v0 += r2.x; v1 += r2.y;
                }
                if (EPI == 2) {
                    v0 = 0.5f * v0 * (1.0f + erff(v0 * 0.70710678118654752f));
                    v1 = 0.5f * v1 * (1.0f + erff(v1 * 0.70710678118654752f));
                }
                if (EPI == 0 || EPI == 2) {
                    __half2 hv;
                    hv.x = __float2half_rn(v0); hv.y = __float2half_rn(v1);
                    *(__half2*)(Ch + tidx(m, col, N)) = hv;
                } else {
                    *(float2*)(Cf + (size_t)m * N + col) = make_float2(v0, v1);
                }
            }
        }
    }
}

// ---------------- Attention: tensor-core (per bc,h block; 4 warps) ----------------
#define ATTN_SMEM 24576
__global__ __launch_bounds__(128)
void attn_kernel() {
    int bh = blockIdx.x;
    int bc = bh >> 3, h = bh & 7;
    extern __shared__ __half smA[];
    const uint32_t sb = smem_u32(smA);
    const int tid = threadIdx.x, warp = tid >> 5, lane = tid & 31;
    const int kq = h * 64, kk0 = 512 + h * 64, kv0 = 1024 + h * 64;

    #pragma unroll
    for (int j = 0; j < 4; j++) {
        int q = tid + j * 128;          // 0..511
        int r = q >> 3, c = q & 7;
        uint32_t doff = (uint32_t)(r * 128 + ((c ^ (r & 7)) << 4));
        int R = bc * 64 + r;
        *(uint4*)((char*)smA + doff)         = *(const uint4*)(g_qkv_h + tidx(R, kq  + c * 8, 1536));
        *(uint4*)((char*)smA + 8192 + doff)  = *(const uint4*)(g_qkv_h + tidx(R, kk0 + c * 8, 1536));
        *(uint4*)((char*)smA + 16384 + doff) = *(const uint4*)(g_qkv_h + tidx(R, kv0 + c * 8, 1536));
    }
    __syncthreads();

    const int rlo = lane & 15, hs = lane >> 4;

    float sacc[8][4];
    #pragma unroll
    for (int nt = 0; nt < 8; nt++)
        #pragma unroll
        for (int i = 0; i < 4; i++) sacc[nt][i] = 0.0f;

    #pragma unroll
    for (int ks = 0; ks < 4; ks++) {
        int cc = ks * 2 + hs;
        uint32_t a0, a1, a2, a3;
        {
            int r = warp * 16 + rlo;
            LDSM4(a0, a1, a2, a3, sb + (uint32_t)(r * 128 + ((cc ^ (r & 7)) << 4)));
        }
        #pragma unroll
        for (int ng = 0; ng < 4; ng++) {
            int r = ng * 16 + rlo;
            uint32_t b0, b1, b2, b3;
            LDSM4(b0, b1, b2, b3, sb + 8192 + (uint32_t)(r * 128 + ((cc ^ (r & 7)) << 4)));
            HMMA(sacc[2 * ng],     a0, a1, a2, a3, b0, b2);
            HMMA(sacc[2 * ng + 1], a0, a1, a2, a3, b1, b3);
        }
    }

    float mx0 = -1e30f, mx1 = -1e30f;
    #pragma unroll
    for (int nt = 0; nt < 8; nt++) {
        #pragma unroll
        for (int i = 0; i < 4; i++) sacc[nt][i] *= 0.125f;
        mx0 = fmaxf(mx0, fmaxf(sacc[nt][0], sacc[nt][1]));
        mx1 = fmaxf(mx1, fmaxf(sacc[nt][2], sacc[nt][3]));
    }
    mx0 = fmaxf(mx0, __shfl_xor_sync(0xffffffffu, mx0, 1));
    mx0 = fmaxf(mx0, __shfl_xor_sync(0xffffffffu, mx0, 2));
    mx1 = fmaxf(mx1, __shfl_xor_sync(0xffffffffu, mx1, 1));
    mx1 = fmaxf(mx1, __shfl_xor_sync(0xffffffffu, mx1, 2));
    float s0 = 0.0f, s1 = 0.0f;
    #pragma unroll
    for (int nt = 0; nt < 8; nt++) {
        sacc[nt][0] = expf(sacc[nt][0] - mx0); s0 += sacc[nt][0];
        sacc[nt][1] = expf(sacc[nt][1] - mx0); s0 += sacc[nt][1];
        sacc[nt][2] = expf(sacc[nt][2] - mx1); s1 += sacc[nt][2];
        sacc[nt][3] = expf(sacc[nt][3] - mx1); s1 += sacc[nt][3];
    }
    s0 += __shfl_xor_sync(0xffffffffu, s0, 1);
    s0 += __shfl_xor_sync(0xffffffffu, s0, 2);
    s1 += __shfl_xor_sync(0xffffffffu, s1, 1);
    s1 += __shfl_xor_sync(0xffffffffu, s1, 2);
    float i0 = 1.0f / s0, i1 = 1.0f / s1;
    #pragma unroll
    for (int nt = 0; nt < 8; nt++) {
        sacc[nt][0] *= i0; sacc[nt][1] *= i0;
        sacc[nt][2] *= i1; sacc[nt][3] *= i1;
    }

    uint32_t pa[4][4];
    #pragma unroll
    for (int ks = 0; ks < 4; ks++) {
        pa[ks][0] = h2pack(sacc[2 * ks][0],     sacc[2 * ks][1]);
        pa[ks][1] = h2pack(sacc[2 * ks][2],     sacc[2 * ks][3]);
        pa[ks][2] = h2pack(sacc[2 * ks + 1][0], sacc[2 * ks + 1][1]);
        pa[ks][3] = h2pack(sacc[2 * ks + 1][2], sacc[2 * ks + 1][3]);
    }

    float oacc[8][4];
    #pragma unroll
    for (int nt = 0; nt < 8; nt++)
        #pragma unroll
        for (int i = 0; i < 4; i++) oacc[nt][i] = 0.0f;

    #pragma unroll
    for (int ks = 0; ks < 4; ks++) {
        #pragma unroll
        for (int et = 0; et < 4; et++) {
            int r = ks * 16 + rlo;
            int cc = et * 2 + hs;
            uint32_t v0, v1, v2, v3;
            LDSM4T(v0, v1, v2, v3, sb + 16384 + (uint32_t)(r * 128 + ((cc ^ (r & 7)) << 4)));
            HMMA(oacc[2 * et],     pa[ks][0], pa[ks][1], pa[ks][2], pa[ks][3], v0, v1);
            HMMA(oacc[2 * et + 1], pa[ks][0], pa[ks][1], pa[ks][2], pa[ks][3], v2, v3);
        }
    }

    int r0w = bc * 64 + warp * 16 + (lane >> 2);
    #pragma unroll
    for (int nt = 0; nt < 8; nt++) {
        int col = h * 64 + nt * 8 + (lane & 3) * 2;
        uint32_t p0 = h2pack(oacc[nt][0], oacc[nt][1]);
        uint32_t p1 = h2pack(oacc[nt][2], oacc[nt][3]);
        *(uint32_t*)(g_attn_h + tidx(r0w,     col, D_)) = p0;
        *(uint32_t*)(g_attn_h + tidx(r0w + 8, col, D_)) = p1;
    }
}

// ---------------- LayerNorm: warp-per-row (8 rows/block) ----------------
__global__ void ln_kernel(const float* __restrict__ X,
                          const float* __restrict__ g, const float* __restrict__ b,
                          float* __restrict__ Yf, __half* __restrict__ Yh) {
    int warp = threadIdx.x >> 5, lane = threadIdx.x & 31;
    int row = blockIdx.x * 8 + warp;
    const float* x = X + (size_t)row * D_;
    float v[16];
    float s = 0.0f, q = 0.0f;
    #pragma unroll
    for (int j = 0; j < 4; j++) {
        float4 f = *(const float4*)(x + lane * 4 + j * 128);
        v[j * 4 + 0] = f.x; v[j * 4 + 1] = f.y; v[j * 4 + 2] = f.z; v[j * 4 + 3] = f.w;
        s += f.x + f.y + f.z + f.w;
        q += f.x * f.x + f.y * f.y + f.z * f.z + f.w * f.w;
    }
    #pragma unroll
    for (int o = 16; o > 0; o >>= 1) {
        s += __shfl_xor_sync(0xffffffffu, s, o);
        q += __shfl_xor_sync(0xffffffffu, q, o);
    }
    float mean = s / (float)D_;
    float inv  = rsqrtf(q / (float)D_ - mean * mean + 1e-5f);
    #pragma unroll
    for (int j = 0; j < 4; j++) {
        int c = lane * 4 + j * 128;
        float4 gg = *(const float4*)(g + c);
        float4 bb = *(const float4*)(b + c);
        float o0 = (v[j * 4 + 0] - mean) * inv * gg.x + bb.x;
        float o1 = (v[j * 4 + 1] - mean) * inv * gg.y + bb.y;
        float o2 = (v[j * 4 + 2] - mean) * inv * gg.z + bb.z;
        float o3 = (v[j * 4 + 3] - mean) * inv * gg.w + bb.w;
        if (Yf) *(float4*)(Yf + (size_t)row * D_ + c) = make_float4(o0, o1, o2, o3);
        uint32_t lo = h2pack(o0, o1), hi = h2pack(o2, o3);
        *(uint2*)(Yh + tidx(row, c, D_)) = make_uint2(lo, hi);
    }
}

// ---------------- BatchNorm stats (deterministic 2-stage) ----------------
__global__ void bn_partial_kernel() {
    int blk = blockIdx.x;
    int d = threadIdx.x;      // 512
    float s = 0.0f, q = 0.0f;
    const float* base = g_tok + (size_t)blk * 256 * D_ + d;
    for (int r = 0; r < 256; r++) {
        float v = base[(size_t)r * D_];
        s += v; q += v * v;
    }
    g_psum[blk * D_ + d] = s;
    g_psq [blk * D_ + d] = q;
}

__global__ void bn_final_kernel(const float* __restrict__ gam,
                                const float* __restrict__ bet) {
    int d = threadIdx.x;      // 512, one block
    float s = 0.0f, q = 0.0f;
    for (int i = 0; i < 256; i++) {
        s += g_psum[i * D_ + d];
        q += g_psq [i * D_ + d];
    }
    float mean = s / (float)ROWS_;
    float var  = q / (float)ROWS_ - mean * mean;
    float a = gam[d] * rsqrtf(var + 1e-5f);
    g_bna[d] = a;
    g_bnb[d] = bet[d] - mean * a;
}

// ---------------- BN apply + (N,D)->(D,N) transpose into enc (tiled half) ----------------
__global__ void enc_transpose_kernel() {
    __shared__ float sm[32][33];
    int bid = blockIdx.x;
    int bc = bid >> 5;
    int r = bid & 31;
    int dt = r >> 1, nt = r & 1;
    int tx = threadIdx.x, ty = threadIdx.y;   // 32 x 8
    int d0 = dt * 32, n0 = nt * 32;
    #pragma unroll
    for (int j = 0; j < 32; j += 8) {
        int n = n0 + ty + j;
        int d = d0 + tx;
        float v = g_tok[((size_t)bc * 64 + n) * D_ + d];
        sm[ty + j][tx] = v * g_bna[d] + g_bnb[d];
    }
    __syncthreads();
    #pragma unroll
    for (int j = 0; j < 32; j += 8) {
        int d = d0 + ty + j;
        int n = n0 + tx;
        g_enc_h[tidx(bc, d * N_ + n, KHEAD_)] = __float2half_rn(sm[tx][ty + j]);
    }
}

// ---------------- head final: sum split-K partials + bias + denorm ----------------
__global__ void head_final_kernel(const float* __restrict__ b_head,
                                  float* __restrict__ out) {
    int m = blockIdx.x;        // bc
    int t = threadIdx.x;       // 512
    float v = b_head[t];
    #pragma unroll
    for (int z = 0; z < KSPLIT_; z++)
        v += g_hpart[((size_t)z * BC_ + m) * T_ + t];
    int b = m >> 5, c = m & 31;
    out[((size_t)b * T_ + t) * C_ + c] = v * g_std[m] + g_mean[m];
}

// ---------------- Launch ----------------
extern "C" void kernel_launch(void* const* d_in, const int* in_sizes, int n_in,
                              void* d_out, int out_size) {
    const float* x_enc = (const float*)d_in[0];
    const float* W_val = (const float*)d_in[1];
    const float* Wq    = (const float*)d_in[2];
    const float* bq    = (const float*)d_in[3];
    const float* Wk    = (const float*)d_in[4];
    const float* bk    = (const float*)d_in[5];
    const float* Wv    = (const float*)d_in[6];
    const float* bv    = (const float*)d_in[7];
    const float* Wo    = (const float*)d_in[8];
    const float* bo    = (const float*)d_in[9];
    const float* Wc1   = (const float*)d_in[10];
    const float* bc1   = (const float*)d_in[11];
    const float* Wc2   = (const float*)d_in[12];
    const float* bc2   = (const float*)d_in[13];
    const float* ln1_g = (const float*)d_in[14];
    const float* ln1_b = (const float*)d_in[15];
    const float* ln2_g = (const float*)d_in[16];
    const float* ln2_b = (const float*)d_in[17];
    const float* bn_g  = (const float*)d_in[18];
    const float* bn_b  = (const float*)d_in[19];
    const float* W_head= (const float*)d_in[20];
    const float* b_head= (const float*)d_in[21];
    float* out = (float*)d_out;

    float *tok, *hpart, *bqkv_p;
    __half *tok_h, *qkv_h, *attn_h, *y_h, *h_h, *enc_h;
    __half *wqkvT, *woT, *wc1T, *wc2T, *whT;
    cudaGetSymbolAddress((void**)&tok,    g_tok);
    cudaGetSymbolAddress((void**)&tok_h,  g_tok_h);
    cudaGetSymbolAddress((void**)&qkv_h,  g_qkv_h);
    cudaGetSymbolAddress((void**)&attn_h, g_attn_h);
    cudaGetSymbolAddress((void**)&y_h,    g_y_h);
    cudaGetSymbolAddress((void**)&h_h,    g_h_h);
    cudaGetSymbolAddress((void**)&enc_h,  g_enc_h);
    cudaGetSymbolAddress((void**)&hpart,  g_hpart);
    cudaGetSymbolAddress((void**)&bqkv_p, g_bqkv);
    cudaGetSymbolAddress((void**)&wqkvT,  g_wqkvT);
    cudaGetSymbolAddress((void**)&woT,    g_woT);
    cudaGetSymbolAddress((void**)&wc1T,   g_wc1T);
    cudaGetSymbolAddress((void**)&wc2T,   g_wc2T);
    cudaGetSymbolAddress((void**)&whT,    g_whT);

    cudaFuncSetAttribute(attn_kernel, cudaFuncAttributeMaxDynamicSharedMemorySize, ATTN_SMEM);
    cudaFuncSetAttribute(hgemm_kernel<0>, cudaFuncAttributeMaxDynamicSharedMemorySize, HG_SMEM);
    cudaFuncSetAttribute(hgemm_kernel<1>, cudaFuncAttributeMaxDynamicSharedMemorySize, HG_SMEM);
    cudaFuncSetAttribute(hgemm_kernel<2>, cudaFuncAttributeMaxDynamicSharedMemorySize, HG_SMEM);
    cudaFuncSetAttribute(hgemm_kernel<4>, cudaFuncAttributeMaxDynamicSharedMemorySize, HG_SMEM);

    dim3 tb32(32, 8);
    dim3 gqkv(1536 / 128, ROWS_ / 128);       // (12, 512)
    dim3 gproj(D_ / 128, ROWS_ / 128);        // (4, 512)
    dim3 gff1(DFF_ / 128, ROWS_ / 128);       // (16, 512)
    dim3 ghead(T_ / 128, BC_ / 128, KSPLIT_); // (4, 8, 8)

    inst_stats_kernel<<<BC_, 256>>>(x_enc);                                       // 1 (+PE)
    patch_embed_kernel<<<BC_, 512>>>(x_enc, W_val);                               // 2
    qkvtrans_kernel<<<dim3(16, 16, 9), tb32>>>(Wq, Wk, Wv, bq, bk, bv);           // 3

    for (int i = 0; i < NL_; i++) {
        hgemm_kernel<0><<<gqkv, 256, HG_SMEM>>>(tok_h, wqkvT + (size_t)i * 1536 * D_,
            bqkv_p + i * 1536, nullptr, qkv_h, ROWS_, 1536, D_, D_, D_);          // #4 for i=0
        if (i == 0) {
            whtrans_kernel<<<dim3(16, 16, 3), tb32>>>(Wo,  woT,  D_, D_);
            whtrans_kernel<<<dim3(64, 16, 3), tb32>>>(Wc1, wc1T, D_, DFF_);
            whtrans_kernel<<<dim3(16, 64, 3), tb32>>>(Wc2, wc2T, DFF_, D_);
        }
        attn_kernel<<<BC_ * H_, 128, ATTN_SMEM>>>();
        hgemm_kernel<1><<<gproj, 256, HG_SMEM>>>(attn_h, woT + (size_t)i * D_ * D_,
            bo + i * D_, tok, tok, ROWS_, D_, D_, D_, D_);
        ln_kernel<<<ROWS_ / 8, 256>>>(tok, ln1_g + i * D_, ln1_b + i * D_, nullptr, y_h);
        hgemm_kernel<2><<<gff1, 256, HG_SMEM>>>(y_h, wc1T + (size_t)i * DFF_ * D_,
            bc1 + i * DFF_, nullptr, h_h, ROWS_, DFF_, D_, D_, D_);
        hgemm_kernel<1><<<gproj, 256, HG_SMEM>>>(h_h, wc2T + (size_t)i * D_ * DFF_,
            bc2 + i * D_, tok, tok, ROWS_, D_, DFF_, DFF_, DFF_);
        ln_kernel<<<ROWS_ / 8, 256>>>(tok, ln2_g + i * D_, ln2_b + i * D_, tok, tok_h);
    }

    whtrans_kernel<<<dim3(16, 1024, 1), tb32>>>(W_head, whT, KHEAD_, T_);
    bn_partial_kernel<<<256, 512>>>();
    bn_final_kernel<<<1, 512>>>(bn_g, bn_b);
    enc_transpose_kernel<<<BC_ * 32, dim3(32, 8)>>>();
    hgemm_kernel<4><<<ghead, 256, HG_SMEM>>>(enc_h, whT, nullptr, nullptr, hpart,
                                             BC_, T_, KCH_, KHEAD_, KHEAD_);
    head_final_kernel<<<BC_, T_>>>(b_head, out);
}

// round 14
// speedup vs baseline: 2.4147x; 1.0382x over previous
#include <cuda_runtime.h>
#include <cuda_fp16.h>
#include <math.h>
#include <stdint.h>

// ---------------- Problem constants ----------------
#define B_    32
#define T_    512
#define C_    32
#define D_    512
#define H_    8
#define E_    64
#define DFF_  2048
#define NL_   3
#define P_    16
#define N_    64
#define PAD_  8
#define BC_   (B_*C_)          // 1024
#define ROWS_ ((BC_)*(N_))     // 65536
#define KSPLIT_ 8
#define KCH_    4096           // 32768 / 8
#define KHEAD_  (D_*N_)        // 32768

// ---------------- Scratch (device globals; no allocation) ----------------
__device__ float  g_mean[BC_];
__device__ float  g_std[BC_];
__device__ float  g_pe  [N_ * D_];
__device__ float  g_tok  [ROWS_ * D_];                      // fp32 residual stream
__device__ __align__(256) __half g_tok_h[ROWS_ * D_];       // tiled half (QKV input)
__device__ __align__(256) __half g_qkv_h[ROWS_ * 1536];     // tiled QKV output
__device__ __align__(256) __half g_attn_h[ROWS_ * D_];      // tiled attn output
__device__ __align__(256) __half g_y_h  [ROWS_ * D_];       // tiled ln1 output
__device__ __align__(256) __half g_h_h  [ROWS_ * DFF_];     // tiled gelu output
__device__ __align__(256) __half g_enc_h[BC_ * KHEAD_];     // tiled head input
__device__ float  g_hpart[KSPLIT_ * BC_ * T_];
__device__ float  g_psum [256 * D_];
__device__ float  g_psq  [256 * D_];
__device__ float  g_bna  [D_];
__device__ float  g_bnb  [D_];
__device__ float  g_bqkv [NL_ * 1536];
// transposed half weights ([N,K] K-major, tiled layout)
__device__ __align__(256) __half g_wqkvT[NL_ * 1536 * D_];
__device__ __align__(256) __half g_woT  [NL_ * D_ * D_];
__device__ __align__(256) __half g_wc1T [NL_ * DFF_ * D_];
__device__ __align__(256) __half g_wc2T [NL_ * D_ * DFF_];
__device__ __align__(256) __half g_whT  [T_ * KHEAD_];

// ---------------- tiled-swizzled layout ----------------
__device__ __forceinline__ size_t tidx(int r, int k, int K) {
    int rr = r & 127;
    int kk = k & 31;
    int c  = ((kk >> 3) ^ ((rr >> 1) & 3));
    return (((size_t)(r >> 7) * (size_t)(K >> 5) + (size_t)(k >> 5)) << 12)
         + (size_t)(rr * 32 + c * 8 + (kk & 7));
}

// ---------------- helpers ----------------
#define LDSM4(r0, r1, r2, r3, addr) \
    asm volatile("ldmatrix.sync.aligned.m8n8.x4.shared.b16 {%0,%1,%2,%3}, [%4];" \
        : "=r"(r0), "=r"(r1), "=r"(r2), "=r"(r3) : "r"(addr))
#define LDSM4T(r0, r1, r2, r3, addr) \
    asm volatile("ldmatrix.sync.aligned.m8n8.x4.trans.shared.b16 {%0,%1,%2,%3}, [%4];" \
        : "=r"(r0), "=r"(r1), "=r"(r2), "=r"(r3) : "r"(addr))
#define HMMA(acc, a0, a1, a2, a3, b0, b1) \
    asm volatile("mma.sync.aligned.m16n8k16.row.col.f32.f16.f16.f32 " \
        "{%0,%1,%2,%3},{%4,%5,%6,%7},{%8,%9},{%0,%1,%2,%3};" \
        : "+f"((acc)[0]), "+f"((acc)[1]), "+f"((acc)[2]), "+f"((acc)[3]) \
        : "r"(a0), "r"(a1), "r"(a2), "r"(a3), "r"(b0), "r"(b1))

#define MBAR_INIT(addr, cnt) \
    asm volatile("mbarrier.init.shared.b64 [%0], %1;" :: "r"(addr), "r"(cnt) : "memory")
#define MBAR_EXPECT(addr, bytes) \
    asm volatile("mbarrier.arrive.expect_tx.shared.b64 _, [%0], %1;" :: "r"(addr), "r"(bytes) : "memory")
#define MBAR_ARRIVE(addr) \
    asm volatile("mbarrier.arrive.shared.b64 _, [%0];" :: "r"(addr) : "memory")
#define BULK_G2S(dst, src, bytes, bar) \
    asm volatile("cp.async.bulk.shared::cta.global.mbarrier::complete_tx::bytes [%0], [%1], %2, [%3];" \
        :: "r"(dst), "l"(src), "r"(bytes), "r"(bar) : "memory")
#define MBAR_WAIT(addr, par) do { \
    uint32_t _m = (addr), _p = (par), _d; \
    asm volatile("{\n\t.reg .pred p;\n\t" \
        "mbarrier.try_wait.parity.acquire.cta.shared::cta.b64 p, [%1], %2;\n\t" \
        "selp.b32 %0, 1, 0, p;\n\t}" : "=r"(_d) : "r"(_m), "r"(_p) : "memory"); \
    if (!_d) { \
        asm volatile("{\n\t.reg .pred P1;\n\t" \
            "WL_%=:\n\t" \
            "mbarrier.try_wait.parity.acquire.cta.shared::cta.b64 P1, [%0], %1, 0x989680;\n\t" \
            "@P1 bra.uni WD_%=;\n\t" \
            "bra.uni WL_%=;\n\t" \
            "WD_%=:\n\t}" :: "r"(_m), "r"(_p) : "memory"); \
    } \
} while (0)

__device__ __forceinline__ uint32_t smem_u32(const void* p) {
    uint32_t a;
    asm("{ .reg .u64 t; cvta.to.shared.u64 t, %1; cvt.u32.u64 %0, t; }" : "=r"(a) : "l"(p));
    return a;
}
__device__ __forceinline__ uint32_t h2pack(float x, float y) {
    __half2 h; h.x = __float2half_rn(x); h.y = __float2half_rn(y);
    return *(uint32_t*)&h;
}

// ---------------- Weight transpose -> half (tiled output), z = layer ----------------
__global__ void whtrans_kernel(const float* __restrict__ W, __half* __restrict__ WT,
                               int K, int Ncols) {
    __shared__ float s[32][33];
    int L = blockIdx.z;
    W  += (size_t)L * K * Ncols;
    WT += (size_t)L * K * Ncols;
    int n0 = blockIdx.x * 32, k0 = blockIdx.y * 32;
    int tx = threadIdx.x, ty = threadIdx.y;   // 32 x 8
    #pragma unroll
    for (int j = 0; j < 32; j += 8)
        s[ty + j][tx] = W[(size_t)(k0 + ty + j) * Ncols + n0 + tx];
    __syncthreads();
    #pragma unroll
    for (int j = 0; j < 32; j += 8)
        WT[tidx(n0 + ty + j, k0 + tx, K)] = __float2half_rn(s[tx][ty + j]);
}

// fused QKV weight transpose, ALL layers (z = layer*3 + m), + bias pack
__global__ void qkvtrans_kernel(const float* __restrict__ Wq, const float* __restrict__ Wk,
                                const float* __restrict__ Wv,
                                const float* __restrict__ bq, const float* __restrict__ bk,
                                const float* __restrict__ bv) {
    __shared__ float s[32][33];
    int L = blockIdx.z / 3, m = blockIdx.z % 3;
    const float* W = ((m == 0) ? Wq : (m == 1) ? Wk : Wv) + (size_t)L * D_ * D_;
    __half* WT = g_wqkvT + (size_t)L * 1536 * D_;
    int n0 = blockIdx.x * 32, k0 = blockIdx.y * 32;
    int tx = threadIdx.x, ty = threadIdx.y;   // 32 x 8
    #pragma unroll
    for (int j = 0; j < 32; j += 8)
        s[ty + j][tx] = W[(size_t)(k0 + ty + j) * D_ + n0 + tx];
    __syncthreads();
    #pragma unroll
    for (int j = 0; j < 32; j += 8)
        WT[tidx(m * 512 + n0 + ty + j, k0 + tx, D_)] = __float2half_rn(s[tx][ty + j]);
    if (m == 0 && blockIdx.x == 0 && blockIdx.y == 0) {
        int t = ty * 32 + tx;                // 0..255
        #pragma unroll
        for (int u = 0; u < 2; u++) {
            int d = t + u * 256;
            g_bqkv[L * 1536 + d]        = bq[L * D_ + d];
            g_bqkv[L * 1536 + 512 + d]  = bk[L * D_ + d];
            g_bqkv[L * 1536 + 1024 + d] = bv[L * D_ + d];
        }
    }
}

// ---------------- Instance-norm stats + PE table (blocks 0..63 fill PE row) ----------------
__global__ void inst_stats_kernel(const float* __restrict__ x_enc) {
    int bc = blockIdx.x;
    int b = bc >> 5, c = bc & 31;
    int tid = threadIdx.x;          // 256
    const float* p = x_enc + (size_t)b * T_ * C_ + c;
    float v0 = p[(size_t)tid * C_];
    float v1 = p[(size_t)(tid + 256) * C_];
    __shared__ float rs[256], rq[256];
    rs[tid] = v0 + v1; rq[tid] = v0 * v0 + v1 * v1;
    __syncthreads();
    for (int off = 128; off > 0; off >>= 1) {
        if (tid < off) { rs[tid] += rs[tid + off]; rq[tid] += rq[tid + off]; }
        __syncthreads();
    }
    if (tid == 0) {
        float mean = rs[0] / (float)T_;
        float var  = rq[0] / (float)T_ - mean * mean;
        g_mean[bc] = mean;
        g_std[bc]  = sqrtf(var + 1e-5f);
    }
    if (bc < N_) {
        #pragma unroll
        for (int u = 0; u < 2; u++) {
            int d = tid + u * 256;
            int i2 = d >> 1;
            float div = expf(-(float)(2 * i2) * (logf(10000.0f) / (float)D_));
            float ang = (float)bc * div;
            g_pe[bc * D_ + d] = (d & 1) ? cosf(ang) : sinf(ang);
        }
    }
}

// ---------------- Patch embedding: one block per sequence (bc) ----------------
__global__ void patch_embed_kernel(const float* __restrict__ x_enc,
                                   const float* __restrict__ W_val) {
    int bc = blockIdx.x;            // 1024
    int b = bc >> 5, c = bc & 31;
    int d = threadIdx.x;            // 512
    __shared__ float xv[T_ + PAD_];
    float mean = g_mean[bc], istd = 1.0f / g_std[bc];
    xv[d] = (x_enc[(size_t)(b * T_ + d) * C_ + c] - mean) * istd;
    __syncthreads();
    if (d < PAD_) xv[T_ + d] = xv[T_ - 1];
    __syncthreads();

    float w[P_];
    #pragma unroll
    for (int p = 0; p < P_; p++) w[p] = W_val[p * D_ + d];

    for (int n = 0; n < N_; n++) {
        float acc = g_pe[n * D_ + d];
        const float* pv = &xv[n * 8];
        #pragma unroll
        for (int p = 0; p < P_; p++)
            acc = fmaf(pv[p], w[p], acc);
        int bn = bc * 64 + n;
        g_tok  [(size_t)bn * D_ + d] = acc;
        g_tok_h[tidx(bn, d, D_)]     = __float2half_rn(acc);
    }
}

// ---------------- FP16 mma GEMM: TMA-bulk staged, 128x128x64 tiles ----------------
// producer/consumer mbarrier pipeline (no __syncthreads in main loop):
//   full[s] (arrive 1, TMA tx)  at sbase + s*8
//   empty[s] (arrive 8 warps)   at sbase + 24 + s*8
// R14: FILL hoisted to loop head (true distance-2 prefetch);
//      empty-arrive after last ldmatrix of the stage (early recycling).
#define NSTG   3
#define STG_B  32768
#define HG_SMEM (64 + NSTG * STG_B)     // 98368 bytes

template<int EPI>
__global__ __launch_bounds__(256, 2)
void hgemm_kernel(const __half* __restrict__ A, const __half* __restrict__ BT,
                  const float* __restrict__ bias, const float* __restrict__ res,
                  void* __restrict__ Cv, int M, int N, int K, int lda, int ldb) {
    extern __shared__ __half smh[];
    const uint32_t sbase = smem_u32(smh);
    const uint32_t stg0  = sbase + 64;

    int koff = 0;
    if (EPI == 4) koff = blockIdx.z * KCH_;

    const int tid  = threadIdx.x;
    const int warp = tid >> 5, lane = tid & 31;
    const int wm = warp >> 1, wn = warp & 1;       // 4x2 warps, 32x64 warp tile
    const int lr = lane >> 2, lc = lane & 3;
    const int bm = blockIdx.y * 128, bn = blockIdx.x * 128;
    const size_t aBlkRow = (size_t)(bm >> 7) * (size_t)(lda >> 5);
    const size_t bBlkRow = (size_t)(bn >> 7) * (size_t)(ldb >> 5);

    if (tid < NSTG) MBAR_INIT(sbase + tid * 8, 1);
    else if (tid < 2 * NSTG) MBAR_INIT(sbase + 24 + (tid - NSTG) * 8, 8);
    __syncthreads();

    float acc[2][8][4];
    #pragma unroll
    for (int mt = 0; mt < 2; mt++)
        #pragma unroll
        for (int nt = 0; nt < 8; nt++)
            #pragma unroll
            for (int i = 0; i < 4; i++) acc[mt][nt][i] = 0.0f;

    uint32_t aQ[2]; int aS[2];
    #pragma unroll
    for (int mt = 0; mt < 2; mt++) {
        int rr = wm * 32 + mt * 16 + (lane & 15);
        aQ[mt] = (uint32_t)(rr * 64);
        aS[mt] = (rr >> 1) & 3;
    }
    uint32_t bQ[4]; int bS[4];
    #pragma unroll
    for (int ng = 0; ng < 4; ng++) {
        int rr = wn * 64 + ng * 16 + (lane & 15);
        bQ[ng] = (uint32_t)(16384 + rr * 64);
        bS[ng] = (rr >> 1) & 3;
    }
    const int hs = lane >> 4;

    const int NIT = K >> 6;      // 64-K chunks

    auto FILL = [&](int s, int k0, int fn) {
        if (tid == 0) {
            if (fn >= NSTG) MBAR_WAIT(sbase + 24 + s * 8, (fn / 3 + 1) & 1);
            uint32_t bar = sbase + s * 8;
            MBAR_EXPECT(bar, 32768);
            const __half* sa = A  + ((aBlkRow + (size_t)((koff + k0) >> 5)) << 12);
            const __half* sb = BT + ((bBlkRow + (size_t)((koff + k0) >> 5)) << 12);
            uint32_t st = stg0 + s * STG_B;
            BULK_G2S(st,         sa, 16384, bar);
            BULK_G2S(st + 16384, sb, 16384, bar);
        }
    };

    FILL(0, 0, 0); FILL(1, 64, 1);

    for (int it = 0; it < NIT; ++it) {
        const int s = it % 3;
        MBAR_WAIT(sbase + s * 8, (it / 3) & 1);
        if (it + 2 < NIT) FILL((it + 2) % 3, (it + 2) << 6, it + 2);   // early TMA issue

        const uint32_t st = stg0 + s * STG_B;
        // ks = 0..2: LDSM + HMMA
        #pragma unroll
        for (int ks = 0; ks < 3; ks++) {
            const uint32_t kblk = st + (uint32_t)((ks >> 1) * 8192);
            const int ksl = ks & 1;
            uint32_t af[2][4];
            #pragma unroll
            for (int mt = 0; mt < 2; mt++)
                LDSM4(af[mt][0], af[mt][1], af[mt][2], af[mt][3],
                      kblk + aQ[mt] + (uint32_t)((((ksl << 1) | hs) ^ aS[mt]) << 4));
            uint32_t bq[4][4];
            #pragma unroll
            for (int ng = 0; ng < 4; ng++)
                LDSM4(bq[ng][0], bq[ng][1], bq[ng][2], bq[ng][3],
                      kblk + bQ[ng] + (uint32_t)((((ksl << 1) | hs) ^ bS[ng]) << 4));
            #pragma unroll
            for (int mt = 0; mt < 2; mt++)
                #pragma unroll
                for (int nt = 0; nt < 8; nt++)
                    HMMA(acc[mt][nt], af[mt][0], af[mt][1], af[mt][2], af[mt][3],
                         bq[nt >> 1][nt & 1], bq[nt >> 1][(nt & 1) + 2]);
        }
        // ks = 3: LDSM, early empty-arrive, then HMMA
        {
            const uint32_t kblk = st + 8192;
            uint32_t af[2][4];
            #pragma unroll
            for (int mt = 0; mt < 2; mt++)
                LDSM4(af[mt][0], af[mt][1], af[mt][2], af[mt][3],
                      kblk + aQ[mt] + (uint32_t)(((2 | hs) ^ aS[mt]) << 4));
            uint32_t bq[4][4];
            #pragma unroll
            for (int ng = 0; ng < 4; ng++)
                LDSM4(bq[ng][0], bq[ng][1], bq[ng][2], bq[ng][3],
                      kblk + bQ[ng] + (uint32_t)(((2 | hs) ^ bS[ng]) << 4));
            if (lane == 0) MBAR_ARRIVE(sbase + 24 + s * 8);   // stage s fully read
            #pragma unroll
            for (int mt = 0; mt < 2; mt++)
                #pragma unroll
                for (int nt = 0; nt < 8; nt++)
                    HMMA(acc[mt][nt], af[mt][0], af[mt][1], af[mt][2], af[mt][3],
                         bq[nt >> 1][nt & 1], bq[nt >> 1][(nt & 1) + 2]);
        }
    }

    // ---------------- epilogue ----------------
    float* Cf = (float*)Cv;
    __half* Ch = (__half*)Cv;
    if (EPI == 4) Cf += (size_t)blockIdx.z * M * N;

    #pragma unroll
    for (int mt = 0; mt < 2; mt++) {
        #pragma unroll
        for (int half = 0; half < 2; half++) {
            int m = bm + wm * 32 + mt * 16 + lr + half * 8;
            #pragma unroll
            for (int nt = 0; nt < 8; nt++) {
                int col = bn + wn * 64 + nt * 8 + lc * 2;
                float v0 = acc[mt][nt][half * 2 + 0];
                float v1 = acc[mt][nt][half * 2 + 1];
                if (EPI != 4) { v0 += bias[col]; v1 += bias[col + 1]; }
                if (EPI == 1) {
                    const float2 r2 = *(const float2*)(res + (size_t)m * N + col);
                    v0 += r2.x; v1 += r2.y;
                }
                if (EPI == 2) {
                    v0 = 0.5f * v0 * (1.0f + erff(v0 * 0.70710678118654752f));
                    v1 = 0.5f * v1 * (1.0f + erff(v1 * 0.70710678118654752f));
                }
                if (EPI == 0 || EPI == 2) {
                    __half2 hv;
                    hv.x = __float2half_rn(v0); hv.y = __float2half_rn(v1);
                    *(__half2*)(Ch + tidx(m, col, N)) = hv;
                } else {
                    *(float2*)(Cf + (size_t)m * N + col) = make_float2(v0, v1);
                }
            }
        }
    }
}

// ---------------- Attention: tensor-core (per bc,h block; 4 warps) ----------------
#define ATTN_SMEM 24576
__global__ __launch_bounds__(128)
void attn_kernel() {
    int bh = blockIdx.x;
    int bc = bh >> 3, h = bh & 7;
    extern __shared__ __half smA[];
    const uint32_t sb = smem_u32(smA);
    const int tid = threadIdx.x, warp = tid >> 5, lane = tid & 31;
    const int kq = h * 64, kk0 = 512 + h * 64, kv0 = 1024 + h * 64;

    #pragma unroll
    for (int j = 0; j < 4; j++) {
        int q = tid + j * 128;          // 0..511
        int r = q >> 3, c = q & 7;
        uint32_t doff = (uint32_t)(r * 128 + ((c ^ (r & 7)) << 4));
        int R = bc * 64 + r;
        *(uint4*)((char*)smA + doff)         = *(const uint4*)(g_qkv_h + tidx(R, kq  + c * 8, 1536));
        *(uint4*)((char*)smA + 8192 + doff)  = *(const uint4*)(g_qkv_h + tidx(R, kk0 + c * 8, 1536));
        *(uint4*)((char*)smA + 16384 + doff) = *(const uint4*)(g_qkv_h + tidx(R, kv0 + c * 8, 1536));
    }
    __syncthreads();

    const int rlo = lane & 15, hs = lane >> 4;

    float sacc[8][4];
    #pragma unroll
    for (int nt = 0; nt < 8; nt++)
        #pragma unroll
        for (int i = 0; i < 4; i++) sacc[nt][i] = 0.0f;

    #pragma unroll
    for (int ks = 0; ks < 4; ks++) {
        int cc = ks * 2 + hs;
        uint32_t a0, a1, a2, a3;
        {
            int r = warp * 16 + rlo;
            LDSM4(a0, a1, a2, a3, sb + (uint32_t)(r * 128 + ((cc ^ (r & 7)) << 4)));
        }
        #pragma unroll
        for (int ng = 0; ng < 4; ng++) {
            int r = ng * 16 + rlo;
            uint32_t b0, b1, b2, b3;
            LDSM4(b0, b1, b2, b3, sb + 8192 + (uint32_t)(r * 128 + ((cc ^ (r & 7)) << 4)));
            HMMA(sacc[2 * ng],     a0, a1, a2, a3, b0, b2);
            HMMA(sacc[2 * ng + 1], a0, a1, a2, a3, b1, b3);
        }
    }

    float mx0 = -1e30f, mx1 = -1e30f;
    #pragma unroll
    for (int nt = 0; nt < 8; nt++) {
        #pragma unroll
        for (int i = 0; i < 4; i++) sacc[nt][i] *= 0.125f;
        mx0 = fmaxf(mx0, fmaxf(sacc[nt][0], sacc[nt][1]));
        mx1 = fmaxf(mx1, fmaxf(sacc[nt][2], sacc[nt][3]));
    }
    mx0 = fmaxf(mx0, __shfl_xor_sync(0xffffffffu, mx0, 1));
    mx0 = fmaxf(mx0, __shfl_xor_sync(0xffffffffu, mx0, 2));
    mx1 = fmaxf(mx1, __shfl_xor_sync(0xffffffffu, mx1, 1));
    mx1 = fmaxf(mx1, __shfl_xor_sync(0xffffffffu, mx1, 2));
    float s0 = 0.0f, s1 = 0.0f;
    #pragma unroll
    for (int nt = 0; nt < 8; nt++) {
        sacc[nt][0] = expf(sacc[nt][0] - mx0); s0 += sacc[nt][0];
        sacc[nt][1] = expf(sacc[nt][1] - mx0); s0 += sacc[nt][1];
        sacc[nt][2] = expf(sacc[nt][2] - mx1); s1 += sacc[nt][2];
        sacc[nt][3] = expf(sacc[nt][3] - mx1); s1 += sacc[nt][3];
    }
    s0 += __shfl_xor_sync(0xffffffffu, s0, 1);
    s0 += __shfl_xor_sync(0xffffffffu, s0, 2);
    s1 += __shfl_xor_sync(0xffffffffu, s1, 1);
    s1 += __shfl_xor_sync(0xffffffffu, s1, 2);
    float i0 = 1.0f / s0, i1 = 1.0f / s1;
    #pragma unroll
    for (int nt = 0; nt < 8; nt++) {
        sacc[nt][0] *= i0; sacc[nt][1] *= i0;
        sacc[nt][2] *= i1; sacc[nt][3] *= i1;
    }

    uint32_t pa[4][4];
    #pragma unroll
    for (int ks = 0; ks < 4; ks++) {
        pa[ks][0] = h2pack(sacc[2 * ks][0],     sacc[2 * ks][1]);
        pa[ks][1] = h2pack(sacc[2 * ks][2],     sacc[2 * ks][3]);
        pa[ks][2] = h2pack(sacc[2 * ks + 1][0], sacc[2 * ks + 1][1]);
        pa[ks][3] = h2pack(sacc[2 * ks + 1][2], sacc[2 * ks + 1][3]);
    }

    float oacc[8][4];
    #pragma unroll
    for (int nt = 0; nt < 8; nt++)
        #pragma unroll
        for (int i = 0; i < 4; i++) oacc[nt][i] = 0.0f;

    #pragma unroll
    for (int ks = 0; ks < 4; ks++) {
        #pragma unroll
        for (int et = 0; et < 4; et++) {
            int r = ks * 16 + rlo;
            int cc = et * 2 + hs;
            uint32_t v0, v1, v2, v3;
            LDSM4T(v0, v1, v2, v3, sb + 16384 + (uint32_t)(r * 128 + ((cc ^ (r & 7)) << 4)));
            HMMA(oacc[2 * et],     pa[ks][0], pa[ks][1], pa[ks][2], pa[ks][3], v0, v1);
            HMMA(oacc[2 * et + 1], pa[ks][0], pa[ks][1], pa[ks][2], pa[ks][3], v2, v3);
        }
    }

    int r0w = bc * 64 + warp * 16 + (lane >> 2);
    #pragma unroll
    for (int nt = 0; nt < 8; nt++) {
        int col = h * 64 + nt * 8 + (lane & 3) * 2;
        uint32_t p0 = h2pack(oacc[nt][0], oacc[nt][1]);
        uint32_t p1 = h2pack(oacc[nt][2], oacc[nt][3]);
        *(uint32_t*)(g_attn_h + tidx(r0w,     col, D_)) = p0;
        *(uint32_t*)(g_attn_h + tidx(r0w + 8, col, D_)) = p1;
    }
}

// ---------------- LayerNorm: warp-per-row (8 rows/block) ----------------
__global__ void ln_kernel(const float* __restrict__ X,
                          const float* __restrict__ g, const float* __restrict__ b,
                          float* __restrict__ Yf, __half* __restrict__ Yh) {
    int warp = threadIdx.x >> 5, lane = threadIdx.x & 31;
    int row = blockIdx.x * 8 + warp;
    const float* x = X + (size_t)row * D_;
    float v[16];
    float s = 0.0f, q = 0.0f;
    #pragma unroll
    for (int j = 0; j < 4; j++) {
        float4 f = *(const float4*)(x + lane * 4 + j * 128);
        v[j * 4 + 0] = f.x; v[j * 4 + 1] = f.y; v[j * 4 + 2] = f.z; v[j * 4 + 3] = f.w;
        s += f.x + f.y + f.z + f.w;
        q += f.x * f.x + f.y * f.y + f.z * f.z + f.w * f.w;
    }
    #pragma unroll
    for (int o = 16; o > 0; o >>= 1) {
        s += __shfl_xor_sync(0xffffffffu, s, o);
        q += __shfl_xor_sync(0xffffffffu, q, o);
    }
    float mean = s / (float)D_;
    float inv  = rsqrtf(q / (float)D_ - mean * mean + 1e-5f);
    #pragma unroll
    for (int j = 0; j < 4; j++) {
        int c = lane * 4 + j * 128;
        float4 gg = *(const float4*)(g + c);
        float4 bb = *(const float4*)(b + c);
        float o0 = (v[j * 4 + 0] - mean) * inv * gg.x + bb.x;
        float o1 = (v[j * 4 + 1] - mean) * inv * gg.y + bb.y;
        float o2 = (v[j * 4 + 2] - mean) * inv * gg.z + bb.z;
        float o3 = (v[j * 4 + 3] - mean) * inv * gg.w + bb.w;
        if (Yf) *(float4*)(Yf + (size_t)row * D_ + c) = make_float4(o0, o1, o2, o3);
        uint32_t lo = h2pack(o0, o1), hi = h2pack(o2, o3);
        *(uint2*)(Yh + tidx(row, c, D_)) = make_uint2(lo, hi);
    }
}

// ---------------- BatchNorm stats (deterministic 2-stage) ----------------
__global__ void bn_partial_kernel() {
    int blk = blockIdx.x;
    int d = threadIdx.x;      // 512
    float s = 0.0f, q = 0.0f;
    const float* base = g_tok + (size_t)blk * 256 * D_ + d;
    for (int r = 0; r < 256; r++) {
        float v = base[(size_t)r * D_];
        s += v; q += v * v;
    }
    g_psum[blk * D_ + d] = s;
    g_psq [blk * D_ + d] = q;
}

__global__ void bn_final_kernel(const float* __restrict__ gam,
                                const float* __restrict__ bet) {
    int d = threadIdx.x;      // 512, one block
    float s = 0.0f, q = 0.0f;
    for (int i = 0; i < 256; i++) {
        s += g_psum[i * D_ + d];
        q += g_psq [i * D_ + d];
    }
    float mean = s / (float)ROWS_;
    float var  = q / (float)ROWS_ - mean * mean;
    float a = gam[d] * rsqrtf(var + 1e-5f);
    g_bna[d] = a;
    g_bnb[d] = bet[d] - mean * a;
}

// ---------------- BN apply + (N,D)->(D,N) transpose into enc (tiled half) ----------------
__global__ void enc_transpose_kernel() {
    __shared__ float sm[32][33];
    int bid = blockIdx.x;
    int bc = bid >> 5;
    int r = bid & 31;
    int dt = r >> 1, nt = r & 1;
    int tx = threadIdx.x, ty = threadIdx.y;   // 32 x 8
    int d0 = dt * 32, n0 = nt * 32;
    #pragma unroll
    for (int j = 0; j < 32; j += 8) {
        int n = n0 + ty + j;
        int d = d0 + tx;
        float v = g_tok[((size_t)bc * 64 + n) * D_ + d];
        sm[ty + j][tx] = v * g_bna[d] + g_bnb[d];
    }
    __syncthreads();
    #pragma unroll
    for (int j = 0; j < 32; j += 8) {
        int d = d0 + ty + j;
        int n = n0 + tx;
        g_enc_h[tidx(bc, d * N_ + n, KHEAD_)] = __float2half_rn(sm[tx][ty + j]);
    }
}

// ---------------- head final: sum split-K partials + bias + denorm ----------------
__global__ void head_final_kernel(const float* __restrict__ b_head,
                                  float* __restrict__ out) {
    int m = blockIdx.x;        // bc
    int t = threadIdx.x;       // 512
    float v = b_head[t];
    #pragma unroll
    for (int z = 0; z < KSPLIT_; z++)
        v += g_hpart[((size_t)z * BC_ + m) * T_ + t];
    int b = m >> 5, c = m & 31;
    out[((size_t)b * T_ + t) * C_ + c] = v * g_std[m] + g_mean[m];
}

// ---------------- Launch ----------------
extern "C" void kernel_launch(void* const* d_in, const int* in_sizes, int n_in,
                              void* d_out, int out_size) {
    const float* x_enc = (const float*)d_in[0];
    const float* W_val = (const float*)d_in[1];
    const float* Wq    = (const float*)d_in[2];
    const float* bq    = (const float*)d_in[3];
    const float* Wk    = (const float*)d_in[4];
    const float* bk    = (const float*)d_in[5];
    const float* Wv    = (const float*)d_in[6];
    const float* bv    = (const float*)d_in[7];
    const float* Wo    = (const float*)d_in[8];
    const float* bo    = (const float*)d_in[9];
    const float* Wc1   = (const float*)d_in[10];
    const float* bc1   = (const float*)d_in[11];
    const float* Wc2   = (const float*)d_in[12];
    const float* bc2   = (const float*)d_in[13];
    const float* ln1_g = (const float*)d_in[14];
    const float* ln1_b = (const float*)d_in[15];
    const float* ln2_g = (const float*)d_in[16];
    const float* ln2_b = (const float*)d_in[17];
    const float* bn_g  = (const float*)d_in[18];
    const float* bn_b  = (const float*)d_in[19];
    const float* W_head= (const float*)d_in[20];
    const float* b_head= (const float*)d_in[21];
    float* out = (float*)d_out;

    float *tok, *hpart, *bqkv_p;
    __half *tok_h, *qkv_h, *attn_h, *y_h, *h_h, *enc_h;
    __half *wqkvT, *woT, *wc1T, *wc2T, *whT;
    cudaGetSymbolAddress((void**)&tok,    g_tok);
    cudaGetSymbolAddress((void**)&tok_h,  g_tok_h);
    cudaGetSymbolAddress((void**)&qkv_h,  g_qkv_h);
    cudaGetSymbolAddress((void**)&attn_h, g_attn_h);
    cudaGetSymbolAddress((void**)&y_h,    g_y_h);
    cudaGetSymbolAddress((void**)&h_h,    g_h_h);
    cudaGetSymbolAddress((void**)&enc_h,  g_enc_h);
    cudaGetSymbolAddress((void**)&hpart,  g_hpart);
    cudaGetSymbolAddress((void**)&bqkv_p, g_bqkv);
    cudaGetSymbolAddress((void**)&wqkvT,  g_wqkvT);
    cudaGetSymbolAddress((void**)&woT,    g_woT);
    cudaGetSymbolAddress((void**)&wc1T,   g_wc1T);
    cudaGetSymbolAddress((void**)&wc2T,   g_wc2T);
    cudaGetSymbolAddress((void**)&whT,    g_whT);

    cudaFuncSetAttribute(attn_kernel, cudaFuncAttributeMaxDynamicSharedMemorySize, ATTN_SMEM);
    cudaFuncSetAttribute(hgemm_kernel<0>, cudaFuncAttributeMaxDynamicSharedMemorySize, HG_SMEM);
    cudaFuncSetAttribute(hgemm_kernel<1>, cudaFuncAttributeMaxDynamicSharedMemorySize, HG_SMEM);
    cudaFuncSetAttribute(hgemm_kernel<2>, cudaFuncAttributeMaxDynamicSharedMemorySize, HG_SMEM);
    cudaFuncSetAttribute(hgemm_kernel<4>, cudaFuncAttributeMaxDynamicSharedMemorySize, HG_SMEM);

    dim3 tb32(32, 8);
    dim3 gqkv(1536 / 128, ROWS_ / 128);       // (12, 512)
    dim3 gproj(D_ / 128, ROWS_ / 128);        // (4, 512)
    dim3 gff1(DFF_ / 128, ROWS_ / 128);       // (16, 512)
    dim3 ghead(T_ / 128, BC_ / 128, KSPLIT_); // (4, 8, 8)

    inst_stats_kernel<<<BC_, 256>>>(x_enc);                                       // 1 (+PE)
    patch_embed_kernel<<<BC_, 512>>>(x_enc, W_val);                               // 2
    qkvtrans_kernel<<<dim3(16, 16, 9), tb32>>>(Wq, Wk, Wv, bq, bk, bv);           // 3

    for (int i = 0; i < NL_; i++) {
        hgemm_kernel<0><<<gqkv, 256, HG_SMEM>>>(tok_h, wqkvT + (size_t)i * 1536 * D_,
            bqkv_p + i * 1536, nullptr, qkv_h, ROWS_, 1536, D_, D_, D_);          // #4 for i=0
        if (i == 0) {
            whtrans_kernel<<<dim3(16, 16, 3), tb32>>>(Wo,  woT,  D_, D_);
            whtrans_kernel<<<dim3(64, 16, 3), tb32>>>(Wc1, wc1T, D_, DFF_);
            whtrans_kernel<<<dim3(16, 64, 3), tb32>>>(Wc2, wc2T, DFF_, D_);
        }
        attn_kernel<<<BC_ * H_, 128, ATTN_SMEM>>>();
        hgemm_kernel<1><<<gproj, 256, HG_SMEM>>>(attn_h, woT + (size_t)i * D_ * D_,
            bo + i * D_, tok, tok, ROWS_, D_, D_, D_, D_);
        ln_kernel<<<ROWS_ / 8, 256>>>(tok, ln1_g + i * D_, ln1_b + i * D_, nullptr, y_h);
        hgemm_kernel<2><<<gff1, 256, HG_SMEM>>>(y_h, wc1T + (size_t)i * DFF_ * D_,
            bc1 + i * DFF_, nullptr, h_h, ROWS_, DFF_, D_, D_, D_);
        hgemm_kernel<1><<<gproj, 256, HG_SMEM>>>(h_h, wc2T + (size_t)i * D_ * DFF_,
            bc2 + i * D_, tok, tok, ROWS_, D_, DFF_, DFF_, DFF_);
        ln_kernel<<<ROWS_ / 8, 256>>>(tok, ln2_g + i * D_, ln2_b + i * D_, tok, tok_h);
    }

    whtrans_kernel<<<dim3(16, 1024, 1), tb32>>>(W_head, whT, KHEAD_, T_);
    bn_partial_kernel<<<256, 512>>>();
    bn_final_kernel<<<1, 512>>>(bn_g, bn_b);
    enc_transpose_kernel<<<BC_ * 32, dim3(32, 8)>>>();
    hgemm_kernel<4><<<ghead, 256, HG_SMEM>>>(enc_h, whT, nullptr, nullptr, hpart,
                                             BC_, T_, KCH_, KHEAD_, KHEAD_);
    head_final_kernel<<<BC_, T_>>>(b_head, out);
}